// round 6
// baseline (speedup 1.0000x reference)
#include <cuda_runtime.h>
#include <cuda_bf16.h>
#include <mma.h>
#include <math.h>

using namespace nvcuda;
typedef __nv_bfloat16 bf16;

#define NB    256
#define NMEM  100000
#define CDIM  511
#define DDIM  512
#define KEYS  64
#define TOTW  640
#define KTOP  64
#define ROWS  (NB*KTOP)   // 16384
#define CAP   1024        // candidate cap per row

// ---------------- scratch (device globals; no allocations allowed) ----------
__device__ bf16  g_tau16[(size_t)NB*NMEM];     // approx tau in bf16, 51.2 MB
__device__ float g_deltas[NB*KTOP];
__device__ int   g_topidx[NB*KTOP];
__device__ int   g_candidx[(size_t)NB*CAP];
__device__ int   g_candcnt[NB];
__device__ float g_mems[(size_t)ROWS*DDIM];
__device__ float g_qkvbuf[(size_t)ROWS*TOTW];
__device__ float g_att[(size_t)ROWS*DDIM];
__device__ float g_mem[(size_t)ROWS*DDIM];
__device__ float g_t2[(size_t)ROWS*DDIM];

// bf16 buffers
__device__ bf16 g_c16[(size_t)NB*DDIM];
__device__ bf16 g_mc16[(size_t)NMEM*DDIM];
__device__ bf16 g_ah[(size_t)ROWS*DDIM];
__device__ bf16 g_al[(size_t)ROWS*DDIM];
__device__ bf16 g_hh[(size_t)ROWS*DDIM];
__device__ bf16 g_hl[(size_t)ROWS*DDIM];
__device__ bf16 g_wqkv_h[(size_t)DDIM*TOTW], g_wqkv_l[(size_t)DDIM*TOTW];
__device__ bf16 g_w1_h[(size_t)DDIM*DDIM],  g_w1_l[(size_t)DDIM*DDIM];
__device__ bf16 g_w2_h[(size_t)DDIM*DDIM],  g_w2_l[(size_t)DDIM*DDIM];
__device__ bf16 g_ws1_h[(size_t)DDIM*DDIM], g_ws1_l[(size_t)DDIM*DDIM];
__device__ bf16 g_ws2_h[(size_t)DDIM*DDIM], g_ws2_l[(size_t)DDIM*DDIM]; // 511->512 pad

// ---------------- cp.async helpers ------------------------------------------
__device__ __forceinline__ void cp16(void* dst_smem, const void* src, bool pred) {
    unsigned d = (unsigned)__cvta_generic_to_shared(dst_smem);
    int sz = pred ? 16 : 0;
    asm volatile("cp.async.cg.shared.global [%0], [%1], 16, %2;\n"
                 :: "r"(d), "l"(src), "r"(sz));
}
__device__ __forceinline__ void cp_commit() {
    asm volatile("cp.async.commit_group;\n");
}
template<int NN>
__device__ __forceinline__ void cp_wait() {
    asm volatile("cp.async.wait_group %0;\n" :: "n"(NN));
}

__device__ __forceinline__ unsigned short f2key16(unsigned short b) {
    return (b & 0x8000u) ? (unsigned short)(~b) : (unsigned short)(b | 0x8000u);
}
__device__ __forceinline__ float key16_to_f(unsigned short k) {
    unsigned short raw = (k & 0x8000u) ? (unsigned short)(k & 0x7FFFu)
                                       : (unsigned short)(~k);
    __nv_bfloat16_raw br; br.x = raw;
    return __bfloat162float((bf16)br);
}

// ---------------- fp32 -> bf16 hi/lo split with optional column pad ---------
__global__ void split_pad_kernel(const float* __restrict__ src,
                                 bf16* __restrict__ hi, bf16* __restrict__ lo,
                                 int rows, int scols, int dcols)
{
    size_t total = (size_t)rows * dcols;
    for (size_t idx = (size_t)blockIdx.x * blockDim.x + threadIdx.x;
         idx < total; idx += (size_t)gridDim.x * blockDim.x) {
        int r = (int)(idx / dcols), cc = (int)(idx % dcols);
        float v = (cc < scols) ? src[(size_t)r * scols + cc] : 0.f;
        bf16 h = __float2bfloat16_rn(v);
        hi[idx] = h;
        if (lo) lo[idx] = __float2bfloat16_rn(v - __bfloat162float(h));
    }
}

// ---------------- WMMA bf16 split GEMM: 128x128 tile, cp.async pipeline -----
// C[M,N] = A[M,K] * B.  BCOL: B is [N,K] row-major (use B^T), else [K,N].
// SPLITS: 1 -> hi only; 3 -> Ah*Bh + Ah*Bl + Al*Bh.
// EPI: 0 none, 1 +bias, 2 +bias+relu.
// Outputs: fp32 C if non-null; bf16 OH (and OL split) if non-null.
template<int SPLITS, int EPI, bool BCOL>
__global__ void __launch_bounds__(256, 2) wgemm(
    const bf16* __restrict__ Ah, const bf16* __restrict__ Al,
    const bf16* __restrict__ Bh, const bf16* __restrict__ Bl,
    const float* __restrict__ bias, float* __restrict__ C,
    bf16* __restrict__ OH, bf16* __restrict__ OL,
    int M, int N, int K, int lda, int ldb, int ldc)
{
    extern __shared__ __align__(16) char smem[];
    constexpr int AP  = 40;    // A / BCOL-B smem leading dim (halves)
    constexpr int BPR = 136;   // row-major B smem leading dim (halves)
    constexpr int STAGE = 40960;

    const int tid = threadIdx.x;
    const int w = tid >> 5, lane = tid & 31;
    const int wm = w >> 1, wn = w & 1;              // 4x2 warps, 32x64 each
    const int m0 = blockIdx.y * 128, n0 = blockIdx.x * 128;

    wmma::fragment<wmma::accumulator, 16, 16, 16, float> acc[2][4];
#pragma unroll
    for (int i = 0; i < 2; i++)
#pragma unroll
        for (int j = 0; j < 4; j++) wmma::fill_fragment(acc[i][j], 0.f);

    // async copy of one K-chunk into stage s
    auto issue = [&](int k0, int s) {
        char* base = smem + s * STAGE;
        bf16* sAh = (bf16*)base;
        bf16* sAl = (bf16*)(base + 10240);
        bf16* sBH = (bf16*)(base + 20480);
        bf16* sBL = (bf16*)(base + 30720);
#pragma unroll
        for (int e = 0; e < 2; e++) {
            int idx = tid + e * 256;
            {   // A: 128 rows x 32 halves
                int row = idx >> 2, c4 = idx & 3;
                size_t off = (size_t)(m0 + row) * lda + k0 + c4 * 8;
                cp16(sAh + row * AP + c4 * 8, Ah + off, true);
                if (SPLITS == 3) cp16(sAl + row * AP + c4 * 8, Al + off, true);
            }
            if (BCOL) {     // B^T tile: 128 n-rows x 32 k-halves
                int n = idx >> 2, c4 = idx & 3;
                bool v = (n0 + n) < N;
                size_t off = v ? ((size_t)(n0 + n) * ldb + k0 + c4 * 8) : 0;
                cp16(sBH + n * AP + c4 * 8, Bh + off, v);
                if (SPLITS == 3) cp16(sBL + n * AP + c4 * 8, Bl + off, v);
            } else {        // B tile: 32 k-rows x 128 n-halves
                int row = idx >> 4, c4 = idx & 15;
                size_t off = (size_t)(k0 + row) * ldb + n0 + c4 * 8;
                cp16(sBH + row * BPR + c4 * 8, Bh + off, true);
                if (SPLITS == 3) cp16(sBL + row * BPR + c4 * 8, Bl + off, true);
            }
        }
        cp_commit();
    };

    auto compute = [&](int s) {
        char* base = smem + s * STAGE;
        bf16* sAh = (bf16*)base;
        bf16* sAl = (bf16*)(base + 10240);
        bf16* sBH = (bf16*)(base + 20480);
        bf16* sBL = (bf16*)(base + 30720);
#pragma unroll
        for (int kf = 0; kf < 32; kf += 16) {
            wmma::fragment<wmma::matrix_a, 16, 16, 16, bf16, wmma::row_major> afh[2], afl[2];
#pragma unroll
            for (int i = 0; i < 2; i++) {
                wmma::load_matrix_sync(afh[i], sAh + (wm * 32 + i * 16) * AP + kf, AP);
                if (SPLITS == 3)
                    wmma::load_matrix_sync(afl[i], sAl + (wm * 32 + i * 16) * AP + kf, AP);
            }
            if constexpr (BCOL) {
                wmma::fragment<wmma::matrix_b, 16, 16, 16, bf16, wmma::col_major> bfh, bfl;
#pragma unroll
                for (int j = 0; j < 4; j++) {
                    wmma::load_matrix_sync(bfh, sBH + (wn * 64 + j * 16) * AP + kf, AP);
                    if (SPLITS == 3)
                        wmma::load_matrix_sync(bfl, sBL + (wn * 64 + j * 16) * AP + kf, AP);
#pragma unroll
                    for (int i = 0; i < 2; i++) {
                        wmma::mma_sync(acc[i][j], afh[i], bfh, acc[i][j]);
                        if (SPLITS == 3) {
                            wmma::mma_sync(acc[i][j], afh[i], bfl, acc[i][j]);
                            wmma::mma_sync(acc[i][j], afl[i], bfh, acc[i][j]);
                        }
                    }
                }
            } else {
                wmma::fragment<wmma::matrix_b, 16, 16, 16, bf16, wmma::row_major> bfh, bfl;
#pragma unroll
                for (int j = 0; j < 4; j++) {
                    wmma::load_matrix_sync(bfh, sBH + kf * BPR + wn * 64 + j * 16, BPR);
                    if (SPLITS == 3)
                        wmma::load_matrix_sync(bfl, sBL + kf * BPR + wn * 64 + j * 16, BPR);
#pragma unroll
                    for (int i = 0; i < 2; i++) {
                        wmma::mma_sync(acc[i][j], afh[i], bfh, acc[i][j]);
                        if (SPLITS == 3) {
                            wmma::mma_sync(acc[i][j], afh[i], bfl, acc[i][j]);
                            wmma::mma_sync(acc[i][j], afl[i], bfh, acc[i][j]);
                        }
                    }
                }
            }
        }
    };

    // 2-stage cp.async pipeline
    issue(0, 0);
    int cur = 0;
    for (int k0 = 0; k0 < K; k0 += 32) {
        bool more = (k0 + 32 < K);
        if (more) issue(k0 + 32, cur ^ 1);
        if (more) cp_wait<1>(); else cp_wait<0>();
        __syncthreads();
        compute(cur);
        __syncthreads();      // all warps done with 'cur' before it is refilled
        cur ^= 1;
    }

    // epilogue via smem staging (reuse pipeline smem)
    float* ep = (float*)smem + w * 2176;   // 32 x 68 per warp
#pragma unroll
    for (int i = 0; i < 2; i++)
#pragma unroll
        for (int j = 0; j < 4; j++)
            wmma::store_matrix_sync(ep + i * 16 * 68 + j * 16, acc[i][j], 68,
                                    wmma::mem_row_major);
    __syncwarp();
#pragma unroll 4
    for (int r = 0; r < 32; r++) {
        int gm = m0 + wm * 32 + r;
#pragma unroll
        for (int it = 0; it < 2; it++) {
            int gn = n0 + wn * 64 + it * 32 + lane;
            if (gn < N) {
                float v = ep[r * 68 + it * 32 + lane];
                if (EPI >= 1) v += bias[gn];
                if (EPI == 2) v = fmaxf(v, 0.f);
                size_t off = (size_t)gm * ldc + gn;
                if (C) C[off] = v;
                if (OH) {
                    bf16 h = __float2bfloat16_rn(v);
                    OH[off] = h;
                    if (OL) OL[off] = __float2bfloat16_rn(v - __bfloat162float(h));
                }
            }
        }
    }
}

// ---------------- approx top-64: 2-pass uint16 radix + margin gather --------
__global__ void __launch_bounds__(256) topk16_kernel()
{
    const int r = blockIdx.x, tid = threadIdx.x;
    const bf16* row = g_tau16 + (size_t)r * NMEM;
    const uint4* row4 = (const uint4*)row;          // 12500 uint4 per row
    __shared__ unsigned hist[256];
    __shared__ int sh_d, sh_need, cnt;

    // pass 1: histogram of key high byte
    hist[tid] = 0; __syncthreads();
    for (int i = tid; i < NMEM / 8; i += 256) {
        uint4 q = row4[i];
        unsigned short hb[8] = {
            (unsigned short)(q.x & 0xFFFFu), (unsigned short)(q.x >> 16),
            (unsigned short)(q.y & 0xFFFFu), (unsigned short)(q.y >> 16),
            (unsigned short)(q.z & 0xFFFFu), (unsigned short)(q.z >> 16),
            (unsigned short)(q.w & 0xFFFFu), (unsigned short)(q.w >> 16)};
#pragma unroll
        for (int t = 0; t < 8; t++)
            atomicAdd(&hist[f2key16(hb[t]) >> 8], 1u);
    }
    __syncthreads();
    if (tid == 0) {
        int cum = 0, d = 255;
        for (; d >= 0; --d) {
            if (cum + (int)hist[d] >= KTOP) break;
            cum += (int)hist[d];
        }
        if (d < 0) d = 0;
        sh_d = d; sh_need = KTOP - cum;
    }
    __syncthreads();
    const unsigned hi8 = (unsigned)sh_d;
    const int need = sh_need;
    __syncthreads();

    // pass 2: histogram of low byte among keys with matching high byte
    hist[tid] = 0; __syncthreads();
    for (int i = tid; i < NMEM / 8; i += 256) {
        uint4 q = row4[i];
        unsigned short hb[8] = {
            (unsigned short)(q.x & 0xFFFFu), (unsigned short)(q.x >> 16),
            (unsigned short)(q.y & 0xFFFFu), (unsigned short)(q.y >> 16),
            (unsigned short)(q.z & 0xFFFFu), (unsigned short)(q.z >> 16),
            (unsigned short)(q.w & 0xFFFFu), (unsigned short)(q.w >> 16)};
#pragma unroll
        for (int t = 0; t < 8; t++) {
            unsigned short k = f2key16(hb[t]);
            if ((k >> 8) == hi8) atomicAdd(&hist[k & 0xFFu], 1u);
        }
    }
    __syncthreads();
    if (tid == 0) {
        int cum = 0, d = 255;
        for (; d >= 0; --d) {
            if (cum + (int)hist[d] >= need) break;
            cum += (int)hist[d];
        }
        if (d < 0) d = 0;
        sh_d = d;
        cnt = 0;
    }
    __syncthreads();
    const unsigned short k64 = (unsigned short)((hi8 << 8) | (unsigned)sh_d);
    const float thr = key16_to_f(k64) - 2.0f;   // margin covers bf16+accum error
    __syncthreads();

    // gather candidates
    for (int i = tid; i < NMEM / 8; i += 256) {
        uint4 q = row4[i];
        unsigned short hb[8] = {
            (unsigned short)(q.x & 0xFFFFu), (unsigned short)(q.x >> 16),
            (unsigned short)(q.y & 0xFFFFu), (unsigned short)(q.y >> 16),
            (unsigned short)(q.z & 0xFFFFu), (unsigned short)(q.z >> 16),
            (unsigned short)(q.w & 0xFFFFu), (unsigned short)(q.w >> 16)};
#pragma unroll
        for (int t = 0; t < 8; t++) {
            __nv_bfloat16_raw br; br.x = hb[t];
            if (__bfloat162float((bf16)br) >= thr) {
                int p = atomicAdd(&cnt, 1);
                if (p < CAP) g_candidx[(size_t)r * CAP + p] = i * 8 + t;
            }
        }
    }
    __syncthreads();
    if (tid == 0) g_candcnt[r] = (cnt < CAP) ? cnt : CAP;
}

// ---------------- fp32 rescore (sequential-k fma, UNCHANGED) ----------------
__global__ void __launch_bounds__(256) rescore_kernel(
    const float* __restrict__ c, const float* __restrict__ mem_c)
{
    const int r = blockIdx.x, tid = threadIdx.x;
    __shared__ float sc[512];
    __shared__ float scores[CAP];
    __shared__ int   cidx[CAP];
    const int nc = g_candcnt[r];

    for (int k = tid; k < CDIM; k += 256) sc[k] = c[(size_t)r * CDIM + k];
    for (int i = tid; i < nc; i += 256) cidx[i] = g_candidx[(size_t)r * CAP + i];
    __syncthreads();

    for (int ci = tid; ci < nc; ci += 256) {
        const float* mr = mem_c + (size_t)cidx[ci] * CDIM;
        float s = 0.f;
#pragma unroll 8
        for (int k = 0; k < CDIM; k++) s = fmaf(sc[k], mr[k], s);
        scores[ci] = s;
    }
    __syncthreads();

    for (int ci = tid; ci < nc; ci += 256) {
        float v = scores[ci]; int id = cidx[ci];
        int rank = 0;
        for (int j = 0; j < nc; j++) {
            float vj = scores[j];
            rank += (vj > v) || (vj == v && cidx[j] < id);
        }
        if (rank < KTOP) {
            g_deltas[r * KTOP + rank] = v;
            g_topidx[r * KTOP + rank] = id;
        }
    }
}

// ---------------- mems = concat(delta, mem_c[idx]) + bf16 split -------------
__global__ void build_mems_kernel(const float* __restrict__ mem_c)
{
    const int row = blockIdx.x, tid = threadIdx.x;
    const int idx = g_topidx[row];
    const float d0 = g_deltas[row];
    float* out = g_mems + (size_t)row * DDIM;
    bf16*  oh  = g_ah  + (size_t)row * DDIM;
    bf16*  ol  = g_al  + (size_t)row * DDIM;
    const float* src = mem_c + (size_t)idx * CDIM;
    for (int cpos = tid; cpos < DDIM; cpos += blockDim.x) {
        float v = (cpos == 0) ? d0 : src[cpos - 1];
        out[cpos] = v;
        bf16 h = __float2bfloat16_rn(v);
        oh[cpos] = h;
        ol[cpos] = __float2bfloat16_rn(v - __bfloat162float(h));
    }
}

// ---------------- single-pass vectorized LayerNorm --------------------------
// blockDim.x = W/4 threads; each thread owns one float4 of the row.
__global__ void ln_kernel(
    const float* __restrict__ x, const float* __restrict__ res,
    const float* __restrict__ g, const float* __restrict__ bb,
    float* __restrict__ out, bf16* __restrict__ oh, bf16* __restrict__ ol, int W)
{
    const int row = blockIdx.x, tid = threadIdx.x;
    float4 v = ((const float4*)(x + (size_t)row * W))[tid];
    if (res) {
        float4 r = ((const float4*)(res + (size_t)row * W))[tid];
        v.x += r.x; v.y += r.y; v.z += r.z; v.w += r.w;
    }
    float s  = v.x + v.y + v.z + v.w;
    float s2 = v.x * v.x + v.y * v.y + v.z * v.z + v.w * v.w;
    __shared__ float red1[8], red2[8];
#pragma unroll
    for (int o = 16; o > 0; o >>= 1) {
        s  += __shfl_xor_sync(0xFFFFFFFFu, s, o);
        s2 += __shfl_xor_sync(0xFFFFFFFFu, s2, o);
    }
    const int wid = tid >> 5, nw = blockDim.x >> 5;
    if ((tid & 31) == 0) { red1[wid] = s; red2[wid] = s2; }
    __syncthreads();
    if (tid < 32) {
        s  = (tid < nw) ? red1[tid] : 0.f;
        s2 = (tid < nw) ? red2[tid] : 0.f;
#pragma unroll
        for (int o = 4; o > 0; o >>= 1) {
            s  += __shfl_xor_sync(0xFFFFFFFFu, s, o);
            s2 += __shfl_xor_sync(0xFFFFFFFFu, s2, o);
        }
        if (tid == 0) { red1[0] = s; red2[0] = s2; }
    }
    __syncthreads();
    const float mu = red1[0] / W;
    const float var = red2[0] / W - mu * mu;
    const float rs = rsqrtf(var + 1e-5f);

    float4 gg = ((const float4*)g)[tid];
    float4 b4 = ((const float4*)bb)[tid];
    float4 y;
    y.x = (v.x - mu) * rs * gg.x + b4.x;
    y.y = (v.y - mu) * rs * gg.y + b4.y;
    y.z = (v.z - mu) * rs * gg.z + b4.z;
    y.w = (v.w - mu) * rs * gg.w + b4.w;
    ((float4*)(out + (size_t)row * W))[tid] = y;
    if (oh) {
        union { bf16 b[4]; uint2 u; } H, L;
        float yy[4] = {y.x, y.y, y.z, y.w};
#pragma unroll
        for (int t = 0; t < 4; t++) {
            H.b[t] = __float2bfloat16_rn(yy[t]);
            L.b[t] = __float2bfloat16_rn(yy[t] - __bfloat162float(H.b[t]));
        }
        ((uint2*)(oh + (size_t)row * W))[tid] = H.u;
        ((uint2*)(ol + (size_t)row * W))[tid] = L.u;
    }
}

// ---------------- per-batch attention (64 tokens, ks=64, v=512) --------------
__global__ void __launch_bounds__(256) attn_kernel()
{
    extern __shared__ float smf[];
    float* sq = smf;
    float* sk = smf + 64 * 65;
    float* ss = smf + 2 * 64 * 65;
    const int b = blockIdx.x, tid = threadIdx.x;
    const float* qkv = g_qkvbuf + (size_t)b * 64 * TOTW;

    for (int e = tid; e < 4096; e += 256) {
        int i = e >> 6, d = e & 63;
        sq[i * 65 + d] = qkv[i * TOTW + d] * 0.125f;
        sk[i * 65 + d] = qkv[i * TOTW + KEYS + d];
    }
    __syncthreads();
    for (int e = tid; e < 4096; e += 256) {
        int i = e >> 6, j = e & 63;
        float acc = 0.f;
#pragma unroll 16
        for (int d = 0; d < 64; d++) acc += sq[i * 65 + d] * sk[j * 65 + d];
        ss[i * 65 + j] = acc;
    }
    __syncthreads();
    if (tid < 64) {
        float m = -1e30f;
        for (int j = 0; j < 64; j++) m = fmaxf(m, ss[tid * 65 + j]);
        float s = 0.f;
        for (int j = 0; j < 64; j++) { float e = expf(ss[tid * 65 + j] - m); ss[tid * 65 + j] = e; s += e; }
        float inv = 1.f / s;
        for (int j = 0; j < 64; j++) ss[tid * 65 + j] *= inv;
    }
    __syncthreads();
    float* vt = sq;
    for (int dc = 0; dc < DDIM; dc += 64) {
        for (int e = tid; e < 4096; e += 256) {
            int j = e >> 6, d = e & 63;
            vt[j * 65 + d] = qkv[j * TOTW + 2 * KEYS + dc + d];
        }
        __syncthreads();
        for (int e = tid; e < 4096; e += 256) {
            int i = e >> 6, d = e & 63;
            float acc = 0.f;
#pragma unroll 16
            for (int j = 0; j < 64; j++) acc += ss[i * 65 + j] * vt[j * 65 + d];
            g_att[(size_t)(b * 64 + i) * DDIM + dc + d] = acc;
        }
        __syncthreads();
    }
}

// ---------------- host orchestration -----------------------------------------
extern "C" void kernel_launch(void* const* d_in, const int* in_sizes, int n_in,
                              void* d_out, int out_size)
{
    const float* c     = (const float*)d_in[0];
    const float* mem_c = (const float*)d_in[1];
    const float* Wqkv  = (const float*)d_in[2];
    const float* bqkv  = (const float*)d_in[3];
    const float* gq    = (const float*)d_in[4];
    const float* bq    = (const float*)d_in[5];
    const float* gm    = (const float*)d_in[6];
    const float* bm    = (const float*)d_in[7];
    const float* W1    = (const float*)d_in[8];
    const float* b1    = (const float*)d_in[9];
    const float* W2    = (const float*)d_in[10];
    const float* b2    = (const float*)d_in[11];
    const float* Ws1   = (const float*)d_in[12];
    const float* bs1   = (const float*)d_in[13];
    const float* Ws2   = (const float*)d_in[14];
    const float* bs2   = (const float*)d_in[15];
    float* out = (float*)d_out;

    float *p_mems, *p_qkv, *p_att, *p_mem, *p_t2;
    bf16 *p_tau16, *p_c16, *p_mc16, *p_ah, *p_al, *p_hh, *p_hl;
    bf16 *p_wqh, *p_wql, *p_w1h, *p_w1l, *p_w2h, *p_w2l, *p_s1h, *p_s1l, *p_s2h, *p_s2l;
    cudaGetSymbolAddress((void**)&p_tau16, g_tau16);
    cudaGetSymbolAddress((void**)&p_mems, g_mems);
    cudaGetSymbolAddress((void**)&p_qkv,  g_qkvbuf);
    cudaGetSymbolAddress((void**)&p_att,  g_att);
    cudaGetSymbolAddress((void**)&p_mem,  g_mem);
    cudaGetSymbolAddress((void**)&p_t2,   g_t2);
    cudaGetSymbolAddress((void**)&p_c16,  g_c16);
    cudaGetSymbolAddress((void**)&p_mc16, g_mc16);
    cudaGetSymbolAddress((void**)&p_ah,   g_ah);
    cudaGetSymbolAddress((void**)&p_al,   g_al);
    cudaGetSymbolAddress((void**)&p_hh,   g_hh);
    cudaGetSymbolAddress((void**)&p_hl,   g_hl);
    cudaGetSymbolAddress((void**)&p_wqh,  g_wqkv_h);
    cudaGetSymbolAddress((void**)&p_wql,  g_wqkv_l);
    cudaGetSymbolAddress((void**)&p_w1h,  g_w1_h);
    cudaGetSymbolAddress((void**)&p_w1l,  g_w1_l);
    cudaGetSymbolAddress((void**)&p_w2h,  g_w2_h);
    cudaGetSymbolAddress((void**)&p_w2l,  g_w2_l);
    cudaGetSymbolAddress((void**)&p_s1h,  g_ws1_h);
    cudaGetSymbolAddress((void**)&p_s1l,  g_ws1_l);
    cudaGetSymbolAddress((void**)&p_s2h,  g_ws2_h);
    cudaGetSymbolAddress((void**)&p_s2l,  g_ws2_l);

    const int WG_SMEM = 81920;
    cudaFuncSetAttribute(wgemm<1, 0, true>,  cudaFuncAttributeMaxDynamicSharedMemorySize, WG_SMEM);
    cudaFuncSetAttribute(wgemm<3, 1, false>, cudaFuncAttributeMaxDynamicSharedMemorySize, WG_SMEM);
    cudaFuncSetAttribute(wgemm<3, 2, false>, cudaFuncAttributeMaxDynamicSharedMemorySize, WG_SMEM);
    cudaFuncSetAttribute(attn_kernel, cudaFuncAttributeMaxDynamicSharedMemorySize,
                         3 * 64 * 65 * 4);
    const dim3 blk(256);

    // --- input/weight conversions ---
    split_pad_kernel<<<512, 256>>>(c,     p_c16,  nullptr, NB,   CDIM, DDIM);
    split_pad_kernel<<<2048, 256>>>(mem_c, p_mc16, nullptr, NMEM, CDIM, DDIM);
    split_pad_kernel<<<512, 256>>>(Wqkv, p_wqh, p_wql, DDIM, TOTW, TOTW);
    split_pad_kernel<<<512, 256>>>(W1,   p_w1h, p_w1l, DDIM, DDIM, DDIM);
    split_pad_kernel<<<512, 256>>>(W2,   p_w2h, p_w2l, DDIM, DDIM, DDIM);
    split_pad_kernel<<<512, 256>>>(Ws1,  p_s1h, p_s1l, DDIM, DDIM, DDIM);
    split_pad_kernel<<<512, 256>>>(Ws2,  p_s2h, p_s2l, DDIM, CDIM, DDIM);

    // --- 1) approx tau (bf16 out) = c16 @ mc16^T ---
    wgemm<1, 0, true><<<dim3((NMEM + 127) / 128, 2), blk, WG_SMEM>>>(
        p_c16, nullptr, p_mc16, nullptr, nullptr, nullptr, p_tau16, nullptr,
        NB, NMEM, DDIM, DDIM, DDIM, NMEM);

    // --- 2) 2-pass uint16 radix candidate select + exact fp32 rescore ---
    topk16_kernel<<<NB, blk>>>();
    rescore_kernel<<<NB, blk>>>(c, mem_c);

    // --- 3) mems + split ---
    build_mems_kernel<<<ROWS, 128>>>(mem_c);

    // --- 4) qkv = LN(mems @ Wqkv + bqkv) ---
    wgemm<3, 1, false><<<dim3(5, 128), blk, WG_SMEM>>>(
        p_ah, p_al, p_wqh, p_wql, bqkv, p_qkv, nullptr, nullptr,
        ROWS, TOTW, DDIM, DDIM, TOTW, TOTW);
    ln_kernel<<<ROWS, 160>>>(p_qkv, nullptr, gq, bq, p_qkv, nullptr, nullptr, TOTW);

    // --- 5) attention ---
    attn_kernel<<<NB, blk, 3 * 64 * 65 * 4>>>();

    // --- 6) mem = LN(mems + attended)  (+ split) ---
    ln_kernel<<<ROWS, 128>>>(p_mems, p_att, gm, bm, p_mem, p_ah, p_al, DDIM);

    // --- 7) two residual MLP blocks ---
    for (int rep = 0; rep < 2; rep++) {
        wgemm<3, 2, false><<<dim3(4, 128), blk, WG_SMEM>>>(
            p_ah, p_al, p_w1h, p_w1l, b1, nullptr, p_hh, p_hl,
            ROWS, DDIM, DDIM, DDIM, DDIM, DDIM);
        wgemm<3, 1, false><<<dim3(4, 128), blk, WG_SMEM>>>(
            p_hh, p_hl, p_w2h, p_w2l, b2, p_t2, nullptr, nullptr,
            ROWS, DDIM, DDIM, DDIM, DDIM, DDIM);
        ln_kernel<<<ROWS, 128>>>(p_t2, p_mem, gm, bm, p_mem, p_ah, p_al, DDIM);
    }

    // --- 8) c_prime = relu(mem @ Ws1 + bs1) @ Ws2 + bs2 ---
    wgemm<3, 2, false><<<dim3(4, 128), blk, WG_SMEM>>>(
        p_ah, p_al, p_s1h, p_s1l, bs1, nullptr, p_hh, p_hl,
        ROWS, DDIM, DDIM, DDIM, DDIM, DDIM);
    wgemm<3, 1, false><<<dim3(4, 128), blk, WG_SMEM>>>(
        p_hh, p_hl, p_s2h, p_s2l, bs2, out, nullptr, nullptr,
        ROWS, CDIM, DDIM, DDIM, DDIM, CDIM);
}

// round 7
// speedup vs baseline: 1.1555x; 1.1555x over previous
#include <cuda_runtime.h>
#include <cuda_bf16.h>
#include <mma.h>
#include <math.h>

using namespace nvcuda;
typedef __nv_bfloat16 bf16;

#define NB    256
#define NMEM  100000
#define CDIM  511
#define DDIM  512
#define KEYS  64
#define TOTW  640
#define KTOP  64
#define ROWS  (NB*KTOP)   // 16384
#define CAP   1024        // candidate cap per row

// ---------------- scratch (device globals; no allocations allowed) ----------
__device__ bf16  g_tau16[(size_t)NB*NMEM];     // approx tau in bf16, 51.2 MB
__device__ float g_deltas[NB*KTOP];
__device__ int   g_topidx[NB*KTOP];
__device__ int   g_candidx[(size_t)NB*CAP];
__device__ int   g_candcnt[NB];
__device__ float g_mems[(size_t)ROWS*DDIM];
__device__ float g_qkvbuf[(size_t)ROWS*TOTW];
__device__ float g_att[(size_t)ROWS*DDIM];
__device__ float g_mem[(size_t)ROWS*DDIM];
__device__ float g_t2[(size_t)ROWS*DDIM];

// bf16 buffers
__device__ bf16 g_c16[(size_t)NB*DDIM];
__device__ bf16 g_mc16[(size_t)NMEM*DDIM];
__device__ bf16 g_ah[(size_t)ROWS*DDIM];
__device__ bf16 g_al[(size_t)ROWS*DDIM];
__device__ bf16 g_hh[(size_t)ROWS*DDIM];
__device__ bf16 g_hl[(size_t)ROWS*DDIM];
__device__ bf16 g_wqkv_h[(size_t)DDIM*TOTW], g_wqkv_l[(size_t)DDIM*TOTW];
__device__ bf16 g_w1_h[(size_t)DDIM*DDIM],  g_w1_l[(size_t)DDIM*DDIM];
__device__ bf16 g_w2_h[(size_t)DDIM*DDIM],  g_w2_l[(size_t)DDIM*DDIM];
__device__ bf16 g_ws1_h[(size_t)DDIM*DDIM], g_ws1_l[(size_t)DDIM*DDIM];
__device__ bf16 g_ws2_h[(size_t)DDIM*DDIM], g_ws2_l[(size_t)DDIM*DDIM]; // 511->512 pad

// ---------------- cp.async helpers ------------------------------------------
__device__ __forceinline__ void cp16(void* dst_smem, const void* src, bool pred) {
    unsigned d = (unsigned)__cvta_generic_to_shared(dst_smem);
    int sz = pred ? 16 : 0;
    asm volatile("cp.async.cg.shared.global [%0], [%1], 16, %2;\n"
                 :: "r"(d), "l"(src), "r"(sz));
}
__device__ __forceinline__ void cp_commit() {
    asm volatile("cp.async.commit_group;\n");
}
template<int NN>
__device__ __forceinline__ void cp_wait() {
    asm volatile("cp.async.wait_group %0;\n" :: "n"(NN));
}

__device__ __forceinline__ unsigned short f2key16(unsigned short b) {
    return (b & 0x8000u) ? (unsigned short)(~b) : (unsigned short)(b | 0x8000u);
}
__device__ __forceinline__ float key16_to_f(unsigned short k) {
    unsigned short raw = (k & 0x8000u) ? (unsigned short)(k & 0x7FFFu)
                                       : (unsigned short)(~k);
    __nv_bfloat16_raw br; br.x = raw;
    return __bfloat162float((bf16)br);
}

// ---------------- fp32 -> bf16 hi/lo split with optional column pad ---------
__global__ void split_pad_kernel(const float* __restrict__ src,
                                 bf16* __restrict__ hi, bf16* __restrict__ lo,
                                 int rows, int scols, int dcols)
{
    size_t total = (size_t)rows * dcols;
    for (size_t idx = (size_t)blockIdx.x * blockDim.x + threadIdx.x;
         idx < total; idx += (size_t)gridDim.x * blockDim.x) {
        int r = (int)(idx / dcols), cc = (int)(idx % dcols);
        float v = (cc < scols) ? src[(size_t)r * scols + cc] : 0.f;
        bf16 h = __float2bfloat16_rn(v);
        hi[idx] = h;
        if (lo) lo[idx] = __float2bfloat16_rn(v - __bfloat162float(h));
    }
}

// ---------------- WMMA bf16 split GEMM: 128x128 tile, 3-stage cp.async ------
// C[M,N] = A[M,K] * B.  BCOL: B is [N,K] row-major (use B^T), else [K,N].
// SPLITS: 1 -> hi only; 3 -> Ah*Bh + Ah*Bl + Al*Bh.
// EPI: 0 none, 1 +bias, 2 +bias+relu.
// Outputs: fp32 C if non-null; bf16 OH (and OL split) if non-null.
template<int SPLITS, int EPI, bool BCOL>
__global__ void __launch_bounds__(256) wgemm(
    const bf16* __restrict__ Ah, const bf16* __restrict__ Al,
    const bf16* __restrict__ Bh, const bf16* __restrict__ Bl,
    const float* __restrict__ bias, float* __restrict__ C,
    bf16* __restrict__ OH, bf16* __restrict__ OL,
    int M, int N, int K, int lda, int ldb, int ldc)
{
    extern __shared__ __align__(16) char smem[];
    constexpr int AP  = 40;    // A / BCOL-B smem leading dim (halves)
    constexpr int BPR = 136;   // row-major B smem leading dim (halves)
    constexpr int STAGE = 40960;

    const int tid = threadIdx.x;
    const int w = tid >> 5, lane = tid & 31;
    const int wm = w >> 1, wn = w & 1;              // 4x2 warps, 32x64 each
    const int m0 = blockIdx.y * 128, n0 = blockIdx.x * 128;

    wmma::fragment<wmma::accumulator, 16, 16, 16, float> acc[2][4];
#pragma unroll
    for (int i = 0; i < 2; i++)
#pragma unroll
        for (int j = 0; j < 4; j++) wmma::fill_fragment(acc[i][j], 0.f);

    // async copy of one K-chunk into stage s
    auto issue = [&](int k0, int s) {
        char* base = smem + s * STAGE;
        bf16* sAh = (bf16*)base;
        bf16* sAl = (bf16*)(base + 10240);
        bf16* sBH = (bf16*)(base + 20480);
        bf16* sBL = (bf16*)(base + 30720);
#pragma unroll
        for (int e = 0; e < 2; e++) {
            int idx = tid + e * 256;
            {   // A: 128 rows x 32 halves
                int row = idx >> 2, c4 = idx & 3;
                size_t off = (size_t)(m0 + row) * lda + k0 + c4 * 8;
                cp16(sAh + row * AP + c4 * 8, Ah + off, true);
                if (SPLITS == 3) cp16(sAl + row * AP + c4 * 8, Al + off, true);
            }
            if (BCOL) {     // B^T tile: 128 n-rows x 32 k-halves
                int n = idx >> 2, c4 = idx & 3;
                bool v = (n0 + n) < N;
                size_t off = v ? ((size_t)(n0 + n) * ldb + k0 + c4 * 8) : 0;
                cp16(sBH + n * AP + c4 * 8, Bh + off, v);
                if (SPLITS == 3) cp16(sBL + n * AP + c4 * 8, Bl + off, v);
            } else {        // B tile: 32 k-rows x 128 n-halves
                int row = idx >> 4, c4 = idx & 15;
                size_t off = (size_t)(k0 + row) * ldb + n0 + c4 * 8;
                cp16(sBH + row * BPR + c4 * 8, Bh + off, true);
                if (SPLITS == 3) cp16(sBL + row * BPR + c4 * 8, Bl + off, true);
            }
        }
        cp_commit();
    };

    auto compute = [&](int s) {
        char* base = smem + s * STAGE;
        bf16* sAh = (bf16*)base;
        bf16* sAl = (bf16*)(base + 10240);
        bf16* sBH = (bf16*)(base + 20480);
        bf16* sBL = (bf16*)(base + 30720);
#pragma unroll
        for (int kf = 0; kf < 32; kf += 16) {
            wmma::fragment<wmma::matrix_a, 16, 16, 16, bf16, wmma::row_major> afh[2], afl[2];
#pragma unroll
            for (int i = 0; i < 2; i++) {
                wmma::load_matrix_sync(afh[i], sAh + (wm * 32 + i * 16) * AP + kf, AP);
                if (SPLITS == 3)
                    wmma::load_matrix_sync(afl[i], sAl + (wm * 32 + i * 16) * AP + kf, AP);
            }
            if constexpr (BCOL) {
                wmma::fragment<wmma::matrix_b, 16, 16, 16, bf16, wmma::col_major> bfh, bfl;
#pragma unroll
                for (int j = 0; j < 4; j++) {
                    wmma::load_matrix_sync(bfh, sBH + (wn * 64 + j * 16) * AP + kf, AP);
                    if (SPLITS == 3)
                        wmma::load_matrix_sync(bfl, sBL + (wn * 64 + j * 16) * AP + kf, AP);
#pragma unroll
                    for (int i = 0; i < 2; i++) {
                        wmma::mma_sync(acc[i][j], afh[i], bfh, acc[i][j]);
                        if (SPLITS == 3) {
                            wmma::mma_sync(acc[i][j], afh[i], bfl, acc[i][j]);
                            wmma::mma_sync(acc[i][j], afl[i], bfh, acc[i][j]);
                        }
                    }
                }
            } else {
                wmma::fragment<wmma::matrix_b, 16, 16, 16, bf16, wmma::row_major> bfh, bfl;
#pragma unroll
                for (int j = 0; j < 4; j++) {
                    wmma::load_matrix_sync(bfh, sBH + kf * BPR + wn * 64 + j * 16, BPR);
                    if (SPLITS == 3)
                        wmma::load_matrix_sync(bfl, sBL + kf * BPR + wn * 64 + j * 16, BPR);
#pragma unroll
                    for (int i = 0; i < 2; i++) {
                        wmma::mma_sync(acc[i][j], afh[i], bfh, acc[i][j]);
                        if (SPLITS == 3) {
                            wmma::mma_sync(acc[i][j], afh[i], bfl, acc[i][j]);
                            wmma::mma_sync(acc[i][j], afl[i], bfh, acc[i][j]);
                        }
                    }
                }
            }
        }
    };

    // 3-stage cp.async pipeline, one barrier per iteration.
    // Barrier at top of iter i proves all warps finished compute(i-1), so
    // re-issuing into that stage ((cur+2)%3) after the barrier is safe.
    issue(0, 0);
    if (32 < K) issue(32, 1);
    int cur = 0;
    for (int k0 = 0; k0 < K; k0 += 32) {
        if (k0 + 32 < K) cp_wait<1>(); else cp_wait<0>();
        __syncthreads();
        if (k0 + 64 < K) issue(k0 + 64, (cur + 2) % 3);
        compute(cur);
        cur = (cur + 1) % 3;
    }
    __syncthreads();   // protect stage smem before epilogue reuse

    // epilogue via smem staging (reuse pipeline smem)
    float* ep = (float*)smem + w * 2176;   // 32 x 68 per warp
#pragma unroll
    for (int i = 0; i < 2; i++)
#pragma unroll
        for (int j = 0; j < 4; j++)
            wmma::store_matrix_sync(ep + i * 16 * 68 + j * 16, acc[i][j], 68,
                                    wmma::mem_row_major);
    __syncwarp();
#pragma unroll 4
    for (int r = 0; r < 32; r++) {
        int gm = m0 + wm * 32 + r;
#pragma unroll
        for (int it = 0; it < 2; it++) {
            int gn = n0 + wn * 64 + it * 32 + lane;
            if (gn < N) {
                float v = ep[r * 68 + it * 32 + lane];
                if (EPI >= 1) v += bias[gn];
                if (EPI == 2) v = fmaxf(v, 0.f);
                size_t off = (size_t)gm * ldc + gn;
                if (C) C[off] = v;
                if (OH) {
                    bf16 h = __float2bfloat16_rn(v);
                    OH[off] = h;
                    if (OL) OL[off] = __float2bfloat16_rn(v - __bfloat162float(h));
                }
            }
        }
    }
}

// ---------------- approx top-64: 2-pass uint16 radix + margin gather --------
__global__ void __launch_bounds__(256) topk16_kernel()
{
    const int r = blockIdx.x, tid = threadIdx.x;
    const bf16* row = g_tau16 + (size_t)r * NMEM;
    const uint4* row4 = (const uint4*)row;          // 12500 uint4 per row
    __shared__ unsigned hist[256];
    __shared__ int sh_d, sh_need, cnt;

    // pass 1: histogram of key high byte
    hist[tid] = 0; __syncthreads();
    for (int i = tid; i < NMEM / 8; i += 256) {
        uint4 q = row4[i];
        unsigned short hb[8] = {
            (unsigned short)(q.x & 0xFFFFu), (unsigned short)(q.x >> 16),
            (unsigned short)(q.y & 0xFFFFu), (unsigned short)(q.y >> 16),
            (unsigned short)(q.z & 0xFFFFu), (unsigned short)(q.z >> 16),
            (unsigned short)(q.w & 0xFFFFu), (unsigned short)(q.w >> 16)};
#pragma unroll
        for (int t = 0; t < 8; t++)
            atomicAdd(&hist[f2key16(hb[t]) >> 8], 1u);
    }
    __syncthreads();
    if (tid == 0) {
        int cum = 0, d = 255;
        for (; d >= 0; --d) {
            if (cum + (int)hist[d] >= KTOP) break;
            cum += (int)hist[d];
        }
        if (d < 0) d = 0;
        sh_d = d; sh_need = KTOP - cum;
    }
    __syncthreads();
    const unsigned hi8 = (unsigned)sh_d;
    const int need = sh_need;
    __syncthreads();

    // pass 2: histogram of low byte among keys with matching high byte
    hist[tid] = 0; __syncthreads();
    for (int i = tid; i < NMEM / 8; i += 256) {
        uint4 q = row4[i];
        unsigned short hb[8] = {
            (unsigned short)(q.x & 0xFFFFu), (unsigned short)(q.x >> 16),
            (unsigned short)(q.y & 0xFFFFu), (unsigned short)(q.y >> 16),
            (unsigned short)(q.z & 0xFFFFu), (unsigned short)(q.z >> 16),
            (unsigned short)(q.w & 0xFFFFu), (unsigned short)(q.w >> 16)};
#pragma unroll
        for (int t = 0; t < 8; t++) {
            unsigned short k = f2key16(hb[t]);
            if ((k >> 8) == hi8) atomicAdd(&hist[k & 0xFFu], 1u);
        }
    }
    __syncthreads();
    if (tid == 0) {
        int cum = 0, d = 255;
        for (; d >= 0; --d) {
            if (cum + (int)hist[d] >= need) break;
            cum += (int)hist[d];
        }
        if (d < 0) d = 0;
        sh_d = d;
        cnt = 0;
    }
    __syncthreads();
    const unsigned short k64 = (unsigned short)((hi8 << 8) | (unsigned)sh_d);
    const float thr = key16_to_f(k64) - 2.0f;   // margin covers bf16+accum error
    __syncthreads();

    // gather candidates
    for (int i = tid; i < NMEM / 8; i += 256) {
        uint4 q = row4[i];
        unsigned short hb[8] = {
            (unsigned short)(q.x & 0xFFFFu), (unsigned short)(q.x >> 16),
            (unsigned short)(q.y & 0xFFFFu), (unsigned short)(q.y >> 16),
            (unsigned short)(q.z & 0xFFFFu), (unsigned short)(q.z >> 16),
            (unsigned short)(q.w & 0xFFFFu), (unsigned short)(q.w >> 16)};
#pragma unroll
        for (int t = 0; t < 8; t++) {
            __nv_bfloat16_raw br; br.x = hb[t];
            if (__bfloat162float((bf16)br) >= thr) {
                int p = atomicAdd(&cnt, 1);
                if (p < CAP) g_candidx[(size_t)r * CAP + p] = i * 8 + t;
            }
        }
    }
    __syncthreads();
    if (tid == 0) g_candcnt[r] = (cnt < CAP) ? cnt : CAP;
}

// ---------------- fp32 rescore (sequential-k fma, UNCHANGED) ----------------
__global__ void __launch_bounds__(256) rescore_kernel(
    const float* __restrict__ c, const float* __restrict__ mem_c)
{
    const int r = blockIdx.x, tid = threadIdx.x;
    __shared__ float sc[512];
    __shared__ float scores[CAP];
    __shared__ int   cidx[CAP];
    const int nc = g_candcnt[r];

    for (int k = tid; k < CDIM; k += 256) sc[k] = c[(size_t)r * CDIM + k];
    for (int i = tid; i < nc; i += 256) cidx[i] = g_candidx[(size_t)r * CAP + i];
    __syncthreads();

    for (int ci = tid; ci < nc; ci += 256) {
        const float* mr = mem_c + (size_t)cidx[ci] * CDIM;
        float s = 0.f;
#pragma unroll 8
        for (int k = 0; k < CDIM; k++) s = fmaf(sc[k], mr[k], s);
        scores[ci] = s;
    }
    __syncthreads();

    for (int ci = tid; ci < nc; ci += 256) {
        float v = scores[ci]; int id = cidx[ci];
        int rank = 0;
        for (int j = 0; j < nc; j++) {
            float vj = scores[j];
            rank += (vj > v) || (vj == v && cidx[j] < id);
        }
        if (rank < KTOP) {
            g_deltas[r * KTOP + rank] = v;
            g_topidx[r * KTOP + rank] = id;
        }
    }
}

// ---------------- mems = concat(delta, mem_c[idx]) + bf16 split -------------
__global__ void build_mems_kernel(const float* __restrict__ mem_c)
{
    const int row = blockIdx.x, tid = threadIdx.x;
    const int idx = g_topidx[row];
    const float d0 = g_deltas[row];
    float* out = g_mems + (size_t)row * DDIM;
    bf16*  oh  = g_ah  + (size_t)row * DDIM;
    bf16*  ol  = g_al  + (size_t)row * DDIM;
    const float* src = mem_c + (size_t)idx * CDIM;
    for (int cpos = tid; cpos < DDIM; cpos += blockDim.x) {
        float v = (cpos == 0) ? d0 : src[cpos - 1];
        out[cpos] = v;
        bf16 h = __float2bfloat16_rn(v);
        oh[cpos] = h;
        ol[cpos] = __float2bfloat16_rn(v - __bfloat162float(h));
    }
}

// ---------------- single-pass vectorized LayerNorm --------------------------
// blockDim.x = W/4 threads; each thread owns one float4 of the row.
__global__ void ln_kernel(
    const float* __restrict__ x, const float* __restrict__ res,
    const float* __restrict__ g, const float* __restrict__ bb,
    float* __restrict__ out, bf16* __restrict__ oh, bf16* __restrict__ ol, int W)
{
    const int row = blockIdx.x, tid = threadIdx.x;
    float4 v = ((const float4*)(x + (size_t)row * W))[tid];
    if (res) {
        float4 r = ((const float4*)(res + (size_t)row * W))[tid];
        v.x += r.x; v.y += r.y; v.z += r.z; v.w += r.w;
    }
    float s  = v.x + v.y + v.z + v.w;
    float s2 = v.x * v.x + v.y * v.y + v.z * v.z + v.w * v.w;
    __shared__ float red1[8], red2[8];
#pragma unroll
    for (int o = 16; o > 0; o >>= 1) {
        s  += __shfl_xor_sync(0xFFFFFFFFu, s, o);
        s2 += __shfl_xor_sync(0xFFFFFFFFu, s2, o);
    }
    const int wid = tid >> 5, nw = blockDim.x >> 5;
    if ((tid & 31) == 0) { red1[wid] = s; red2[wid] = s2; }
    __syncthreads();
    if (tid < 32) {
        s  = (tid < nw) ? red1[tid] : 0.f;
        s2 = (tid < nw) ? red2[tid] : 0.f;
#pragma unroll
        for (int o = 4; o > 0; o >>= 1) {
            s  += __shfl_xor_sync(0xFFFFFFFFu, s, o);
            s2 += __shfl_xor_sync(0xFFFFFFFFu, s2, o);
        }
        if (tid == 0) { red1[0] = s; red2[0] = s2; }
    }
    __syncthreads();
    const float mu = red1[0] / W;
    const float var = red2[0] / W - mu * mu;
    const float rs = rsqrtf(var + 1e-5f);

    float4 gg = ((const float4*)g)[tid];
    float4 b4 = ((const float4*)bb)[tid];
    float4 y;
    y.x = (v.x - mu) * rs * gg.x + b4.x;
    y.y = (v.y - mu) * rs * gg.y + b4.y;
    y.z = (v.z - mu) * rs * gg.z + b4.z;
    y.w = (v.w - mu) * rs * gg.w + b4.w;
    ((float4*)(out + (size_t)row * W))[tid] = y;
    if (oh) {
        union { bf16 b[4]; uint2 u; } H, L;
        float yy[4] = {y.x, y.y, y.z, y.w};
#pragma unroll
        for (int t = 0; t < 4; t++) {
            H.b[t] = __float2bfloat16_rn(yy[t]);
            L.b[t] = __float2bfloat16_rn(yy[t] - __bfloat162float(H.b[t]));
        }
        ((uint2*)(oh + (size_t)row * W))[tid] = H.u;
        ((uint2*)(ol + (size_t)row * W))[tid] = L.u;
    }
}

// ---------------- per-batch attention (64 tokens, ks=64, v=512) --------------
__global__ void __launch_bounds__(256) attn_kernel()
{
    extern __shared__ float smf[];
    float* sq = smf;
    float* sk = smf + 64 * 65;
    float* ss = smf + 2 * 64 * 65;
    const int b = blockIdx.x, tid = threadIdx.x;
    const float* qkv = g_qkvbuf + (size_t)b * 64 * TOTW;

    for (int e = tid; e < 4096; e += 256) {
        int i = e >> 6, d = e & 63;
        sq[i * 65 + d] = qkv[i * TOTW + d] * 0.125f;
        sk[i * 65 + d] = qkv[i * TOTW + KEYS + d];
    }
    __syncthreads();
    for (int e = tid; e < 4096; e += 256) {
        int i = e >> 6, j = e & 63;
        float acc = 0.f;
#pragma unroll 16
        for (int d = 0; d < 64; d++) acc += sq[i * 65 + d] * sk[j * 65 + d];
        ss[i * 65 + j] = acc;
    }
    __syncthreads();
    if (tid < 64) {
        float m = -1e30f;
        for (int j = 0; j < 64; j++) m = fmaxf(m, ss[tid * 65 + j]);
        float s = 0.f;
        for (int j = 0; j < 64; j++) { float e = expf(ss[tid * 65 + j] - m); ss[tid * 65 + j] = e; s += e; }
        float inv = 1.f / s;
        for (int j = 0; j < 64; j++) ss[tid * 65 + j] *= inv;
    }
    __syncthreads();
    float* vt = sq;
    for (int dc = 0; dc < DDIM; dc += 64) {
        for (int e = tid; e < 4096; e += 256) {
            int j = e >> 6, d = e & 63;
            vt[j * 65 + d] = qkv[j * TOTW + 2 * KEYS + dc + d];
        }
        __syncthreads();
        for (int e = tid; e < 4096; e += 256) {
            int i = e >> 6, d = e & 63;
            float acc = 0.f;
#pragma unroll 16
            for (int j = 0; j < 64; j++) acc += ss[i * 65 + j] * vt[j * 65 + d];
            g_att[(size_t)(b * 64 + i) * DDIM + dc + d] = acc;
        }
        __syncthreads();
    }
}

// ---------------- host orchestration -----------------------------------------
extern "C" void kernel_launch(void* const* d_in, const int* in_sizes, int n_in,
                              void* d_out, int out_size)
{
    const float* c     = (const float*)d_in[0];
    const float* mem_c = (const float*)d_in[1];
    const float* Wqkv  = (const float*)d_in[2];
    const float* bqkv  = (const float*)d_in[3];
    const float* gq    = (const float*)d_in[4];
    const float* bq    = (const float*)d_in[5];
    const float* gm    = (const float*)d_in[6];
    const float* bm    = (const float*)d_in[7];
    const float* W1    = (const float*)d_in[8];
    const float* b1    = (const float*)d_in[9];
    const float* W2    = (const float*)d_in[10];
    const float* b2    = (const float*)d_in[11];
    const float* Ws1   = (const float*)d_in[12];
    const float* bs1   = (const float*)d_in[13];
    const float* Ws2   = (const float*)d_in[14];
    const float* bs2   = (const float*)d_in[15];
    float* out = (float*)d_out;

    float *p_mems, *p_qkv, *p_att, *p_mem, *p_t2;
    bf16 *p_tau16, *p_c16, *p_mc16, *p_ah, *p_al, *p_hh, *p_hl;
    bf16 *p_wqh, *p_wql, *p_w1h, *p_w1l, *p_w2h, *p_w2l, *p_s1h, *p_s1l, *p_s2h, *p_s2l;
    cudaGetSymbolAddress((void**)&p_tau16, g_tau16);
    cudaGetSymbolAddress((void**)&p_mems, g_mems);
    cudaGetSymbolAddress((void**)&p_qkv,  g_qkvbuf);
    cudaGetSymbolAddress((void**)&p_att,  g_att);
    cudaGetSymbolAddress((void**)&p_mem,  g_mem);
    cudaGetSymbolAddress((void**)&p_t2,   g_t2);
    cudaGetSymbolAddress((void**)&p_c16,  g_c16);
    cudaGetSymbolAddress((void**)&p_mc16, g_mc16);
    cudaGetSymbolAddress((void**)&p_ah,   g_ah);
    cudaGetSymbolAddress((void**)&p_al,   g_al);
    cudaGetSymbolAddress((void**)&p_hh,   g_hh);
    cudaGetSymbolAddress((void**)&p_hl,   g_hl);
    cudaGetSymbolAddress((void**)&p_wqh,  g_wqkv_h);
    cudaGetSymbolAddress((void**)&p_wql,  g_wqkv_l);
    cudaGetSymbolAddress((void**)&p_w1h,  g_w1_h);
    cudaGetSymbolAddress((void**)&p_w1l,  g_w1_l);
    cudaGetSymbolAddress((void**)&p_w2h,  g_w2_h);
    cudaGetSymbolAddress((void**)&p_w2l,  g_w2_l);
    cudaGetSymbolAddress((void**)&p_s1h,  g_ws1_h);
    cudaGetSymbolAddress((void**)&p_s1l,  g_ws1_l);
    cudaGetSymbolAddress((void**)&p_s2h,  g_ws2_h);
    cudaGetSymbolAddress((void**)&p_s2l,  g_ws2_l);

    const int WG_SMEM = 122880;   // 3 stages x 40960
    cudaFuncSetAttribute(wgemm<1, 0, true>,  cudaFuncAttributeMaxDynamicSharedMemorySize, WG_SMEM);
    cudaFuncSetAttribute(wgemm<3, 1, false>, cudaFuncAttributeMaxDynamicSharedMemorySize, WG_SMEM);
    cudaFuncSetAttribute(wgemm<3, 2, false>, cudaFuncAttributeMaxDynamicSharedMemorySize, WG_SMEM);
    cudaFuncSetAttribute(attn_kernel, cudaFuncAttributeMaxDynamicSharedMemorySize,
                         3 * 64 * 65 * 4);
    const dim3 blk(256);

    // --- input/weight conversions ---
    split_pad_kernel<<<512, 256>>>(c,     p_c16,  nullptr, NB,   CDIM, DDIM);
    split_pad_kernel<<<2048, 256>>>(mem_c, p_mc16, nullptr, NMEM, CDIM, DDIM);
    split_pad_kernel<<<512, 256>>>(Wqkv, p_wqh, p_wql, DDIM, TOTW, TOTW);
    split_pad_kernel<<<512, 256>>>(W1,   p_w1h, p_w1l, DDIM, DDIM, DDIM);
    split_pad_kernel<<<512, 256>>>(W2,   p_w2h, p_w2l, DDIM, DDIM, DDIM);
    split_pad_kernel<<<512, 256>>>(Ws1,  p_s1h, p_s1l, DDIM, DDIM, DDIM);
    split_pad_kernel<<<512, 256>>>(Ws2,  p_s2h, p_s2l, DDIM, CDIM, DDIM);

    // --- 1) approx tau (bf16 out) = c16 @ mc16^T ---
    wgemm<1, 0, true><<<dim3((NMEM + 127) / 128, 2), blk, WG_SMEM>>>(
        p_c16, nullptr, p_mc16, nullptr, nullptr, nullptr, p_tau16, nullptr,
        NB, NMEM, DDIM, DDIM, DDIM, NMEM);

    // --- 2) 2-pass uint16 radix candidate select + exact fp32 rescore ---
    topk16_kernel<<<NB, blk>>>();
    rescore_kernel<<<NB, blk>>>(c, mem_c);

    // --- 3) mems + split ---
    build_mems_kernel<<<ROWS, 128>>>(mem_c);

    // --- 4) qkv = LN(mems @ Wqkv + bqkv) ---
    wgemm<3, 1, false><<<dim3(5, 128), blk, WG_SMEM>>>(
        p_ah, p_al, p_wqh, p_wql, bqkv, p_qkv, nullptr, nullptr,
        ROWS, TOTW, DDIM, DDIM, TOTW, TOTW);
    ln_kernel<<<ROWS, 160>>>(p_qkv, nullptr, gq, bq, p_qkv, nullptr, nullptr, TOTW);

    // --- 5) attention ---
    attn_kernel<<<NB, blk, 3 * 64 * 65 * 4>>>();

    // --- 6) mem = LN(mems + attended)  (+ split) ---
    ln_kernel<<<ROWS, 128>>>(p_mems, p_att, gm, bm, p_mem, p_ah, p_al, DDIM);

    // --- 7) two residual MLP blocks ---
    for (int rep = 0; rep < 2; rep++) {
        wgemm<3, 2, false><<<dim3(4, 128), blk, WG_SMEM>>>(
            p_ah, p_al, p_w1h, p_w1l, b1, nullptr, p_hh, p_hl,
            ROWS, DDIM, DDIM, DDIM, DDIM, DDIM);
        wgemm<3, 1, false><<<dim3(4, 128), blk, WG_SMEM>>>(
            p_hh, p_hl, p_w2h, p_w2l, b2, p_t2, nullptr, nullptr,
            ROWS, DDIM, DDIM, DDIM, DDIM, DDIM);
        ln_kernel<<<ROWS, 128>>>(p_t2, p_mem, gm, bm, p_mem, p_ah, p_al, DDIM);
    }

    // --- 8) c_prime = relu(mem @ Ws1 + bs1) @ Ws2 + bs2 ---
    wgemm<3, 2, false><<<dim3(4, 128), blk, WG_SMEM>>>(
        p_ah, p_al, p_s1h, p_s1l, bs1, nullptr, p_hh, p_hl,
        ROWS, DDIM, DDIM, DDIM, DDIM, DDIM);
    wgemm<3, 1, false><<<dim3(4, 128), blk, WG_SMEM>>>(
        p_hh, p_hl, p_s2h, p_s2l, bs2, out, nullptr, nullptr,
        ROWS, CDIM, DDIM, DDIM, DDIM, CDIM);
}

// round 8
// speedup vs baseline: 1.9075x; 1.6508x over previous
#include <cuda_runtime.h>
#include <cuda_bf16.h>
#include <cuda_fp16.h>
#include <mma.h>
#include <math.h>

using namespace nvcuda;
typedef __nv_bfloat16 bf16;

#define NB    256
#define NMEM  100000
#define CDIM  511
#define DDIM  512
#define KEYS  64
#define TOTW  640
#define KTOP  64
#define ROWS  (NB*KTOP)   // 16384
#define CAP   1024        // candidate cap per row

// ---------------- scratch (device globals; no allocations allowed) ----------
__device__ bf16  g_tau16[(size_t)NB*NMEM];     // approx tau in bf16, 51.2 MB
__device__ float g_deltas[NB*KTOP];
__device__ int   g_topidx[NB*KTOP];
__device__ int   g_candidx[(size_t)NB*CAP];
__device__ int   g_candcnt[NB];
__device__ float g_mems[(size_t)ROWS*DDIM];
__device__ float g_qkvbuf[(size_t)ROWS*TOTW];
__device__ float g_att[(size_t)ROWS*DDIM];
__device__ float g_mem[(size_t)ROWS*DDIM];
__device__ float g_t2[(size_t)ROWS*DDIM];

// tau path stays bf16 (selection invariance)
__device__ bf16 g_c16[(size_t)NB*DDIM];
__device__ bf16 g_mc16[(size_t)NMEM*DDIM];
// downstream path: fp16 single-term
__device__ half g_ah[(size_t)ROWS*DDIM];
__device__ half g_hh[(size_t)ROWS*DDIM];
__device__ half g_wqkv[(size_t)DDIM*TOTW];
__device__ half g_w1[(size_t)DDIM*DDIM];
__device__ half g_w2[(size_t)DDIM*DDIM];
__device__ half g_ws1[(size_t)DDIM*DDIM];
__device__ half g_ws2[(size_t)DDIM*DDIM];     // 511->512 pad

// ---------------- cp.async helpers ------------------------------------------
__device__ __forceinline__ void cp16(void* dst_smem, const void* src, bool pred) {
    unsigned d = (unsigned)__cvta_generic_to_shared(dst_smem);
    int sz = pred ? 16 : 0;
    asm volatile("cp.async.cg.shared.global [%0], [%1], 16, %2;\n"
                 :: "r"(d), "l"(src), "r"(sz));
}
__device__ __forceinline__ void cp_commit() {
    asm volatile("cp.async.commit_group;\n");
}
template<int NN>
__device__ __forceinline__ void cp_wait() {
    asm volatile("cp.async.wait_group %0;\n" :: "n"(NN));
}

__device__ __forceinline__ unsigned short f2key16(unsigned short b) {
    return (b & 0x8000u) ? (unsigned short)(~b) : (unsigned short)(b | 0x8000u);
}
__device__ __forceinline__ float key16_to_f(unsigned short k) {
    unsigned short raw = (k & 0x8000u) ? (unsigned short)(k & 0x7FFFu)
                                       : (unsigned short)(~k);
    __nv_bfloat16_raw br; br.x = raw;
    return __bfloat162float((bf16)br);
}

template<typename T> __device__ __forceinline__ T f2t(float v);
template<> __device__ __forceinline__ half f2t<half>(float v) { return __float2half_rn(v); }
template<> __device__ __forceinline__ bf16 f2t<bf16>(float v) { return __float2bfloat16_rn(v); }

// ---------------- fp32 -> T convert with optional column pad ----------------
template<typename T>
__global__ void conv_pad_kernel(const float* __restrict__ src,
                                T* __restrict__ dst,
                                int rows, int scols, int dcols)
{
    size_t total = (size_t)rows * dcols;
    for (size_t idx = (size_t)blockIdx.x * blockDim.x + threadIdx.x;
         idx < total; idx += (size_t)gridDim.x * blockDim.x) {
        int r = (int)(idx / dcols), cc = (int)(idx % dcols);
        float v = (cc < scols) ? src[(size_t)r * scols + cc] : 0.f;
        dst[idx] = f2t<T>(v);
    }
}

// ---------------- WMMA GEMM: 128x128 tile, 3-stage cp.async -----------------
// TT: half (1-term) or bf16.  C[M,N] = A[M,K] * B.
// BCOL: B is [N,K] row-major (use B^T), else [K,N].
// EPI: 0 none, 1 +bias, 2 +bias+relu.
// Outputs: fp32 C if non-null; TT OH if non-null.
template<typename TT, int EPI, bool BCOL>
__global__ void __launch_bounds__(256) wgemm(
    const TT* __restrict__ A, const TT* __restrict__ B,
    const float* __restrict__ bias, float* __restrict__ C,
    TT* __restrict__ OH,
    int M, int N, int K, int lda, int ldb, int ldc)
{
    extern __shared__ __align__(16) char smem[];
    constexpr int AP  = 40;    // A / BCOL-B smem leading dim (elements)
    constexpr int BPR = 136;   // row-major B smem leading dim (elements)
    constexpr int STAGE = 20480;

    const int tid = threadIdx.x;
    const int w = tid >> 5, lane = tid & 31;
    const int wm = w >> 1, wn = w & 1;              // 4x2 warps, 32x64 each
    const int m0 = blockIdx.y * 128, n0 = blockIdx.x * 128;

    wmma::fragment<wmma::accumulator, 16, 16, 16, float> acc[2][4];
#pragma unroll
    for (int i = 0; i < 2; i++)
#pragma unroll
        for (int j = 0; j < 4; j++) wmma::fill_fragment(acc[i][j], 0.f);

    auto issue = [&](int k0, int s) {
        char* base = smem + s * STAGE;
        TT* sA = (TT*)base;
        TT* sB = (TT*)(base + 10240);
#pragma unroll
        for (int e = 0; e < 2; e++) {
            int idx = tid + e * 256;
            {   // A: 128 rows x 32 elements
                int row = idx >> 2, c4 = idx & 3;
                size_t off = (size_t)(m0 + row) * lda + k0 + c4 * 8;
                cp16(sA + row * AP + c4 * 8, A + off, true);
            }
            if (BCOL) {     // B^T tile: 128 n-rows x 32 k-elements
                int n = idx >> 2, c4 = idx & 3;
                bool v = (n0 + n) < N;
                size_t off = v ? ((size_t)(n0 + n) * ldb + k0 + c4 * 8) : 0;
                cp16(sB + n * AP + c4 * 8, B + off, v);
            } else {        // B tile: 32 k-rows x 128 n-elements
                int row = idx >> 4, c4 = idx & 15;
                size_t off = (size_t)(k0 + row) * ldb + n0 + c4 * 8;
                cp16(sB + row * BPR + c4 * 8, B + off, true);
            }
        }
        cp_commit();
    };

    auto compute = [&](int s) {
        char* base = smem + s * STAGE;
        TT* sA = (TT*)base;
        TT* sB = (TT*)(base + 10240);
#pragma unroll
        for (int kf = 0; kf < 32; kf += 16) {
            wmma::fragment<wmma::matrix_a, 16, 16, 16, TT, wmma::row_major> af[2];
#pragma unroll
            for (int i = 0; i < 2; i++)
                wmma::load_matrix_sync(af[i], sA + (wm * 32 + i * 16) * AP + kf, AP);
            if constexpr (BCOL) {
                wmma::fragment<wmma::matrix_b, 16, 16, 16, TT, wmma::col_major> bf;
#pragma unroll
                for (int j = 0; j < 4; j++) {
                    wmma::load_matrix_sync(bf, sB + (wn * 64 + j * 16) * AP + kf, AP);
#pragma unroll
                    for (int i = 0; i < 2; i++)
                        wmma::mma_sync(acc[i][j], af[i], bf, acc[i][j]);
                }
            } else {
                wmma::fragment<wmma::matrix_b, 16, 16, 16, TT, wmma::row_major> bf;
#pragma unroll
                for (int j = 0; j < 4; j++) {
                    wmma::load_matrix_sync(bf, sB + kf * BPR + wn * 64 + j * 16, BPR);
#pragma unroll
                    for (int i = 0; i < 2; i++)
                        wmma::mma_sync(acc[i][j], af[i], bf, acc[i][j]);
                }
            }
        }
    };

    // 3-stage cp.async pipeline, one barrier per iteration
    issue(0, 0);
    if (32 < K) issue(32, 1);
    int cur = 0;
    for (int k0 = 0; k0 < K; k0 += 32) {
        if (k0 + 32 < K) cp_wait<1>(); else cp_wait<0>();
        __syncthreads();
        if (k0 + 64 < K) issue(k0 + 64, (cur + 2) % 3);
        compute(cur);
        cur = (cur + 1) % 3;
    }
    __syncthreads();   // protect stage smem before epilogue reuse

    // epilogue via smem staging
    float* ep = (float*)smem + w * 2176;   // 32 x 68 per warp
#pragma unroll
    for (int i = 0; i < 2; i++)
#pragma unroll
        for (int j = 0; j < 4; j++)
            wmma::store_matrix_sync(ep + i * 16 * 68 + j * 16, acc[i][j], 68,
                                    wmma::mem_row_major);
    __syncwarp();
#pragma unroll 4
    for (int r = 0; r < 32; r++) {
        int gm = m0 + wm * 32 + r;
#pragma unroll
        for (int it = 0; it < 2; it++) {
            int gn = n0 + wn * 64 + it * 32 + lane;
            if (gn < N) {
                float v = ep[r * 68 + it * 32 + lane];
                if (EPI >= 1) v += bias[gn];
                if (EPI == 2) v = fmaxf(v, 0.f);
                size_t off = (size_t)gm * ldc + gn;
                if (C) C[off] = v;
                if (OH) OH[off] = f2t<TT>(v);
            }
        }
    }
}

// ---------------- approx top-64: 2-pass uint16 radix + margin gather --------
__global__ void __launch_bounds__(256) topk16_kernel()
{
    const int r = blockIdx.x, tid = threadIdx.x;
    const bf16* row = g_tau16 + (size_t)r * NMEM;
    const uint4* row4 = (const uint4*)row;          // 12500 uint4 per row
    __shared__ unsigned hist[256];
    __shared__ int sh_d, sh_need, cnt;

    // pass 1: histogram of key high byte
    hist[tid] = 0; __syncthreads();
    for (int i = tid; i < NMEM / 8; i += 256) {
        uint4 q = row4[i];
        unsigned short hb[8] = {
            (unsigned short)(q.x & 0xFFFFu), (unsigned short)(q.x >> 16),
            (unsigned short)(q.y & 0xFFFFu), (unsigned short)(q.y >> 16),
            (unsigned short)(q.z & 0xFFFFu), (unsigned short)(q.z >> 16),
            (unsigned short)(q.w & 0xFFFFu), (unsigned short)(q.w >> 16)};
#pragma unroll
        for (int t = 0; t < 8; t++)
            atomicAdd(&hist[f2key16(hb[t]) >> 8], 1u);
    }
    __syncthreads();
    if (tid == 0) {
        int cum = 0, d = 255;
        for (; d >= 0; --d) {
            if (cum + (int)hist[d] >= KTOP) break;
            cum += (int)hist[d];
        }
        if (d < 0) d = 0;
        sh_d = d; sh_need = KTOP - cum;
    }
    __syncthreads();
    const unsigned hi8 = (unsigned)sh_d;
    const int need = sh_need;
    __syncthreads();

    // pass 2: histogram of low byte among keys with matching high byte
    hist[tid] = 0; __syncthreads();
    for (int i = tid; i < NMEM / 8; i += 256) {
        uint4 q = row4[i];
        unsigned short hb[8] = {
            (unsigned short)(q.x & 0xFFFFu), (unsigned short)(q.x >> 16),
            (unsigned short)(q.y & 0xFFFFu), (unsigned short)(q.y >> 16),
            (unsigned short)(q.z & 0xFFFFu), (unsigned short)(q.z >> 16),
            (unsigned short)(q.w & 0xFFFFu), (unsigned short)(q.w >> 16)};
#pragma unroll
        for (int t = 0; t < 8; t++) {
            unsigned short k = f2key16(hb[t]);
            if ((k >> 8) == hi8) atomicAdd(&hist[k & 0xFFu], 1u);
        }
    }
    __syncthreads();
    if (tid == 0) {
        int cum = 0, d = 255;
        for (; d >= 0; --d) {
            if (cum + (int)hist[d] >= need) break;
            cum += (int)hist[d];
        }
        if (d < 0) d = 0;
        sh_d = d;
        cnt = 0;
    }
    __syncthreads();
    const unsigned short k64 = (unsigned short)((hi8 << 8) | (unsigned)sh_d);
    const float thr = key16_to_f(k64) - 2.0f;   // margin covers bf16+accum error
    __syncthreads();

    // gather candidates
    for (int i = tid; i < NMEM / 8; i += 256) {
        uint4 q = row4[i];
        unsigned short hb[8] = {
            (unsigned short)(q.x & 0xFFFFu), (unsigned short)(q.x >> 16),
            (unsigned short)(q.y & 0xFFFFu), (unsigned short)(q.y >> 16),
            (unsigned short)(q.z & 0xFFFFu), (unsigned short)(q.z >> 16),
            (unsigned short)(q.w & 0xFFFFu), (unsigned short)(q.w >> 16)};
#pragma unroll
        for (int t = 0; t < 8; t++) {
            __nv_bfloat16_raw br; br.x = hb[t];
            if (__bfloat162float((bf16)br) >= thr) {
                int p = atomicAdd(&cnt, 1);
                if (p < CAP) g_candidx[(size_t)r * CAP + p] = i * 8 + t;
            }
        }
    }
    __syncthreads();
    if (tid == 0) g_candcnt[r] = (cnt < CAP) ? cnt : CAP;
}

// ---------------- fp32 rescore (sequential-k fma, UNCHANGED) ----------------
__global__ void __launch_bounds__(256) rescore_kernel(
    const float* __restrict__ c, const float* __restrict__ mem_c)
{
    const int r = blockIdx.x, tid = threadIdx.x;
    __shared__ float sc[512];
    __shared__ float scores[CAP];
    __shared__ int   cidx[CAP];
    const int nc = g_candcnt[r];

    for (int k = tid; k < CDIM; k += 256) sc[k] = c[(size_t)r * CDIM + k];
    for (int i = tid; i < nc; i += 256) cidx[i] = g_candidx[(size_t)r * CAP + i];
    __syncthreads();

    for (int ci = tid; ci < nc; ci += 256) {
        const float* mr = mem_c + (size_t)cidx[ci] * CDIM;
        float s = 0.f;
#pragma unroll 8
        for (int k = 0; k < CDIM; k++) s = fmaf(sc[k], mr[k], s);
        scores[ci] = s;
    }
    __syncthreads();

    for (int ci = tid; ci < nc; ci += 256) {
        float v = scores[ci]; int id = cidx[ci];
        int rank = 0;
        for (int j = 0; j < nc; j++) {
            float vj = scores[j];
            rank += (vj > v) || (vj == v && cidx[j] < id);
        }
        if (rank < KTOP) {
            g_deltas[r * KTOP + rank] = v;
            g_topidx[r * KTOP + rank] = id;
        }
    }
}

// ---------------- mems = concat(delta, mem_c[idx]) + fp16 emit --------------
__global__ void build_mems_kernel(const float* __restrict__ mem_c)
{
    const int row = blockIdx.x, tid = threadIdx.x;
    const int idx = g_topidx[row];
    const float d0 = g_deltas[row];
    float* out = g_mems + (size_t)row * DDIM;
    half*  oh  = g_ah  + (size_t)row * DDIM;
    const float* src = mem_c + (size_t)idx * CDIM;
    for (int cpos = tid; cpos < DDIM; cpos += blockDim.x) {
        float v = (cpos == 0) ? d0 : src[cpos - 1];
        out[cpos] = v;
        oh[cpos] = __float2half_rn(v);
    }
}

// ---------------- single-pass vectorized LayerNorm (fp16 emit) --------------
// blockDim.x = W/4 threads; each thread owns one float4 of the row.
__global__ void ln_kernel(
    const float* __restrict__ x, const float* __restrict__ res,
    const float* __restrict__ g, const float* __restrict__ bb,
    float* __restrict__ out, half* __restrict__ oh, int W)
{
    const int row = blockIdx.x, tid = threadIdx.x;
    float4 v = ((const float4*)(x + (size_t)row * W))[tid];
    if (res) {
        float4 r = ((const float4*)(res + (size_t)row * W))[tid];
        v.x += r.x; v.y += r.y; v.z += r.z; v.w += r.w;
    }
    float s  = v.x + v.y + v.z + v.w;
    float s2 = v.x * v.x + v.y * v.y + v.z * v.z + v.w * v.w;
    __shared__ float red1[8], red2[8];
#pragma unroll
    for (int o = 16; o > 0; o >>= 1) {
        s  += __shfl_xor_sync(0xFFFFFFFFu, s, o);
        s2 += __shfl_xor_sync(0xFFFFFFFFu, s2, o);
    }
    const int wid = tid >> 5, nw = blockDim.x >> 5;
    if ((tid & 31) == 0) { red1[wid] = s; red2[wid] = s2; }
    __syncthreads();
    if (tid < 32) {
        s  = (tid < nw) ? red1[tid] : 0.f;
        s2 = (tid < nw) ? red2[tid] : 0.f;
#pragma unroll
        for (int o = 4; o > 0; o >>= 1) {
            s  += __shfl_xor_sync(0xFFFFFFFFu, s, o);
            s2 += __shfl_xor_sync(0xFFFFFFFFu, s2, o);
        }
        if (tid == 0) { red1[0] = s; red2[0] = s2; }
    }
    __syncthreads();
    const float mu = red1[0] / W;
    const float var = red2[0] / W - mu * mu;
    const float rs = rsqrtf(var + 1e-5f);

    float4 gg = ((const float4*)g)[tid];
    float4 b4 = ((const float4*)bb)[tid];
    float4 y;
    y.x = (v.x - mu) * rs * gg.x + b4.x;
    y.y = (v.y - mu) * rs * gg.y + b4.y;
    y.z = (v.z - mu) * rs * gg.z + b4.z;
    y.w = (v.w - mu) * rs * gg.w + b4.w;
    ((float4*)(out + (size_t)row * W))[tid] = y;
    if (oh) {
        union { half h[4]; uint2 u; } H;
        H.h[0] = __float2half_rn(y.x);
        H.h[1] = __float2half_rn(y.y);
        H.h[2] = __float2half_rn(y.z);
        H.h[3] = __float2half_rn(y.w);
        ((uint2*)(oh + (size_t)row * W))[tid] = H.u;
    }
}

// ---------------- per-batch attention (64 tokens, ks=64, v=512) --------------
__global__ void __launch_bounds__(256) attn_kernel()
{
    extern __shared__ float smf[];
    float* sq = smf;
    float* sk = smf + 64 * 65;
    float* ss = smf + 2 * 64 * 65;
    const int b = blockIdx.x, tid = threadIdx.x;
    const float* qkv = g_qkvbuf + (size_t)b * 64 * TOTW;

    for (int e = tid; e < 4096; e += 256) {
        int i = e >> 6, d = e & 63;
        sq[i * 65 + d] = qkv[i * TOTW + d] * 0.125f;
        sk[i * 65 + d] = qkv[i * TOTW + KEYS + d];
    }
    __syncthreads();
    for (int e = tid; e < 4096; e += 256) {
        int i = e >> 6, j = e & 63;
        float acc = 0.f;
#pragma unroll 16
        for (int d = 0; d < 64; d++) acc += sq[i * 65 + d] * sk[j * 65 + d];
        ss[i * 65 + j] = acc;
    }
    __syncthreads();
    if (tid < 64) {
        float m = -1e30f;
        for (int j = 0; j < 64; j++) m = fmaxf(m, ss[tid * 65 + j]);
        float s = 0.f;
        for (int j = 0; j < 64; j++) { float e = expf(ss[tid * 65 + j] - m); ss[tid * 65 + j] = e; s += e; }
        float inv = 1.f / s;
        for (int j = 0; j < 64; j++) ss[tid * 65 + j] *= inv;
    }
    __syncthreads();
    float* vt = sq;
    for (int dc = 0; dc < DDIM; dc += 64) {
        for (int e = tid; e < 4096; e += 256) {
            int j = e >> 6, d = e & 63;
            vt[j * 65 + d] = qkv[j * TOTW + 2 * KEYS + dc + d];
        }
        __syncthreads();
        for (int e = tid; e < 4096; e += 256) {
            int i = e >> 6, d = e & 63;
            float acc = 0.f;
#pragma unroll 16
            for (int j = 0; j < 64; j++) acc += ss[i * 65 + j] * vt[j * 65 + d];
            g_att[(size_t)(b * 64 + i) * DDIM + dc + d] = acc;
        }
        __syncthreads();
    }
}

// ---------------- host orchestration -----------------------------------------
extern "C" void kernel_launch(void* const* d_in, const int* in_sizes, int n_in,
                              void* d_out, int out_size)
{
    const float* c     = (const float*)d_in[0];
    const float* mem_c = (const float*)d_in[1];
    const float* Wqkv  = (const float*)d_in[2];
    const float* bqkv  = (const float*)d_in[3];
    const float* gq    = (const float*)d_in[4];
    const float* bq    = (const float*)d_in[5];
    const float* gm    = (const float*)d_in[6];
    const float* bm    = (const float*)d_in[7];
    const float* W1    = (const float*)d_in[8];
    const float* b1    = (const float*)d_in[9];
    const float* W2    = (const float*)d_in[10];
    const float* b2    = (const float*)d_in[11];
    const float* Ws1   = (const float*)d_in[12];
    const float* bs1   = (const float*)d_in[13];
    const float* Ws2   = (const float*)d_in[14];
    const float* bs2   = (const float*)d_in[15];
    float* out = (float*)d_out;

    float *p_mems, *p_qkv, *p_att, *p_mem, *p_t2;
    bf16 *p_tau16, *p_c16, *p_mc16;
    half *p_ah, *p_hh, *p_wq, *p_w1, *p_w2, *p_s1, *p_s2;
    cudaGetSymbolAddress((void**)&p_tau16, g_tau16);
    cudaGetSymbolAddress((void**)&p_mems, g_mems);
    cudaGetSymbolAddress((void**)&p_qkv,  g_qkvbuf);
    cudaGetSymbolAddress((void**)&p_att,  g_att);
    cudaGetSymbolAddress((void**)&p_mem,  g_mem);
    cudaGetSymbolAddress((void**)&p_t2,   g_t2);
    cudaGetSymbolAddress((void**)&p_c16,  g_c16);
    cudaGetSymbolAddress((void**)&p_mc16, g_mc16);
    cudaGetSymbolAddress((void**)&p_ah,   g_ah);
    cudaGetSymbolAddress((void**)&p_hh,   g_hh);
    cudaGetSymbolAddress((void**)&p_wq,   g_wqkv);
    cudaGetSymbolAddress((void**)&p_w1,   g_w1);
    cudaGetSymbolAddress((void**)&p_w2,   g_w2);
    cudaGetSymbolAddress((void**)&p_s1,   g_ws1);
    cudaGetSymbolAddress((void**)&p_s2,   g_ws2);

    const int SM_TAU = 122880;   // bf16 path keeps room (3x20480 stages + 69632 epi)
    const int SM_F16 = 69632;    // max(3*20480, 8*32*68*4)
    cudaFuncSetAttribute(wgemm<bf16, 0, true>,  cudaFuncAttributeMaxDynamicSharedMemorySize, SM_TAU);
    cudaFuncSetAttribute(wgemm<half, 1, false>, cudaFuncAttributeMaxDynamicSharedMemorySize, SM_F16);
    cudaFuncSetAttribute(wgemm<half, 2, false>, cudaFuncAttributeMaxDynamicSharedMemorySize, SM_F16);
    cudaFuncSetAttribute(attn_kernel, cudaFuncAttributeMaxDynamicSharedMemorySize,
                         3 * 64 * 65 * 4);
    const dim3 blk(256);

    // --- input/weight conversions ---
    conv_pad_kernel<bf16><<<512, 256>>>(c,     p_c16,  NB,   CDIM, DDIM);
    conv_pad_kernel<bf16><<<2048, 256>>>(mem_c, p_mc16, NMEM, CDIM, DDIM);
    conv_pad_kernel<half><<<512, 256>>>(Wqkv, p_wq, DDIM, TOTW, TOTW);
    conv_pad_kernel<half><<<512, 256>>>(W1,   p_w1, DDIM, DDIM, DDIM);
    conv_pad_kernel<half><<<512, 256>>>(W2,   p_w2, DDIM, DDIM, DDIM);
    conv_pad_kernel<half><<<512, 256>>>(Ws1,  p_s1, DDIM, DDIM, DDIM);
    conv_pad_kernel<half><<<512, 256>>>(Ws2,  p_s2, DDIM, CDIM, DDIM);

    // --- 1) approx tau (bf16 out) = c16 @ mc16^T  (UNCHANGED precision path) ---
    wgemm<bf16, 0, true><<<dim3((NMEM + 127) / 128, 2), blk, SM_TAU>>>(
        p_c16, p_mc16, nullptr, nullptr, p_tau16,
        NB, NMEM, DDIM, DDIM, DDIM, NMEM);

    // --- 2) 2-pass uint16 radix candidate select + exact fp32 rescore ---
    topk16_kernel<<<NB, blk>>>();
    rescore_kernel<<<NB, blk>>>(c, mem_c);

    // --- 3) mems + fp16 emit ---
    build_mems_kernel<<<ROWS, 128>>>(mem_c);

    // --- 4) qkv = LN(mems @ Wqkv + bqkv) ---
    wgemm<half, 1, false><<<dim3(5, 128), blk, SM_F16>>>(
        p_ah, p_wq, bqkv, p_qkv, (half*)nullptr,
        ROWS, TOTW, DDIM, DDIM, TOTW, TOTW);
    ln_kernel<<<ROWS, 160>>>(p_qkv, nullptr, gq, bq, p_qkv, nullptr, TOTW);

    // --- 5) attention ---
    attn_kernel<<<NB, blk, 3 * 64 * 65 * 4>>>();

    // --- 6) mem = LN(mems + attended)  (+ fp16 emit) ---
    ln_kernel<<<ROWS, 128>>>(p_mems, p_att, gm, bm, p_mem, p_ah, DDIM);

    // --- 7) two residual MLP blocks ---
    for (int rep = 0; rep < 2; rep++) {
        wgemm<half, 2, false><<<dim3(4, 128), blk, SM_F16>>>(
            p_ah, p_w1, b1, nullptr, p_hh,
            ROWS, DDIM, DDIM, DDIM, DDIM, DDIM);
        wgemm<half, 1, false><<<dim3(4, 128), blk, SM_F16>>>(
            p_hh, p_w2, b2, p_t2, (half*)nullptr,
            ROWS, DDIM, DDIM, DDIM, DDIM, DDIM);
        ln_kernel<<<ROWS, 128>>>(p_t2, p_mem, gm, bm, p_mem, p_ah, DDIM);
    }

    // --- 8) c_prime = relu(mem @ Ws1 + bs1) @ Ws2 + bs2 ---
    wgemm<half, 2, false><<<dim3(4, 128), blk, SM_F16>>>(
        p_ah, p_s1, bs1, nullptr, p_hh,
        ROWS, DDIM, DDIM, DDIM, DDIM, DDIM);
    wgemm<half, 1, false><<<dim3(4, 128), blk, SM_F16>>>(
        p_hh, p_s2, bs2, out, (half*)nullptr,
        ROWS, CDIM, DDIM, DDIM, DDIM, CDIM);
}

// round 9
// speedup vs baseline: 1.9634x; 1.0293x over previous
#include <cuda_runtime.h>
#include <cuda_bf16.h>
#include <cuda_fp16.h>
#include <mma.h>
#include <math.h>

using namespace nvcuda;
typedef __nv_bfloat16 bf16;

#define NB    256
#define NMEM  100000
#define CDIM  511
#define DDIM  512
#define KEYS  64
#define TOTW  640
#define KTOP  64
#define ROWS  (NB*KTOP)   // 16384
#define CAP   1024        // candidate cap per row

// ---------------- scratch (device globals; no allocations allowed) ----------
__device__ bf16  g_tau16[(size_t)NB*NMEM];     // approx tau in bf16, 51.2 MB
__device__ float g_deltas[NB*KTOP];
__device__ int   g_topidx[NB*KTOP];
__device__ int   g_candidx[(size_t)NB*CAP];
__device__ int   g_candcnt[NB];
__device__ float g_mems[(size_t)ROWS*DDIM];
__device__ float g_qkvbuf[(size_t)ROWS*TOTW];
__device__ float g_att[(size_t)ROWS*DDIM];
__device__ float g_mem[(size_t)ROWS*DDIM];
__device__ float g_t2[(size_t)ROWS*DDIM];

// tau path stays bf16 (selection invariance)
__device__ bf16 g_c16[(size_t)NB*DDIM];
__device__ bf16 g_mc16[(size_t)NMEM*DDIM];
// downstream path: fp16 single-term
__device__ half g_ah[(size_t)ROWS*DDIM];
__device__ half g_hh[(size_t)ROWS*DDIM];
__device__ half g_wqkv[(size_t)DDIM*TOTW];
__device__ half g_w1[(size_t)DDIM*DDIM];
__device__ half g_w2[(size_t)DDIM*DDIM];
__device__ half g_ws1[(size_t)DDIM*DDIM];
__device__ half g_ws2[(size_t)DDIM*DDIM];     // 511->512 pad

// ---------------- cp.async helpers ------------------------------------------
__device__ __forceinline__ void cp16(void* dst_smem, const void* src, bool pred) {
    unsigned d = (unsigned)__cvta_generic_to_shared(dst_smem);
    int sz = pred ? 16 : 0;
    asm volatile("cp.async.cg.shared.global [%0], [%1], 16, %2;\n"
                 :: "r"(d), "l"(src), "r"(sz));
}
__device__ __forceinline__ void cp_commit() {
    asm volatile("cp.async.commit_group;\n");
}
template<int NN>
__device__ __forceinline__ void cp_wait() {
    asm volatile("cp.async.wait_group %0;\n" :: "n"(NN));
}

__device__ __forceinline__ unsigned short f2key16(unsigned short b) {
    return (b & 0x8000u) ? (unsigned short)(~b) : (unsigned short)(b | 0x8000u);
}
__device__ __forceinline__ float key16_to_f(unsigned short k) {
    unsigned short raw = (k & 0x8000u) ? (unsigned short)(k & 0x7FFFu)
                                       : (unsigned short)(~k);
    __nv_bfloat16_raw br; br.x = raw;
    return __bfloat162float((bf16)br);
}

template<typename T> __device__ __forceinline__ T f2t(float v);
template<> __device__ __forceinline__ half f2t<half>(float v) { return __float2half_rn(v); }
template<> __device__ __forceinline__ bf16 f2t<bf16>(float v) { return __float2bfloat16_rn(v); }

// ---------------- fp32 -> T convert, one row per block (NO division) --------
template<typename T>
__global__ void conv_rows_kernel(const float* __restrict__ src,
                                 T* __restrict__ dst, int scols, int dcols)
{
    const int r = blockIdx.x;
    const float* s = src + (size_t)r * scols;
    T* d = dst + (size_t)r * dcols;
    for (int c = threadIdx.x; c < dcols; c += blockDim.x)
        d[c] = f2t<T>(c < scols ? s[c] : 0.f);
}

// ---------------- WMMA GEMM: 128x128 tile, 3-stage cp.async (UNCHANGED) -----
template<typename TT, int EPI, bool BCOL>
__global__ void __launch_bounds__(256) wgemm(
    const TT* __restrict__ A, const TT* __restrict__ B,
    const float* __restrict__ bias, float* __restrict__ C,
    TT* __restrict__ OH,
    int M, int N, int K, int lda, int ldb, int ldc)
{
    extern __shared__ __align__(16) char smem[];
    constexpr int AP  = 40;
    constexpr int BPR = 136;
    constexpr int STAGE = 20480;

    const int tid = threadIdx.x;
    const int w = tid >> 5, lane = tid & 31;
    const int wm = w >> 1, wn = w & 1;
    const int m0 = blockIdx.y * 128, n0 = blockIdx.x * 128;

    wmma::fragment<wmma::accumulator, 16, 16, 16, float> acc[2][4];
#pragma unroll
    for (int i = 0; i < 2; i++)
#pragma unroll
        for (int j = 0; j < 4; j++) wmma::fill_fragment(acc[i][j], 0.f);

    auto issue = [&](int k0, int s) {
        char* base = smem + s * STAGE;
        TT* sA = (TT*)base;
        TT* sB = (TT*)(base + 10240);
#pragma unroll
        for (int e = 0; e < 2; e++) {
            int idx = tid + e * 256;
            {
                int row = idx >> 2, c4 = idx & 3;
                size_t off = (size_t)(m0 + row) * lda + k0 + c4 * 8;
                cp16(sA + row * AP + c4 * 8, A + off, true);
            }
            if (BCOL) {
                int n = idx >> 2, c4 = idx & 3;
                bool v = (n0 + n) < N;
                size_t off = v ? ((size_t)(n0 + n) * ldb + k0 + c4 * 8) : 0;
                cp16(sB + n * AP + c4 * 8, B + off, v);
            } else {
                int row = idx >> 4, c4 = idx & 15;
                size_t off = (size_t)(k0 + row) * ldb + n0 + c4 * 8;
                cp16(sB + row * BPR + c4 * 8, B + off, true);
            }
        }
        cp_commit();
    };

    auto compute = [&](int s) {
        char* base = smem + s * STAGE;
        TT* sA = (TT*)base;
        TT* sB = (TT*)(base + 10240);
#pragma unroll
        for (int kf = 0; kf < 32; kf += 16) {
            wmma::fragment<wmma::matrix_a, 16, 16, 16, TT, wmma::row_major> af[2];
#pragma unroll
            for (int i = 0; i < 2; i++)
                wmma::load_matrix_sync(af[i], sA + (wm * 32 + i * 16) * AP + kf, AP);
            if constexpr (BCOL) {
                wmma::fragment<wmma::matrix_b, 16, 16, 16, TT, wmma::col_major> bf;
#pragma unroll
                for (int j = 0; j < 4; j++) {
                    wmma::load_matrix_sync(bf, sB + (wn * 64 + j * 16) * AP + kf, AP);
#pragma unroll
                    for (int i = 0; i < 2; i++)
                        wmma::mma_sync(acc[i][j], af[i], bf, acc[i][j]);
                }
            } else {
                wmma::fragment<wmma::matrix_b, 16, 16, 16, TT, wmma::row_major> bf;
#pragma unroll
                for (int j = 0; j < 4; j++) {
                    wmma::load_matrix_sync(bf, sB + kf * BPR + wn * 64 + j * 16, BPR);
#pragma unroll
                    for (int i = 0; i < 2; i++)
                        wmma::mma_sync(acc[i][j], af[i], bf, acc[i][j]);
                }
            }
        }
    };

    issue(0, 0);
    if (32 < K) issue(32, 1);
    int cur = 0;
    for (int k0 = 0; k0 < K; k0 += 32) {
        if (k0 + 32 < K) cp_wait<1>(); else cp_wait<0>();
        __syncthreads();
        if (k0 + 64 < K) issue(k0 + 64, (cur + 2) % 3);
        compute(cur);
        cur = (cur + 1) % 3;
    }
    __syncthreads();

    float* ep = (float*)smem + w * 2176;
#pragma unroll
    for (int i = 0; i < 2; i++)
#pragma unroll
        for (int j = 0; j < 4; j++)
            wmma::store_matrix_sync(ep + i * 16 * 68 + j * 16, acc[i][j], 68,
                                    wmma::mem_row_major);
    __syncwarp();
#pragma unroll 4
    for (int r = 0; r < 32; r++) {
        int gm = m0 + wm * 32 + r;
#pragma unroll
        for (int it = 0; it < 2; it++) {
            int gn = n0 + wn * 64 + it * 32 + lane;
            if (gn < N) {
                float v = ep[r * 68 + it * 32 + lane];
                if (EPI >= 1) v += bias[gn];
                if (EPI == 2) v = fmaxf(v, 0.f);
                size_t off = (size_t)gm * ldc + gn;
                if (C) C[off] = v;
                if (OH) OH[off] = f2t<TT>(v);
            }
        }
    }
}

// ---------------- approx top-64: 2-pass uint16 radix, per-warp hists --------
__global__ void __launch_bounds__(256) topk16_kernel()
{
    const int r = blockIdx.x, tid = threadIdx.x;
    const int wid = tid >> 5;
    const bf16* row = g_tau16 + (size_t)r * NMEM;
    const uint4* row4 = (const uint4*)row;
    __shared__ unsigned hist[8 * 256];
    __shared__ int sh_d, sh_need, cnt;
    unsigned* myh = hist + wid * 256;

    // pass 1: per-warp histogram of key high byte
    for (int i = tid; i < 8 * 256; i += 256) hist[i] = 0;
    __syncthreads();
    for (int i = tid; i < NMEM / 8; i += 256) {
        uint4 q = row4[i];
        unsigned short hb[8] = {
            (unsigned short)(q.x & 0xFFFFu), (unsigned short)(q.x >> 16),
            (unsigned short)(q.y & 0xFFFFu), (unsigned short)(q.y >> 16),
            (unsigned short)(q.z & 0xFFFFu), (unsigned short)(q.z >> 16),
            (unsigned short)(q.w & 0xFFFFu), (unsigned short)(q.w >> 16)};
#pragma unroll
        for (int t = 0; t < 8; t++)
            atomicAdd(&myh[f2key16(hb[t]) >> 8], 1u);
    }
    __syncthreads();
    {   // reduce 8 warps -> hist[tid]
        unsigned tot = 0;
#pragma unroll
        for (int wdx = 0; wdx < 8; wdx++) tot += hist[wdx * 256 + tid];
        __syncthreads();
        hist[tid] = tot;
    }
    __syncthreads();
    if (tid == 0) {
        int cum = 0, d = 255;
        for (; d >= 0; --d) {
            if (cum + (int)hist[d] >= KTOP) break;
            cum += (int)hist[d];
        }
        if (d < 0) d = 0;
        sh_d = d; sh_need = KTOP - cum;
    }
    __syncthreads();
    const unsigned hi8 = (unsigned)sh_d;
    const int need = sh_need;
    __syncthreads();

    // pass 2: per-warp histogram of low byte among matching high byte
    for (int i = tid; i < 8 * 256; i += 256) hist[i] = 0;
    __syncthreads();
    for (int i = tid; i < NMEM / 8; i += 256) {
        uint4 q = row4[i];
        unsigned short hb[8] = {
            (unsigned short)(q.x & 0xFFFFu), (unsigned short)(q.x >> 16),
            (unsigned short)(q.y & 0xFFFFu), (unsigned short)(q.y >> 16),
            (unsigned short)(q.z & 0xFFFFu), (unsigned short)(q.z >> 16),
            (unsigned short)(q.w & 0xFFFFu), (unsigned short)(q.w >> 16)};
#pragma unroll
        for (int t = 0; t < 8; t++) {
            unsigned short k = f2key16(hb[t]);
            if ((k >> 8) == hi8) atomicAdd(&myh[k & 0xFFu], 1u);
        }
    }
    __syncthreads();
    {
        unsigned tot = 0;
#pragma unroll
        for (int wdx = 0; wdx < 8; wdx++) tot += hist[wdx * 256 + tid];
        __syncthreads();
        hist[tid] = tot;
    }
    __syncthreads();
    if (tid == 0) {
        int cum = 0, d = 255;
        for (; d >= 0; --d) {
            if (cum + (int)hist[d] >= need) break;
            cum += (int)hist[d];
        }
        if (d < 0) d = 0;
        sh_d = d;
        cnt = 0;
    }
    __syncthreads();
    const unsigned short k64 = (unsigned short)((hi8 << 8) | (unsigned)sh_d);
    const float thr = key16_to_f(k64) - 2.0f;   // margin covers bf16+accum error
    __syncthreads();

    // gather candidates
    for (int i = tid; i < NMEM / 8; i += 256) {
        uint4 q = row4[i];
        unsigned short hb[8] = {
            (unsigned short)(q.x & 0xFFFFu), (unsigned short)(q.x >> 16),
            (unsigned short)(q.y & 0xFFFFu), (unsigned short)(q.y >> 16),
            (unsigned short)(q.z & 0xFFFFu), (unsigned short)(q.z >> 16),
            (unsigned short)(q.w & 0xFFFFu), (unsigned short)(q.w >> 16)};
#pragma unroll
        for (int t = 0; t < 8; t++) {
            __nv_bfloat16_raw br; br.x = hb[t];
            if (__bfloat162float((bf16)br) >= thr) {
                int p = atomicAdd(&cnt, 1);
                if (p < CAP) g_candidx[(size_t)r * CAP + p] = i * 8 + t;
            }
        }
    }
    __syncthreads();
    if (tid == 0) g_candcnt[r] = (cnt < CAP) ? cnt : CAP;
}

// ---------------- fp32 rescore (sequential-k fma, UNCHANGED) ----------------
__global__ void __launch_bounds__(256) rescore_kernel(
    const float* __restrict__ c, const float* __restrict__ mem_c)
{
    const int r = blockIdx.x, tid = threadIdx.x;
    __shared__ float sc[512];
    __shared__ float scores[CAP];
    __shared__ int   cidx[CAP];
    const int nc = g_candcnt[r];

    for (int k = tid; k < CDIM; k += 256) sc[k] = c[(size_t)r * CDIM + k];
    for (int i = tid; i < nc; i += 256) cidx[i] = g_candidx[(size_t)r * CAP + i];
    __syncthreads();

    for (int ci = tid; ci < nc; ci += 256) {
        const float* mr = mem_c + (size_t)cidx[ci] * CDIM;
        float s = 0.f;
#pragma unroll 8
        for (int k = 0; k < CDIM; k++) s = fmaf(sc[k], mr[k], s);
        scores[ci] = s;
    }
    __syncthreads();

    for (int ci = tid; ci < nc; ci += 256) {
        float v = scores[ci]; int id = cidx[ci];
        int rank = 0;
        for (int j = 0; j < nc; j++) {
            float vj = scores[j];
            rank += (vj > v) || (vj == v && cidx[j] < id);
        }
        if (rank < KTOP) {
            g_deltas[r * KTOP + rank] = v;
            g_topidx[r * KTOP + rank] = id;
        }
    }
}

// ---------------- mems = concat(delta, mem_c[idx]) + fp16 emit --------------
__global__ void build_mems_kernel(const float* __restrict__ mem_c)
{
    const int row = blockIdx.x, tid = threadIdx.x;
    const int idx = g_topidx[row];
    const float d0 = g_deltas[row];
    float* out = g_mems + (size_t)row * DDIM;
    half*  oh  = g_ah  + (size_t)row * DDIM;
    const float* src = mem_c + (size_t)idx * CDIM;
    for (int cpos = tid; cpos < DDIM; cpos += blockDim.x) {
        float v = (cpos == 0) ? d0 : src[cpos - 1];
        out[cpos] = v;
        oh[cpos] = __float2half_rn(v);
    }
}

// ---------------- single-pass vectorized LayerNorm (fp16 emit) --------------
__global__ void ln_kernel(
    const float* __restrict__ x, const float* __restrict__ res,
    const float* __restrict__ g, const float* __restrict__ bb,
    float* __restrict__ out, half* __restrict__ oh, int W)
{
    const int row = blockIdx.x, tid = threadIdx.x;
    float4 v = ((const float4*)(x + (size_t)row * W))[tid];
    if (res) {
        float4 r = ((const float4*)(res + (size_t)row * W))[tid];
        v.x += r.x; v.y += r.y; v.z += r.z; v.w += r.w;
    }
    float s  = v.x + v.y + v.z + v.w;
    float s2 = v.x * v.x + v.y * v.y + v.z * v.z + v.w * v.w;
    __shared__ float red1[8], red2[8];
#pragma unroll
    for (int o = 16; o > 0; o >>= 1) {
        s  += __shfl_xor_sync(0xFFFFFFFFu, s, o);
        s2 += __shfl_xor_sync(0xFFFFFFFFu, s2, o);
    }
    const int wid = tid >> 5, nw = blockDim.x >> 5;
    if ((tid & 31) == 0) { red1[wid] = s; red2[wid] = s2; }
    __syncthreads();
    if (tid < 32) {
        s  = (tid < nw) ? red1[tid] : 0.f;
        s2 = (tid < nw) ? red2[tid] : 0.f;
#pragma unroll
        for (int o = 4; o > 0; o >>= 1) {
            s  += __shfl_xor_sync(0xFFFFFFFFu, s, o);
            s2 += __shfl_xor_sync(0xFFFFFFFFu, s2, o);
        }
        if (tid == 0) { red1[0] = s; red2[0] = s2; }
    }
    __syncthreads();
    const float mu = red1[0] / W;
    const float var = red2[0] / W - mu * mu;
    const float rs = rsqrtf(var + 1e-5f);

    float4 gg = ((const float4*)g)[tid];
    float4 b4 = ((const float4*)bb)[tid];
    float4 y;
    y.x = (v.x - mu) * rs * gg.x + b4.x;
    y.y = (v.y - mu) * rs * gg.y + b4.y;
    y.z = (v.z - mu) * rs * gg.z + b4.z;
    y.w = (v.w - mu) * rs * gg.w + b4.w;
    ((float4*)(out + (size_t)row * W))[tid] = y;
    if (oh) {
        union { half h[4]; uint2 u; } H;
        H.h[0] = __float2half_rn(y.x);
        H.h[1] = __float2half_rn(y.y);
        H.h[2] = __float2half_rn(y.z);
        H.h[3] = __float2half_rn(y.w);
        ((uint2*)(oh + (size_t)row * W))[tid] = H.u;
    }
}

// ---------------- fused LN(qkv) + attention per batch ------------------------
// smem: qkv tile 64 x 645 fp32 (odd stride -> conflict-free), scores 64x65,
//       mu/rs 64 each.  Total 182272 bytes.
#define QP 645
__global__ void __launch_bounds__(256) attn_ln_kernel(
    const float* __restrict__ gq, const float* __restrict__ gb)
{
    extern __shared__ float smf[];
    float* sqkv = smf;                    // 64*645
    float* ss   = smf + 64 * QP;          // 64*65
    float* smu  = ss + 64 * 65;           // 64
    float* srs  = smu + 64;               // 64
    const int b = blockIdx.x, tid = threadIdx.x;
    const int wid = tid >> 5, lane = tid & 31;
    const float* qkv = g_qkvbuf + (size_t)b * 64 * TOTW;

    // load whole tile (coalesced)
    for (int e = tid; e < 64 * TOTW; e += 256) {
        int i = e / TOTW, col = e % TOTW;      // TOTW literal -> cheap
        sqkv[i * QP + col] = qkv[e];
    }
    __syncthreads();

    // per-row LN stats: warp w handles rows 8w..8w+7
    for (int rr = 0; rr < 8; rr++) {
        int rowi = wid * 8 + rr;
        float s = 0.f, s2 = 0.f;
        for (int col = lane; col < TOTW; col += 32) {
            float v = sqkv[rowi * QP + col];
            s += v; s2 += v * v;
        }
#pragma unroll
        for (int o = 16; o > 0; o >>= 1) {
            s  += __shfl_xor_sync(0xFFFFFFFFu, s, o);
            s2 += __shfl_xor_sync(0xFFFFFFFFu, s2, o);
        }
        if (lane == 0) {
            float mu = s / TOTW;
            float var = s2 / TOTW - mu * mu;
            smu[rowi] = mu;
            srs[rowi] = rsqrtf(var + 1e-5f);
        }
    }
    __syncthreads();

    // normalize in place (+ q-scale for cols < 64)
    for (int e = tid; e < 64 * TOTW; e += 256) {
        int i = e / TOTW, col = e % TOTW;
        float v = (sqkv[i * QP + col] - smu[i]) * srs[i] * gq[col] + gb[col];
        if (col < KEYS) v *= 0.125f;
        sqkv[i * QP + col] = v;
    }
    __syncthreads();

    // scores[i][j] = sum_d q[i][d] * k[j][d]
    for (int e = tid; e < 4096; e += 256) {
        int i = e >> 6, j = e & 63;
        float acc = 0.f;
#pragma unroll 16
        for (int d = 0; d < 64; d++)
            acc += sqkv[i * QP + d] * sqkv[j * QP + KEYS + d];
        ss[i * 65 + j] = acc;
    }
    __syncthreads();

    // softmax per row
    if (tid < 64) {
        float m = -1e30f;
        for (int j = 0; j < 64; j++) m = fmaxf(m, ss[tid * 65 + j]);
        float s = 0.f;
        for (int j = 0; j < 64; j++) { float e = expf(ss[tid * 65 + j] - m); ss[tid * 65 + j] = e; s += e; }
        float inv = 1.f / s;
        for (int j = 0; j < 64; j++) ss[tid * 65 + j] *= inv;
    }
    __syncthreads();

    // attended[i][d] = sum_j w[i][j] * v[j][d]
    for (int e = tid; e < 64 * DDIM; e += 256) {
        int i = e >> 9, d = e & 511;
        float acc = 0.f;
#pragma unroll 16
        for (int j = 0; j < 64; j++)
            acc += ss[i * 65 + j] * sqkv[j * QP + 2 * KEYS + d];
        g_att[(size_t)(b * 64 + i) * DDIM + d] = acc;
    }
}

// ---------------- host orchestration -----------------------------------------
extern "C" void kernel_launch(void* const* d_in, const int* in_sizes, int n_in,
                              void* d_out, int out_size)
{
    const float* c     = (const float*)d_in[0];
    const float* mem_c = (const float*)d_in[1];
    const float* Wqkv  = (const float*)d_in[2];
    const float* bqkv  = (const float*)d_in[3];
    const float* gq    = (const float*)d_in[4];
    const float* bq    = (const float*)d_in[5];
    const float* gm    = (const float*)d_in[6];
    const float* bm    = (const float*)d_in[7];
    const float* W1    = (const float*)d_in[8];
    const float* b1    = (const float*)d_in[9];
    const float* W2    = (const float*)d_in[10];
    const float* b2    = (const float*)d_in[11];
    const float* Ws1   = (const float*)d_in[12];
    const float* bs1   = (const float*)d_in[13];
    const float* Ws2   = (const float*)d_in[14];
    const float* bs2   = (const float*)d_in[15];
    float* out = (float*)d_out;

    float *p_mems, *p_qkv, *p_att, *p_mem, *p_t2;
    bf16 *p_tau16, *p_c16, *p_mc16;
    half *p_ah, *p_hh, *p_wq, *p_w1, *p_w2, *p_s1, *p_s2;
    cudaGetSymbolAddress((void**)&p_tau16, g_tau16);
    cudaGetSymbolAddress((void**)&p_mems, g_mems);
    cudaGetSymbolAddress((void**)&p_qkv,  g_qkvbuf);
    cudaGetSymbolAddress((void**)&p_att,  g_att);
    cudaGetSymbolAddress((void**)&p_mem,  g_mem);
    cudaGetSymbolAddress((void**)&p_t2,   g_t2);
    cudaGetSymbolAddress((void**)&p_c16,  g_c16);
    cudaGetSymbolAddress((void**)&p_mc16, g_mc16);
    cudaGetSymbolAddress((void**)&p_ah,   g_ah);
    cudaGetSymbolAddress((void**)&p_hh,   g_hh);
    cudaGetSymbolAddress((void**)&p_wq,   g_wqkv);
    cudaGetSymbolAddress((void**)&p_w1,   g_w1);
    cudaGetSymbolAddress((void**)&p_w2,   g_w2);
    cudaGetSymbolAddress((void**)&p_s1,   g_ws1);
    cudaGetSymbolAddress((void**)&p_s2,   g_ws2);

    const int SM_TAU = 122880;
    const int SM_F16 = 69632;
    const int SM_ATTN = (64 * QP + 64 * 65 + 128) * 4;   // 182272
    cudaFuncSetAttribute(wgemm<bf16, 0, true>,  cudaFuncAttributeMaxDynamicSharedMemorySize, SM_TAU);
    cudaFuncSetAttribute(wgemm<half, 1, false>, cudaFuncAttributeMaxDynamicSharedMemorySize, SM_F16);
    cudaFuncSetAttribute(wgemm<half, 2, false>, cudaFuncAttributeMaxDynamicSharedMemorySize, SM_F16);
    cudaFuncSetAttribute(attn_ln_kernel, cudaFuncAttributeMaxDynamicSharedMemorySize, SM_ATTN);
    const dim3 blk(256);

    // --- input/weight conversions (row-per-block, no division) ---
    conv_rows_kernel<bf16><<<NB,   128>>>(c,     p_c16,  CDIM, DDIM);
    conv_rows_kernel<bf16><<<NMEM, 128>>>(mem_c, p_mc16, CDIM, DDIM);
    conv_rows_kernel<half><<<DDIM, 128>>>(Wqkv, p_wq, TOTW, TOTW);
    conv_rows_kernel<half><<<DDIM, 128>>>(W1,   p_w1, DDIM, DDIM);
    conv_rows_kernel<half><<<DDIM, 128>>>(W2,   p_w2, DDIM, DDIM);
    conv_rows_kernel<half><<<DDIM, 128>>>(Ws1,  p_s1, DDIM, DDIM);
    conv_rows_kernel<half><<<DDIM, 128>>>(Ws2,  p_s2, CDIM, DDIM);

    // --- 1) approx tau (bf16 out) = c16 @ mc16^T ---
    wgemm<bf16, 0, true><<<dim3((NMEM + 127) / 128, 2), blk, SM_TAU>>>(
        p_c16, p_mc16, nullptr, nullptr, p_tau16,
        NB, NMEM, DDIM, DDIM, DDIM, NMEM);

    // --- 2) radix candidate select + exact fp32 rescore ---
    topk16_kernel<<<NB, blk>>>();
    rescore_kernel<<<NB, blk>>>(c, mem_c);

    // --- 3) mems + fp16 emit ---
    build_mems_kernel<<<ROWS, 128>>>(mem_c);

    // --- 4) qkv = mems @ Wqkv + bqkv  (LN fused into attention) ---
    wgemm<half, 1, false><<<dim3(5, 128), blk, SM_F16>>>(
        p_ah, p_wq, bqkv, p_qkv, (half*)nullptr,
        ROWS, TOTW, DDIM, DDIM, TOTW, TOTW);

    // --- 5) fused LN + attention ---
    attn_ln_kernel<<<NB, blk, SM_ATTN>>>(gq, bq);

    // --- 6) mem = LN(mems + attended)  (+ fp16 emit) ---
    ln_kernel<<<ROWS, 128>>>(p_mems, p_att, gm, bm, p_mem, p_ah, DDIM);

    // --- 7) two residual MLP blocks ---
    for (int rep = 0; rep < 2; rep++) {
        wgemm<half, 2, false><<<dim3(4, 128), blk, SM_F16>>>(
            p_ah, p_w1, b1, nullptr, p_hh,
            ROWS, DDIM, DDIM, DDIM, DDIM, DDIM);
        wgemm<half, 1, false><<<dim3(4, 128), blk, SM_F16>>>(
            p_hh, p_w2, b2, p_t2, (half*)nullptr,
            ROWS, DDIM, DDIM, DDIM, DDIM, DDIM);
        ln_kernel<<<ROWS, 128>>>(p_t2, p_mem, gm, bm, p_mem, p_ah, DDIM);
    }

    // --- 8) c_prime = relu(mem @ Ws1 + bs1) @ Ws2 + bs2 ---
    wgemm<half, 2, false><<<dim3(4, 128), blk, SM_F16>>>(
        p_ah, p_s1, bs1, nullptr, p_hh,
        ROWS, DDIM, DDIM, DDIM, DDIM, DDIM);
    wgemm<half, 1, false><<<dim3(4, 128), blk, SM_F16>>>(
        p_hh, p_s2, bs2, out, (half*)nullptr,
        ROWS, CDIM, DDIM, DDIM, DDIM, CDIM);
}

// round 10
// speedup vs baseline: 2.1402x; 1.0900x over previous
#include <cuda_runtime.h>
#include <cuda_bf16.h>
#include <cuda_fp16.h>
#include <mma.h>
#include <math.h>

using namespace nvcuda;
typedef __nv_bfloat16 bf16;

#define NB    256
#define NMEM  100000
#define CDIM  511
#define DDIM  512
#define KEYS  64
#define TOTW  640
#define KTOP  64
#define ROWS  (NB*KTOP)   // 16384
#define CAP   1024        // candidate cap per row

// ---------------- scratch (device globals; no allocations allowed) ----------
__device__ bf16  g_tau16[(size_t)NB*NMEM];     // approx tau in bf16, 51.2 MB
__device__ float g_deltas[NB*KTOP];
__device__ int   g_topidx[NB*KTOP];
__device__ int   g_candidx[(size_t)NB*CAP];
__device__ int   g_candcnt[NB];
__device__ float g_mems[(size_t)ROWS*DDIM];
__device__ float g_qkvbuf[(size_t)ROWS*TOTW];
__device__ float g_att[(size_t)ROWS*DDIM];
__device__ float g_mem[(size_t)ROWS*DDIM];
__device__ float g_t2[(size_t)ROWS*DDIM];

// tau path stays bf16 (selection invariance)
__device__ bf16 g_c16[(size_t)NB*DDIM];
__device__ bf16 g_mc16[(size_t)NMEM*DDIM];
// downstream path: fp16 single-term
__device__ half g_ah[(size_t)ROWS*DDIM];
__device__ half g_hh[(size_t)ROWS*DDIM];
__device__ half g_wqkv[(size_t)DDIM*TOTW];
__device__ half g_w1[(size_t)DDIM*DDIM];
__device__ half g_w2[(size_t)DDIM*DDIM];
__device__ half g_ws1[(size_t)DDIM*DDIM];
__device__ half g_ws2[(size_t)DDIM*DDIM];     // 511->512 pad

// ---------------- cp.async helpers ------------------------------------------
__device__ __forceinline__ void cp16(void* dst_smem, const void* src, bool pred) {
    unsigned d = (unsigned)__cvta_generic_to_shared(dst_smem);
    int sz = pred ? 16 : 0;
    asm volatile("cp.async.cg.shared.global [%0], [%1], 16, %2;\n"
                 :: "r"(d), "l"(src), "r"(sz));
}
__device__ __forceinline__ void cp_commit() {
    asm volatile("cp.async.commit_group;\n");
}
template<int NN>
__device__ __forceinline__ void cp_wait() {
    asm volatile("cp.async.wait_group %0;\n" :: "n"(NN));
}

__device__ __forceinline__ unsigned short f2key16(unsigned short b) {
    return (b & 0x8000u) ? (unsigned short)(~b) : (unsigned short)(b | 0x8000u);
}
__device__ __forceinline__ float key16_to_f(unsigned short k) {
    unsigned short raw = (k & 0x8000u) ? (unsigned short)(k & 0x7FFFu)
                                       : (unsigned short)(~k);
    __nv_bfloat16_raw br; br.x = raw;
    return __bfloat162float((bf16)br);
}

template<typename T> __device__ __forceinline__ T f2t(float v);
template<> __device__ __forceinline__ half f2t<half>(float v) { return __float2half_rn(v); }
template<> __device__ __forceinline__ bf16 f2t<bf16>(float v) { return __float2bfloat16_rn(v); }

// ---------------- fp32 -> T convert, one row per block ----------------------
template<typename T>
__global__ void conv_rows_kernel(const float* __restrict__ src,
                                 T* __restrict__ dst, int scols, int dcols)
{
    const int r = blockIdx.x;
    const float* s = src + (size_t)r * scols;
    T* d = dst + (size_t)r * dcols;
    for (int c = threadIdx.x; c < dcols; c += blockDim.x)
        d[c] = f2t<T>(c < scols ? s[c] : 0.f);
}

// ---------------- WMMA GEMM: 128x128 tile, 3-stage cp.async, 2 CTA/SM -------
template<typename TT, int EPI, bool BCOL>
__global__ void __launch_bounds__(256, 2) wgemm(
    const TT* __restrict__ A, const TT* __restrict__ B,
    const float* __restrict__ bias, float* __restrict__ C,
    TT* __restrict__ OH,
    int M, int N, int K, int lda, int ldb, int ldc)
{
    extern __shared__ __align__(16) char smem[];
    constexpr int AP  = 40;
    constexpr int BPR = 136;
    constexpr int STAGE = 20480;

    const int tid = threadIdx.x;
    const int w = tid >> 5, lane = tid & 31;
    const int wm = w >> 1, wn = w & 1;
    const int m0 = blockIdx.y * 128, n0 = blockIdx.x * 128;

    wmma::fragment<wmma::accumulator, 16, 16, 16, float> acc[2][4];
#pragma unroll
    for (int i = 0; i < 2; i++)
#pragma unroll
        for (int j = 0; j < 4; j++) wmma::fill_fragment(acc[i][j], 0.f);

    auto issue = [&](int k0, int s) {
        char* base = smem + s * STAGE;
        TT* sA = (TT*)base;
        TT* sB = (TT*)(base + 10240);
#pragma unroll
        for (int e = 0; e < 2; e++) {
            int idx = tid + e * 256;
            {
                int row = idx >> 2, c4 = idx & 3;
                size_t off = (size_t)(m0 + row) * lda + k0 + c4 * 8;
                cp16(sA + row * AP + c4 * 8, A + off, true);
            }
            if (BCOL) {
                int n = idx >> 2, c4 = idx & 3;
                bool v = (n0 + n) < N;
                size_t off = v ? ((size_t)(n0 + n) * ldb + k0 + c4 * 8) : 0;
                cp16(sB + n * AP + c4 * 8, B + off, v);
            } else {
                int row = idx >> 4, c4 = idx & 15;
                size_t off = (size_t)(k0 + row) * ldb + n0 + c4 * 8;
                cp16(sB + row * BPR + c4 * 8, B + off, true);
            }
        }
        cp_commit();
    };

    auto compute = [&](int s) {
        char* base = smem + s * STAGE;
        TT* sA = (TT*)base;
        TT* sB = (TT*)(base + 10240);
#pragma unroll
        for (int kf = 0; kf < 32; kf += 16) {
            wmma::fragment<wmma::matrix_a, 16, 16, 16, TT, wmma::row_major> af[2];
#pragma unroll
            for (int i = 0; i < 2; i++)
                wmma::load_matrix_sync(af[i], sA + (wm * 32 + i * 16) * AP + kf, AP);
            if constexpr (BCOL) {
                wmma::fragment<wmma::matrix_b, 16, 16, 16, TT, wmma::col_major> bf;
#pragma unroll
                for (int j = 0; j < 4; j++) {
                    wmma::load_matrix_sync(bf, sB + (wn * 64 + j * 16) * AP + kf, AP);
#pragma unroll
                    for (int i = 0; i < 2; i++)
                        wmma::mma_sync(acc[i][j], af[i], bf, acc[i][j]);
                }
            } else {
                wmma::fragment<wmma::matrix_b, 16, 16, 16, TT, wmma::row_major> bf;
#pragma unroll
                for (int j = 0; j < 4; j++) {
                    wmma::load_matrix_sync(bf, sB + kf * BPR + wn * 64 + j * 16, BPR);
#pragma unroll
                    for (int i = 0; i < 2; i++)
                        wmma::mma_sync(acc[i][j], af[i], bf, acc[i][j]);
                }
            }
        }
    };

    issue(0, 0);
    if (32 < K) issue(32, 1);
    int cur = 0;
    for (int k0 = 0; k0 < K; k0 += 32) {
        if (k0 + 32 < K) cp_wait<1>(); else cp_wait<0>();
        __syncthreads();
        if (k0 + 64 < K) issue(k0 + 64, (cur + 2) % 3);
        compute(cur);
        cur = (cur + 1) % 3;
    }
    __syncthreads();

    float* ep = (float*)smem + w * 2176;
#pragma unroll
    for (int i = 0; i < 2; i++)
#pragma unroll
        for (int j = 0; j < 4; j++)
            wmma::store_matrix_sync(ep + i * 16 * 68 + j * 16, acc[i][j], 68,
                                    wmma::mem_row_major);
    __syncwarp();
#pragma unroll 4
    for (int r = 0; r < 32; r++) {
        int gm = m0 + wm * 32 + r;
#pragma unroll
        for (int it = 0; it < 2; it++) {
            int gn = n0 + wn * 64 + it * 32 + lane;
            if (gn < N) {
                float v = ep[r * 68 + it * 32 + lane];
                if (EPI >= 1) v += bias[gn];
                if (EPI == 2) v = fmaxf(v, 0.f);
                size_t off = (size_t)gm * ldc + gn;
                if (C) C[off] = v;
                if (OH) OH[off] = f2t<TT>(v);
            }
        }
    }
}

// ---------------- approx top-64: 2-pass uint16 radix, per-warp hists --------
__global__ void __launch_bounds__(256) topk16_kernel()
{
    const int r = blockIdx.x, tid = threadIdx.x;
    const int wid = tid >> 5;
    const bf16* row = g_tau16 + (size_t)r * NMEM;
    const uint4* row4 = (const uint4*)row;
    __shared__ unsigned hist[8 * 256];
    __shared__ int sh_d, sh_need, cnt;
    unsigned* myh = hist + wid * 256;

    for (int i = tid; i < 8 * 256; i += 256) hist[i] = 0;
    __syncthreads();
    for (int i = tid; i < NMEM / 8; i += 256) {
        uint4 q = row4[i];
        unsigned short hb[8] = {
            (unsigned short)(q.x & 0xFFFFu), (unsigned short)(q.x >> 16),
            (unsigned short)(q.y & 0xFFFFu), (unsigned short)(q.y >> 16),
            (unsigned short)(q.z & 0xFFFFu), (unsigned short)(q.z >> 16),
            (unsigned short)(q.w & 0xFFFFu), (unsigned short)(q.w >> 16)};
#pragma unroll
        for (int t = 0; t < 8; t++)
            atomicAdd(&myh[f2key16(hb[t]) >> 8], 1u);
    }
    __syncthreads();
    {
        unsigned tot = 0;
#pragma unroll
        for (int wdx = 0; wdx < 8; wdx++) tot += hist[wdx * 256 + tid];
        __syncthreads();
        hist[tid] = tot;
    }
    __syncthreads();
    if (tid == 0) {
        int cum = 0, d = 255;
        for (; d >= 0; --d) {
            if (cum + (int)hist[d] >= KTOP) break;
            cum += (int)hist[d];
        }
        if (d < 0) d = 0;
        sh_d = d; sh_need = KTOP - cum;
    }
    __syncthreads();
    const unsigned hi8 = (unsigned)sh_d;
    const int need = sh_need;
    __syncthreads();

    for (int i = tid; i < 8 * 256; i += 256) hist[i] = 0;
    __syncthreads();
    for (int i = tid; i < NMEM / 8; i += 256) {
        uint4 q = row4[i];
        unsigned short hb[8] = {
            (unsigned short)(q.x & 0xFFFFu), (unsigned short)(q.x >> 16),
            (unsigned short)(q.y & 0xFFFFu), (unsigned short)(q.y >> 16),
            (unsigned short)(q.z & 0xFFFFu), (unsigned short)(q.z >> 16),
            (unsigned short)(q.w & 0xFFFFu), (unsigned short)(q.w >> 16)};
#pragma unroll
        for (int t = 0; t < 8; t++) {
            unsigned short k = f2key16(hb[t]);
            if ((k >> 8) == hi8) atomicAdd(&myh[k & 0xFFu], 1u);
        }
    }
    __syncthreads();
    {
        unsigned tot = 0;
#pragma unroll
        for (int wdx = 0; wdx < 8; wdx++) tot += hist[wdx * 256 + tid];
        __syncthreads();
        hist[tid] = tot;
    }
    __syncthreads();
    if (tid == 0) {
        int cum = 0, d = 255;
        for (; d >= 0; --d) {
            if (cum + (int)hist[d] >= need) break;
            cum += (int)hist[d];
        }
        if (d < 0) d = 0;
        sh_d = d;
        cnt = 0;
    }
    __syncthreads();
    const unsigned short k64 = (unsigned short)((hi8 << 8) | (unsigned)sh_d);
    const float thr = key16_to_f(k64) - 2.0f;
    __syncthreads();

    for (int i = tid; i < NMEM / 8; i += 256) {
        uint4 q = row4[i];
        unsigned short hb[8] = {
            (unsigned short)(q.x & 0xFFFFu), (unsigned short)(q.x >> 16),
            (unsigned short)(q.y & 0xFFFFu), (unsigned short)(q.y >> 16),
            (unsigned short)(q.z & 0xFFFFu), (unsigned short)(q.z >> 16),
            (unsigned short)(q.w & 0xFFFFu), (unsigned short)(q.w >> 16)};
#pragma unroll
        for (int t = 0; t < 8; t++) {
            __nv_bfloat16_raw br; br.x = hb[t];
            if (__bfloat162float((bf16)br) >= thr) {
                int p = atomicAdd(&cnt, 1);
                if (p < CAP) g_candidx[(size_t)r * CAP + p] = i * 8 + t;
            }
        }
    }
    __syncthreads();
    if (tid == 0) g_candcnt[r] = (cnt < CAP) ? cnt : CAP;
}

// ---------------- fp32 rescore (sequential-k fma, UNCHANGED) ----------------
__global__ void __launch_bounds__(256) rescore_kernel(
    const float* __restrict__ c, const float* __restrict__ mem_c)
{
    const int r = blockIdx.x, tid = threadIdx.x;
    __shared__ float sc[512];
    __shared__ float scores[CAP];
    __shared__ int   cidx[CAP];
    const int nc = g_candcnt[r];

    for (int k = tid; k < CDIM; k += 256) sc[k] = c[(size_t)r * CDIM + k];
    for (int i = tid; i < nc; i += 256) cidx[i] = g_candidx[(size_t)r * CAP + i];
    __syncthreads();

    for (int ci = tid; ci < nc; ci += 256) {
        const float* mr = mem_c + (size_t)cidx[ci] * CDIM;
        float s = 0.f;
#pragma unroll 8
        for (int k = 0; k < CDIM; k++) s = fmaf(sc[k], mr[k], s);
        scores[ci] = s;
    }
    __syncthreads();

    for (int ci = tid; ci < nc; ci += 256) {
        float v = scores[ci]; int id = cidx[ci];
        int rank = 0;
        for (int j = 0; j < nc; j++) {
            float vj = scores[j];
            rank += (vj > v) || (vj == v && cidx[j] < id);
        }
        if (rank < KTOP) {
            g_deltas[r * KTOP + rank] = v;
            g_topidx[r * KTOP + rank] = id;
        }
    }
}

// ---------------- mems = concat(delta, mem_c[idx]) + fp16 emit --------------
__global__ void build_mems_kernel(const float* __restrict__ mem_c)
{
    const int row = blockIdx.x, tid = threadIdx.x;
    const int idx = g_topidx[row];
    const float d0 = g_deltas[row];
    float* out = g_mems + (size_t)row * DDIM;
    half*  oh  = g_ah  + (size_t)row * DDIM;
    const float* src = mem_c + (size_t)idx * CDIM;
    for (int cpos = tid; cpos < DDIM; cpos += blockDim.x) {
        float v = (cpos == 0) ? d0 : src[cpos - 1];
        out[cpos] = v;
        oh[cpos] = __float2half_rn(v);
    }
}

// ---------------- single-pass vectorized LayerNorm (fp16 emit) --------------
__global__ void ln_kernel(
    const float* __restrict__ x, const float* __restrict__ res,
    const float* __restrict__ g, const float* __restrict__ bb,
    float* __restrict__ out, half* __restrict__ oh, int W)
{
    const int row = blockIdx.x, tid = threadIdx.x;
    float4 v = ((const float4*)(x + (size_t)row * W))[tid];
    if (res) {
        float4 r = ((const float4*)(res + (size_t)row * W))[tid];
        v.x += r.x; v.y += r.y; v.z += r.z; v.w += r.w;
    }
    float s  = v.x + v.y + v.z + v.w;
    float s2 = v.x * v.x + v.y * v.y + v.z * v.z + v.w * v.w;
    __shared__ float red1[8], red2[8];
#pragma unroll
    for (int o = 16; o > 0; o >>= 1) {
        s  += __shfl_xor_sync(0xFFFFFFFFu, s, o);
        s2 += __shfl_xor_sync(0xFFFFFFFFu, s2, o);
    }
    const int wid = tid >> 5, nw = blockDim.x >> 5;
    if ((tid & 31) == 0) { red1[wid] = s; red2[wid] = s2; }
    __syncthreads();
    if (tid < 32) {
        s  = (tid < nw) ? red1[tid] : 0.f;
        s2 = (tid < nw) ? red2[tid] : 0.f;
#pragma unroll
        for (int o = 4; o > 0; o >>= 1) {
            s  += __shfl_xor_sync(0xFFFFFFFFu, s, o);
            s2 += __shfl_xor_sync(0xFFFFFFFFu, s2, o);
        }
        if (tid == 0) { red1[0] = s; red2[0] = s2; }
    }
    __syncthreads();
    const float mu = red1[0] / W;
    const float var = red2[0] / W - mu * mu;
    const float rs = rsqrtf(var + 1e-5f);

    float4 gg = ((const float4*)g)[tid];
    float4 b4 = ((const float4*)bb)[tid];
    float4 y;
    y.x = (v.x - mu) * rs * gg.x + b4.x;
    y.y = (v.y - mu) * rs * gg.y + b4.y;
    y.z = (v.z - mu) * rs * gg.z + b4.z;
    y.w = (v.w - mu) * rs * gg.w + b4.w;
    ((float4*)(out + (size_t)row * W))[tid] = y;
    if (oh) {
        union { half h[4]; uint2 u; } H;
        H.h[0] = __float2half_rn(y.x);
        H.h[1] = __float2half_rn(y.y);
        H.h[2] = __float2half_rn(y.z);
        H.h[3] = __float2half_rn(y.w);
        ((uint2*)(oh + (size_t)row * W))[tid] = H.u;
    }
}

// ---------------- fused LN(qkv) + attention per batch ------------------------
// smem: qkv tile 64 x 645 fp32, scores 64 x 68 (float4-aligned rows), mu/rs.
#define QP 645
#define SP 68
__global__ void __launch_bounds__(256) attn_ln_kernel(
    const float* __restrict__ gq, const float* __restrict__ gb)
{
    extern __shared__ float smf[];
    float* sqkv = smf;                    // 64*645
    float* ss   = smf + 64 * QP;          // 64*68
    float* smu  = ss + 64 * SP;           // 64
    float* srs  = smu + 64;               // 64
    const int b = blockIdx.x, tid = threadIdx.x;
    const int wid = tid >> 5, lane = tid & 31;
    const float* qkv = g_qkvbuf + (size_t)b * 64 * TOTW;

    for (int e = tid; e < 64 * TOTW; e += 256) {
        int i = e / TOTW, col = e % TOTW;
        sqkv[i * QP + col] = qkv[e];
    }
    __syncthreads();

    // per-row LN stats: warp w handles rows 8w..8w+7
    for (int rr = 0; rr < 8; rr++) {
        int rowi = wid * 8 + rr;
        float s = 0.f, s2 = 0.f;
        for (int col = lane; col < TOTW; col += 32) {
            float v = sqkv[rowi * QP + col];
            s += v; s2 += v * v;
        }
#pragma unroll
        for (int o = 16; o > 0; o >>= 1) {
            s  += __shfl_xor_sync(0xFFFFFFFFu, s, o);
            s2 += __shfl_xor_sync(0xFFFFFFFFu, s2, o);
        }
        if (lane == 0) {
            float mu = s / TOTW;
            float var = s2 / TOTW - mu * mu;
            smu[rowi] = mu;
            srs[rowi] = rsqrtf(var + 1e-5f);
        }
    }
    __syncthreads();

    // normalize in place (+ q-scale for cols < 64)
    for (int e = tid; e < 64 * TOTW; e += 256) {
        int i = e / TOTW, col = e % TOTW;
        float v = (sqkv[i * QP + col] - smu[i]) * srs[i] * gq[col] + gb[col];
        if (col < KEYS) v *= 0.125f;
        sqkv[i * QP + col] = v;
    }
    __syncthreads();

    // scores[i][j] = sum_d q[i][d] * k[j][d]
    for (int e = tid; e < 4096; e += 256) {
        int i = e >> 6, j = e & 63;
        float acc = 0.f;
#pragma unroll 16
        for (int d = 0; d < 64; d++)
            acc += sqkv[i * QP + d] * sqkv[j * QP + KEYS + d];
        ss[i * SP + j] = acc;
    }
    __syncthreads();

    // softmax: warp per row group
    for (int rowi = wid; rowi < 64; rowi += 8) {
        float m = -1e30f;
        for (int j = lane; j < 64; j += 32) m = fmaxf(m, ss[rowi * SP + j]);
#pragma unroll
        for (int o = 16; o > 0; o >>= 1)
            m = fmaxf(m, __shfl_xor_sync(0xFFFFFFFFu, m, o));
        float s = 0.f;
        for (int j = lane; j < 64; j += 32) {
            float e = expf(ss[rowi * SP + j] - m);
            ss[rowi * SP + j] = e; s += e;
        }
#pragma unroll
        for (int o = 16; o > 0; o >>= 1)
            s += __shfl_xor_sync(0xFFFFFFFFu, s, o);
        float inv = 1.f / s;
        for (int j = lane; j < 64; j += 32) ss[rowi * SP + j] *= inv;
    }
    __syncthreads();

    // attended: thread owns one d column; acc[64] in registers,
    // v cached 8-at-a-time, weights read as broadcast float4.
    for (int dpass = 0; dpass < 2; dpass++) {
        const int d = dpass * 256 + tid;
        float acc[64];
#pragma unroll
        for (int i = 0; i < 64; i++) acc[i] = 0.f;
        for (int jb = 0; jb < 64; jb += 8) {
            float vv[8];
#pragma unroll
            for (int t = 0; t < 8; t++)
                vv[t] = sqkv[(jb + t) * QP + 2 * KEYS + d];
#pragma unroll
            for (int i = 0; i < 64; i++) {
                float4 w0 = *(const float4*)&ss[i * SP + jb];
                float4 w1 = *(const float4*)&ss[i * SP + jb + 4];
                acc[i] += w0.x * vv[0] + w0.y * vv[1] + w0.z * vv[2] + w0.w * vv[3]
                        + w1.x * vv[4] + w1.y * vv[5] + w1.z * vv[6] + w1.w * vv[7];
            }
        }
#pragma unroll
        for (int i = 0; i < 64; i++)
            g_att[(size_t)(b * 64 + i) * DDIM + d] = acc[i];
    }
}

// ---------------- host orchestration -----------------------------------------
extern "C" void kernel_launch(void* const* d_in, const int* in_sizes, int n_in,
                              void* d_out, int out_size)
{
    const float* c     = (const float*)d_in[0];
    const float* mem_c = (const float*)d_in[1];
    const float* Wqkv  = (const float*)d_in[2];
    const float* bqkv  = (const float*)d_in[3];
    const float* gq    = (const float*)d_in[4];
    const float* bq    = (const float*)d_in[5];
    const float* gm    = (const float*)d_in[6];
    const float* bm    = (const float*)d_in[7];
    const float* W1    = (const float*)d_in[8];
    const float* b1    = (const float*)d_in[9];
    const float* W2    = (const float*)d_in[10];
    const float* b2    = (const float*)d_in[11];
    const float* Ws1   = (const float*)d_in[12];
    const float* bs1   = (const float*)d_in[13];
    const float* Ws2   = (const float*)d_in[14];
    const float* bs2   = (const float*)d_in[15];
    float* out = (float*)d_out;

    float *p_mems, *p_qkv, *p_att, *p_mem, *p_t2;
    bf16 *p_tau16, *p_c16, *p_mc16;
    half *p_ah, *p_hh, *p_wq, *p_w1, *p_w2, *p_s1, *p_s2;
    cudaGetSymbolAddress((void**)&p_tau16, g_tau16);
    cudaGetSymbolAddress((void**)&p_mems, g_mems);
    cudaGetSymbolAddress((void**)&p_qkv,  g_qkvbuf);
    cudaGetSymbolAddress((void**)&p_att,  g_att);
    cudaGetSymbolAddress((void**)&p_mem,  g_mem);
    cudaGetSymbolAddress((void**)&p_t2,   g_t2);
    cudaGetSymbolAddress((void**)&p_c16,  g_c16);
    cudaGetSymbolAddress((void**)&p_mc16, g_mc16);
    cudaGetSymbolAddress((void**)&p_ah,   g_ah);
    cudaGetSymbolAddress((void**)&p_hh,   g_hh);
    cudaGetSymbolAddress((void**)&p_wq,   g_wqkv);
    cudaGetSymbolAddress((void**)&p_w1,   g_w1);
    cudaGetSymbolAddress((void**)&p_w2,   g_w2);
    cudaGetSymbolAddress((void**)&p_s1,   g_ws1);
    cudaGetSymbolAddress((void**)&p_s2,   g_ws2);

    const int SM_WG = 69632;                              // 3*20480 stages | epi
    const int SM_ATTN = (64 * QP + 64 * SP + 128) * 4;    // 183040
    cudaFuncSetAttribute(wgemm<bf16, 0, true>,  cudaFuncAttributeMaxDynamicSharedMemorySize, SM_WG);
    cudaFuncSetAttribute(wgemm<half, 1, false>, cudaFuncAttributeMaxDynamicSharedMemorySize, SM_WG);
    cudaFuncSetAttribute(wgemm<half, 2, false>, cudaFuncAttributeMaxDynamicSharedMemorySize, SM_WG);
    cudaFuncSetAttribute(attn_ln_kernel, cudaFuncAttributeMaxDynamicSharedMemorySize, SM_ATTN);
    const dim3 blk(256);

    // --- input/weight conversions ---
    conv_rows_kernel<bf16><<<NB,   128>>>(c,     p_c16,  CDIM, DDIM);
    conv_rows_kernel<bf16><<<NMEM, 128>>>(mem_c, p_mc16, CDIM, DDIM);
    conv_rows_kernel<half><<<DDIM, 128>>>(Wqkv, p_wq, TOTW, TOTW);
    conv_rows_kernel<half><<<DDIM, 128>>>(W1,   p_w1, DDIM, DDIM);
    conv_rows_kernel<half><<<DDIM, 128>>>(W2,   p_w2, DDIM, DDIM);
    conv_rows_kernel<half><<<DDIM, 128>>>(Ws1,  p_s1, DDIM, DDIM);
    conv_rows_kernel<half><<<DDIM, 128>>>(Ws2,  p_s2, CDIM, DDIM);

    // --- 1) approx tau (bf16 out) = c16 @ mc16^T ---
    wgemm<bf16, 0, true><<<dim3((NMEM + 127) / 128, 2), blk, SM_WG>>>(
        p_c16, p_mc16, nullptr, nullptr, p_tau16,
        NB, NMEM, DDIM, DDIM, DDIM, NMEM);

    // --- 2) radix candidate select + exact fp32 rescore ---
    topk16_kernel<<<NB, blk>>>();
    rescore_kernel<<<NB, blk>>>(c, mem_c);

    // --- 3) mems + fp16 emit ---
    build_mems_kernel<<<ROWS, 128>>>(mem_c);

    // --- 4) qkv = mems @ Wqkv + bqkv  (LN fused into attention) ---
    wgemm<half, 1, false><<<dim3(5, 128), blk, SM_WG>>>(
        p_ah, p_wq, bqkv, p_qkv, (half*)nullptr,
        ROWS, TOTW, DDIM, DDIM, TOTW, TOTW);

    // --- 5) fused LN + attention ---
    attn_ln_kernel<<<NB, blk, SM_ATTN>>>(gq, bq);

    // --- 6) mem = LN(mems + attended)  (+ fp16 emit) ---
    ln_kernel<<<ROWS, 128>>>(p_mems, p_att, gm, bm, p_mem, p_ah, DDIM);

    // --- 7) two residual MLP blocks ---
    for (int rep = 0; rep < 2; rep++) {
        wgemm<half, 2, false><<<dim3(4, 128), blk, SM_WG>>>(
            p_ah, p_w1, b1, nullptr, p_hh,
            ROWS, DDIM, DDIM, DDIM, DDIM, DDIM);
        wgemm<half, 1, false><<<dim3(4, 128), blk, SM_WG>>>(
            p_hh, p_w2, b2, p_t2, (half*)nullptr,
            ROWS, DDIM, DDIM, DDIM, DDIM, DDIM);
        ln_kernel<<<ROWS, 128>>>(p_t2, p_mem, gm, bm, p_mem, p_ah, DDIM);
    }

    // --- 8) c_prime = relu(mem @ Ws1 + bs1) @ Ws2 + bs2 ---
    wgemm<half, 2, false><<<dim3(4, 128), blk, SM_WG>>>(
        p_ah, p_s1, bs1, nullptr, p_hh,
        ROWS, DDIM, DDIM, DDIM, DDIM, DDIM);
    wgemm<half, 1, false><<<dim3(4, 128), blk, SM_WG>>>(
        p_hh, p_s2, bs2, out, (half*)nullptr,
        ROWS, CDIM, DDIM, DDIM, DDIM, CDIM);
}

// round 11
// speedup vs baseline: 2.2212x; 1.0379x over previous
#include <cuda_runtime.h>
#include <cuda_bf16.h>
#include <cuda_fp16.h>
#include <mma.h>
#include <math.h>

using namespace nvcuda;
typedef __nv_bfloat16 bf16;

#define NB    256
#define NMEM  100000
#define CDIM  511
#define DDIM  512
#define KEYS  64
#define TOTW  640
#define KTOP  64
#define ROWS  (NB*KTOP)   // 16384
#define CAP   1024        // candidate cap per row

// ---------------- scratch (device globals; no allocations allowed) ----------
__device__ bf16  g_tau16[(size_t)NB*NMEM];     // approx tau in bf16, 51.2 MB
__device__ float g_deltas[NB*KTOP];
__device__ int   g_topidx[NB*KTOP];
__device__ int   g_candidx[(size_t)NB*CAP];
__device__ int   g_candcnt[NB];
__device__ float g_mems[(size_t)ROWS*DDIM];
__device__ float g_qkvbuf[(size_t)ROWS*TOTW];
__device__ float g_att[(size_t)ROWS*DDIM];
__device__ float g_mem[(size_t)ROWS*DDIM];
__device__ float g_t2[(size_t)ROWS*DDIM];

// tau path stays bf16 (selection invariance)
__device__ bf16 g_c16[(size_t)NB*DDIM];
__device__ bf16 g_mc16[(size_t)NMEM*DDIM];
// downstream path: fp16 single-term
__device__ half g_ah[(size_t)ROWS*DDIM];
__device__ half g_hh[(size_t)ROWS*DDIM];
__device__ half g_wqkv[(size_t)DDIM*TOTW];
__device__ half g_w1[(size_t)DDIM*DDIM];
__device__ half g_w2[(size_t)DDIM*DDIM];
__device__ half g_ws1[(size_t)DDIM*DDIM];
__device__ half g_ws2[(size_t)DDIM*DDIM];     // 511->512 pad

// ---------------- cp.async helpers ------------------------------------------
__device__ __forceinline__ void cp16(void* dst_smem, const void* src, bool pred) {
    unsigned d = (unsigned)__cvta_generic_to_shared(dst_smem);
    int sz = pred ? 16 : 0;
    asm volatile("cp.async.cg.shared.global [%0], [%1], 16, %2;\n"
                 :: "r"(d), "l"(src), "r"(sz));
}
__device__ __forceinline__ void cp_commit() {
    asm volatile("cp.async.commit_group;\n");
}
template<int NN>
__device__ __forceinline__ void cp_wait() {
    asm volatile("cp.async.wait_group %0;\n" :: "n"(NN));
}

__device__ __forceinline__ unsigned short f2key16(unsigned short b) {
    return (b & 0x8000u) ? (unsigned short)(~b) : (unsigned short)(b | 0x8000u);
}
__device__ __forceinline__ float key16_to_f(unsigned short k) {
    unsigned short raw = (k & 0x8000u) ? (unsigned short)(k & 0x7FFFu)
                                       : (unsigned short)(~k);
    __nv_bfloat16_raw br; br.x = raw;
    return __bfloat162float((bf16)br);
}

template<typename T> __device__ __forceinline__ T f2t(float v);
template<> __device__ __forceinline__ half f2t<half>(float v) { return __float2half_rn(v); }
template<> __device__ __forceinline__ bf16 f2t<bf16>(float v) { return __float2bfloat16_rn(v); }

// ---------------- fp32 -> T convert, one row per block ----------------------
template<typename T>
__global__ void conv_rows_kernel(const float* __restrict__ src,
                                 T* __restrict__ dst, int scols, int dcols)
{
    const int r = blockIdx.x;
    const float* s = src + (size_t)r * scols;
    T* d = dst + (size_t)r * dcols;
    for (int c = threadIdx.x; c < dcols; c += blockDim.x)
        d[c] = f2t<T>(c < scols ? s[c] : 0.f);
}

// ---------------- WMMA GEMM: 128x128 tile, K-chunk 64, 2-stage, 2 CTA/SM ----
// One barrier per iteration: barrier at iter i proves all warps finished
// compute on stage cur^1 (iter i-1), so re-issuing into it is race-free;
// the next chunk's cp.async overlaps with compute(cur).
template<typename TT, int EPI, bool BCOL>
__global__ void __launch_bounds__(256, 2) wgemm(
    const TT* __restrict__ A, const TT* __restrict__ B,
    const float* __restrict__ bias, float* __restrict__ C,
    TT* __restrict__ OH,
    int M, int N, int K, int lda, int ldb, int ldc)
{
    extern __shared__ __align__(16) char smem[];
    constexpr int AP  = 72;    // A / BCOL-B smem leading dim (elements), K-chunk 64
    constexpr int BPR = 136;   // row-major B smem leading dim (elements)
    constexpr int STAGE = 36864;

    const int tid = threadIdx.x;
    const int w = tid >> 5, lane = tid & 31;
    const int wm = w >> 1, wn = w & 1;
    const int m0 = blockIdx.y * 128, n0 = blockIdx.x * 128;

    wmma::fragment<wmma::accumulator, 16, 16, 16, float> acc[2][4];
#pragma unroll
    for (int i = 0; i < 2; i++)
#pragma unroll
        for (int j = 0; j < 4; j++) wmma::fill_fragment(acc[i][j], 0.f);

    // async copy of one 64-wide K chunk into stage s
    auto issue = [&](int k0, int s) {
        char* base = smem + s * STAGE;
        TT* sA = (TT*)base;
        TT* sB = (TT*)(base + 18432);
#pragma unroll
        for (int e = 0; e < 4; e++) {
            int idx = tid + e * 256;
            {   // A: 128 rows x 64 elements = 8 uint4 per row
                int row = idx >> 3, c4 = idx & 7;
                size_t off = (size_t)(m0 + row) * lda + k0 + c4 * 8;
                cp16(sA + row * AP + c4 * 8, A + off, true);
            }
            if (BCOL) {     // B^T tile: 128 n-rows x 64 k-elements
                int n = idx >> 3, c4 = idx & 7;
                bool v = (n0 + n) < N;
                size_t off = v ? ((size_t)(n0 + n) * ldb + k0 + c4 * 8) : 0;
                cp16(sB + n * AP + c4 * 8, B + off, v);
            } else {        // B tile: 64 k-rows x 128 n-elements = 16 uint4 per row
                int row = idx >> 4, c4 = idx & 15;
                size_t off = (size_t)(k0 + row) * ldb + n0 + c4 * 8;
                cp16(sB + row * BPR + c4 * 8, B + off, true);
            }
        }
        cp_commit();
    };

    auto compute = [&](int s) {
        char* base = smem + s * STAGE;
        TT* sA = (TT*)base;
        TT* sB = (TT*)(base + 18432);
#pragma unroll
        for (int kf = 0; kf < 64; kf += 16) {
            wmma::fragment<wmma::matrix_a, 16, 16, 16, TT, wmma::row_major> af[2];
#pragma unroll
            for (int i = 0; i < 2; i++)
                wmma::load_matrix_sync(af[i], sA + (wm * 32 + i * 16) * AP + kf, AP);
            if constexpr (BCOL) {
                wmma::fragment<wmma::matrix_b, 16, 16, 16, TT, wmma::col_major> bf;
#pragma unroll
                for (int j = 0; j < 4; j++) {
                    wmma::load_matrix_sync(bf, sB + (wn * 64 + j * 16) * AP + kf, AP);
#pragma unroll
                    for (int i = 0; i < 2; i++)
                        wmma::mma_sync(acc[i][j], af[i], bf, acc[i][j]);
                }
            } else {
                wmma::fragment<wmma::matrix_b, 16, 16, 16, TT, wmma::row_major> bf;
#pragma unroll
                for (int j = 0; j < 4; j++) {
                    wmma::load_matrix_sync(bf, sB + kf * BPR + wn * 64 + j * 16, BPR);
#pragma unroll
                    for (int i = 0; i < 2; i++)
                        wmma::mma_sync(acc[i][j], af[i], bf, acc[i][j]);
                }
            }
        }
    };

    // 2-stage pipeline, 1 barrier/iter, prefetch depth 1 chunk
    issue(0, 0);
    int cur = 0;
    for (int k0 = 0; k0 < K; k0 += 64) {
        cp_wait<0>();
        __syncthreads();
        if (k0 + 64 < K) issue(k0 + 64, cur ^ 1);
        compute(cur);
        cur ^= 1;
    }
    __syncthreads();

    float* ep = (float*)smem + w * 2176;
#pragma unroll
    for (int i = 0; i < 2; i++)
#pragma unroll
        for (int j = 0; j < 4; j++)
            wmma::store_matrix_sync(ep + i * 16 * 68 + j * 16, acc[i][j], 68,
                                    wmma::mem_row_major);
    __syncwarp();
#pragma unroll 4
    for (int r = 0; r < 32; r++) {
        int gm = m0 + wm * 32 + r;
#pragma unroll
        for (int it = 0; it < 2; it++) {
            int gn = n0 + wn * 64 + it * 32 + lane;
            if (gn < N) {
                float v = ep[r * 68 + it * 32 + lane];
                if (EPI >= 1) v += bias[gn];
                if (EPI == 2) v = fmaxf(v, 0.f);
                size_t off = (size_t)gm * ldc + gn;
                if (C) C[off] = v;
                if (OH) OH[off] = f2t<TT>(v);
            }
        }
    }
}

// ---------------- approx top-64: 2-pass uint16 radix, per-warp hists --------
__global__ void __launch_bounds__(256) topk16_kernel()
{
    const int r = blockIdx.x, tid = threadIdx.x;
    const int wid = tid >> 5;
    const bf16* row = g_tau16 + (size_t)r * NMEM;
    const uint4* row4 = (const uint4*)row;
    __shared__ unsigned hist[8 * 256];
    __shared__ int sh_d, sh_need, cnt;
    unsigned* myh = hist + wid * 256;

    for (int i = tid; i < 8 * 256; i += 256) hist[i] = 0;
    __syncthreads();
    for (int i = tid; i < NMEM / 8; i += 256) {
        uint4 q = row4[i];
        unsigned short hb[8] = {
            (unsigned short)(q.x & 0xFFFFu), (unsigned short)(q.x >> 16),
            (unsigned short)(q.y & 0xFFFFu), (unsigned short)(q.y >> 16),
            (unsigned short)(q.z & 0xFFFFu), (unsigned short)(q.z >> 16),
            (unsigned short)(q.w & 0xFFFFu), (unsigned short)(q.w >> 16)};
#pragma unroll
        for (int t = 0; t < 8; t++)
            atomicAdd(&myh[f2key16(hb[t]) >> 8], 1u);
    }
    __syncthreads();
    {
        unsigned tot = 0;
#pragma unroll
        for (int wdx = 0; wdx < 8; wdx++) tot += hist[wdx * 256 + tid];
        __syncthreads();
        hist[tid] = tot;
    }
    __syncthreads();
    if (tid == 0) {
        int cum = 0, d = 255;
        for (; d >= 0; --d) {
            if (cum + (int)hist[d] >= KTOP) break;
            cum += (int)hist[d];
        }
        if (d < 0) d = 0;
        sh_d = d; sh_need = KTOP - cum;
    }
    __syncthreads();
    const unsigned hi8 = (unsigned)sh_d;
    const int need = sh_need;
    __syncthreads();

    for (int i = tid; i < 8 * 256; i += 256) hist[i] = 0;
    __syncthreads();
    for (int i = tid; i < NMEM / 8; i += 256) {
        uint4 q = row4[i];
        unsigned short hb[8] = {
            (unsigned short)(q.x & 0xFFFFu), (unsigned short)(q.x >> 16),
            (unsigned short)(q.y & 0xFFFFu), (unsigned short)(q.y >> 16),
            (unsigned short)(q.z & 0xFFFFu), (unsigned short)(q.z >> 16),
            (unsigned short)(q.w & 0xFFFFu), (unsigned short)(q.w >> 16)};
#pragma unroll
        for (int t = 0; t < 8; t++) {
            unsigned short k = f2key16(hb[t]);
            if ((k >> 8) == hi8) atomicAdd(&myh[k & 0xFFu], 1u);
        }
    }
    __syncthreads();
    {
        unsigned tot = 0;
#pragma unroll
        for (int wdx = 0; wdx < 8; wdx++) tot += hist[wdx * 256 + tid];
        __syncthreads();
        hist[tid] = tot;
    }
    __syncthreads();
    if (tid == 0) {
        int cum = 0, d = 255;
        for (; d >= 0; --d) {
            if (cum + (int)hist[d] >= need) break;
            cum += (int)hist[d];
        }
        if (d < 0) d = 0;
        sh_d = d;
        cnt = 0;
    }
    __syncthreads();
    const unsigned short k64 = (unsigned short)((hi8 << 8) | (unsigned)sh_d);
    const float thr = key16_to_f(k64) - 2.0f;
    __syncthreads();

    for (int i = tid; i < NMEM / 8; i += 256) {
        uint4 q = row4[i];
        unsigned short hb[8] = {
            (unsigned short)(q.x & 0xFFFFu), (unsigned short)(q.x >> 16),
            (unsigned short)(q.y & 0xFFFFu), (unsigned short)(q.y >> 16),
            (unsigned short)(q.z & 0xFFFFu), (unsigned short)(q.z >> 16),
            (unsigned short)(q.w & 0xFFFFu), (unsigned short)(q.w >> 16)};
#pragma unroll
        for (int t = 0; t < 8; t++) {
            __nv_bfloat16_raw br; br.x = hb[t];
            if (__bfloat162float((bf16)br) >= thr) {
                int p = atomicAdd(&cnt, 1);
                if (p < CAP) g_candidx[(size_t)r * CAP + p] = i * 8 + t;
            }
        }
    }
    __syncthreads();
    if (tid == 0) g_candcnt[r] = (cnt < CAP) ? cnt : CAP;
}

// ---------------- fp32 rescore (sequential-k fma, UNCHANGED) ----------------
__global__ void __launch_bounds__(256) rescore_kernel(
    const float* __restrict__ c, const float* __restrict__ mem_c)
{
    const int r = blockIdx.x, tid = threadIdx.x;
    __shared__ float sc[512];
    __shared__ float scores[CAP];
    __shared__ int   cidx[CAP];
    const int nc = g_candcnt[r];

    for (int k = tid; k < CDIM; k += 256) sc[k] = c[(size_t)r * CDIM + k];
    for (int i = tid; i < nc; i += 256) cidx[i] = g_candidx[(size_t)r * CAP + i];
    __syncthreads();

    for (int ci = tid; ci < nc; ci += 256) {
        const float* mr = mem_c + (size_t)cidx[ci] * CDIM;
        float s = 0.f;
#pragma unroll 8
        for (int k = 0; k < CDIM; k++) s = fmaf(sc[k], mr[k], s);
        scores[ci] = s;
    }
    __syncthreads();

    for (int ci = tid; ci < nc; ci += 256) {
        float v = scores[ci]; int id = cidx[ci];
        int rank = 0;
        for (int j = 0; j < nc; j++) {
            float vj = scores[j];
            rank += (vj > v) || (vj == v && cidx[j] < id);
        }
        if (rank < KTOP) {
            g_deltas[r * KTOP + rank] = v;
            g_topidx[r * KTOP + rank] = id;
        }
    }
}

// ---------------- mems = concat(delta, mem_c[idx]) + fp16 emit --------------
__global__ void build_mems_kernel(const float* __restrict__ mem_c)
{
    const int row = blockIdx.x, tid = threadIdx.x;
    const int idx = g_topidx[row];
    const float d0 = g_deltas[row];
    float* out = g_mems + (size_t)row * DDIM;
    half*  oh  = g_ah  + (size_t)row * DDIM;
    const float* src = mem_c + (size_t)idx * CDIM;
    for (int cpos = tid; cpos < DDIM; cpos += blockDim.x) {
        float v = (cpos == 0) ? d0 : src[cpos - 1];
        out[cpos] = v;
        oh[cpos] = __float2half_rn(v);
    }
}

// ---------------- single-pass vectorized LayerNorm (fp16 emit) --------------
__global__ void ln_kernel(
    const float* __restrict__ x, const float* __restrict__ res,
    const float* __restrict__ g, const float* __restrict__ bb,
    float* __restrict__ out, half* __restrict__ oh, int W)
{
    const int row = blockIdx.x, tid = threadIdx.x;
    float4 v = ((const float4*)(x + (size_t)row * W))[tid];
    if (res) {
        float4 r = ((const float4*)(res + (size_t)row * W))[tid];
        v.x += r.x; v.y += r.y; v.z += r.z; v.w += r.w;
    }
    float s  = v.x + v.y + v.z + v.w;
    float s2 = v.x * v.x + v.y * v.y + v.z * v.z + v.w * v.w;
    __shared__ float red1[8], red2[8];
#pragma unroll
    for (int o = 16; o > 0; o >>= 1) {
        s  += __shfl_xor_sync(0xFFFFFFFFu, s, o);
        s2 += __shfl_xor_sync(0xFFFFFFFFu, s2, o);
    }
    const int wid = tid >> 5, nw = blockDim.x >> 5;
    if ((tid & 31) == 0) { red1[wid] = s; red2[wid] = s2; }
    __syncthreads();
    if (tid < 32) {
        s  = (tid < nw) ? red1[tid] : 0.f;
        s2 = (tid < nw) ? red2[tid] : 0.f;
#pragma unroll
        for (int o = 4; o > 0; o >>= 1) {
            s  += __shfl_xor_sync(0xFFFFFFFFu, s, o);
            s2 += __shfl_xor_sync(0xFFFFFFFFu, s2, o);
        }
        if (tid == 0) { red1[0] = s; red2[0] = s2; }
    }
    __syncthreads();
    const float mu = red1[0] / W;
    const float var = red2[0] / W - mu * mu;
    const float rs = rsqrtf(var + 1e-5f);

    float4 gg = ((const float4*)g)[tid];
    float4 b4 = ((const float4*)bb)[tid];
    float4 y;
    y.x = (v.x - mu) * rs * gg.x + b4.x;
    y.y = (v.y - mu) * rs * gg.y + b4.y;
    y.z = (v.z - mu) * rs * gg.z + b4.z;
    y.w = (v.w - mu) * rs * gg.w + b4.w;
    ((float4*)(out + (size_t)row * W))[tid] = y;
    if (oh) {
        union { half h[4]; uint2 u; } H;
        H.h[0] = __float2half_rn(y.x);
        H.h[1] = __float2half_rn(y.y);
        H.h[2] = __float2half_rn(y.z);
        H.h[3] = __float2half_rn(y.w);
        ((uint2*)(oh + (size_t)row * W))[tid] = H.u;
    }
}

// ---------------- fused LN(qkv) + attention per batch ------------------------
#define QP 645
#define SP 68
__global__ void __launch_bounds__(256) attn_ln_kernel(
    const float* __restrict__ gq, const float* __restrict__ gb)
{
    extern __shared__ float smf[];
    float* sqkv = smf;                    // 64*645
    float* ss   = smf + 64 * QP;          // 64*68
    float* smu  = ss + 64 * SP;           // 64
    float* srs  = smu + 64;               // 64
    const int b = blockIdx.x, tid = threadIdx.x;
    const int wid = tid >> 5, lane = tid & 31;
    const float* qkv = g_qkvbuf + (size_t)b * 64 * TOTW;

    for (int e = tid; e < 64 * TOTW; e += 256) {
        int i = e / TOTW, col = e % TOTW;
        sqkv[i * QP + col] = qkv[e];
    }
    __syncthreads();

    for (int rr = 0; rr < 8; rr++) {
        int rowi = wid * 8 + rr;
        float s = 0.f, s2 = 0.f;
        for (int col = lane; col < TOTW; col += 32) {
            float v = sqkv[rowi * QP + col];
            s += v; s2 += v * v;
        }
#pragma unroll
        for (int o = 16; o > 0; o >>= 1) {
            s  += __shfl_xor_sync(0xFFFFFFFFu, s, o);
            s2 += __shfl_xor_sync(0xFFFFFFFFu, s2, o);
        }
        if (lane == 0) {
            float mu = s / TOTW;
            float var = s2 / TOTW - mu * mu;
            smu[rowi] = mu;
            srs[rowi] = rsqrtf(var + 1e-5f);
        }
    }
    __syncthreads();

    for (int e = tid; e < 64 * TOTW; e += 256) {
        int i = e / TOTW, col = e % TOTW;
        float v = (sqkv[i * QP + col] - smu[i]) * srs[i] * gq[col] + gb[col];
        if (col < KEYS) v *= 0.125f;
        sqkv[i * QP + col] = v;
    }
    __syncthreads();

    for (int e = tid; e < 4096; e += 256) {
        int i = e >> 6, j = e & 63;
        float acc = 0.f;
#pragma unroll 16
        for (int d = 0; d < 64; d++)
            acc += sqkv[i * QP + d] * sqkv[j * QP + KEYS + d];
        ss[i * SP + j] = acc;
    }
    __syncthreads();

    for (int rowi = wid; rowi < 64; rowi += 8) {
        float m = -1e30f;
        for (int j = lane; j < 64; j += 32) m = fmaxf(m, ss[rowi * SP + j]);
#pragma unroll
        for (int o = 16; o > 0; o >>= 1)
            m = fmaxf(m, __shfl_xor_sync(0xFFFFFFFFu, m, o));
        float s = 0.f;
        for (int j = lane; j < 64; j += 32) {
            float e = expf(ss[rowi * SP + j] - m);
            ss[rowi * SP + j] = e; s += e;
        }
#pragma unroll
        for (int o = 16; o > 0; o >>= 1)
            s += __shfl_xor_sync(0xFFFFFFFFu, s, o);
        float inv = 1.f / s;
        for (int j = lane; j < 64; j += 32) ss[rowi * SP + j] *= inv;
    }
    __syncthreads();

    for (int dpass = 0; dpass < 2; dpass++) {
        const int d = dpass * 256 + tid;
        float acc[64];
#pragma unroll
        for (int i = 0; i < 64; i++) acc[i] = 0.f;
        for (int jb = 0; jb < 64; jb += 8) {
            float vv[8];
#pragma unroll
            for (int t = 0; t < 8; t++)
                vv[t] = sqkv[(jb + t) * QP + 2 * KEYS + d];
#pragma unroll
            for (int i = 0; i < 64; i++) {
                float4 w0 = *(const float4*)&ss[i * SP + jb];
                float4 w1 = *(const float4*)&ss[i * SP + jb + 4];
                acc[i] += w0.x * vv[0] + w0.y * vv[1] + w0.z * vv[2] + w0.w * vv[3]
                        + w1.x * vv[4] + w1.y * vv[5] + w1.z * vv[6] + w1.w * vv[7];
            }
        }
#pragma unroll
        for (int i = 0; i < 64; i++)
            g_att[(size_t)(b * 64 + i) * DDIM + d] = acc[i];
    }
}

// ---------------- host orchestration -----------------------------------------
extern "C" void kernel_launch(void* const* d_in, const int* in_sizes, int n_in,
                              void* d_out, int out_size)
{
    const float* c     = (const float*)d_in[0];
    const float* mem_c = (const float*)d_in[1];
    const float* Wqkv  = (const float*)d_in[2];
    const float* bqkv  = (const float*)d_in[3];
    const float* gq    = (const float*)d_in[4];
    const float* bq    = (const float*)d_in[5];
    const float* gm    = (const float*)d_in[6];
    const float* bm    = (const float*)d_in[7];
    const float* W1    = (const float*)d_in[8];
    const float* b1    = (const float*)d_in[9];
    const float* W2    = (const float*)d_in[10];
    const float* b2    = (const float*)d_in[11];
    const float* Ws1   = (const float*)d_in[12];
    const float* bs1   = (const float*)d_in[13];
    const float* Ws2   = (const float*)d_in[14];
    const float* bs2   = (const float*)d_in[15];
    float* out = (float*)d_out;

    float *p_mems, *p_qkv, *p_att, *p_mem, *p_t2;
    bf16 *p_tau16, *p_c16, *p_mc16;
    half *p_ah, *p_hh, *p_wq, *p_w1, *p_w2, *p_s1, *p_s2;
    cudaGetSymbolAddress((void**)&p_tau16, g_tau16);
    cudaGetSymbolAddress((void**)&p_mems, g_mems);
    cudaGetSymbolAddress((void**)&p_qkv,  g_qkvbuf);
    cudaGetSymbolAddress((void**)&p_att,  g_att);
    cudaGetSymbolAddress((void**)&p_mem,  g_mem);
    cudaGetSymbolAddress((void**)&p_t2,   g_t2);
    cudaGetSymbolAddress((void**)&p_c16,  g_c16);
    cudaGetSymbolAddress((void**)&p_mc16, g_mc16);
    cudaGetSymbolAddress((void**)&p_ah,   g_ah);
    cudaGetSymbolAddress((void**)&p_hh,   g_hh);
    cudaGetSymbolAddress((void**)&p_wq,   g_wqkv);
    cudaGetSymbolAddress((void**)&p_w1,   g_w1);
    cudaGetSymbolAddress((void**)&p_w2,   g_w2);
    cudaGetSymbolAddress((void**)&p_s1,   g_ws1);
    cudaGetSymbolAddress((void**)&p_s2,   g_ws2);

    const int SM_WG = 73728;                              // 2 stages x 36864
    const int SM_ATTN = (64 * QP + 64 * SP + 128) * 4;    // 183040
    cudaFuncSetAttribute(wgemm<bf16, 0, true>,  cudaFuncAttributeMaxDynamicSharedMemorySize, SM_WG);
    cudaFuncSetAttribute(wgemm<half, 1, false>, cudaFuncAttributeMaxDynamicSharedMemorySize, SM_WG);
    cudaFuncSetAttribute(wgemm<half, 2, false>, cudaFuncAttributeMaxDynamicSharedMemorySize, SM_WG);
    cudaFuncSetAttribute(attn_ln_kernel, cudaFuncAttributeMaxDynamicSharedMemorySize, SM_ATTN);
    const dim3 blk(256);

    // --- input/weight conversions ---
    conv_rows_kernel<bf16><<<NB,   128>>>(c,     p_c16,  CDIM, DDIM);
    conv_rows_kernel<bf16><<<NMEM, 128>>>(mem_c, p_mc16, CDIM, DDIM);
    conv_rows_kernel<half><<<DDIM, 128>>>(Wqkv, p_wq, TOTW, TOTW);
    conv_rows_kernel<half><<<DDIM, 128>>>(W1,   p_w1, DDIM, DDIM);
    conv_rows_kernel<half><<<DDIM, 128>>>(W2,   p_w2, DDIM, DDIM);
    conv_rows_kernel<half><<<DDIM, 128>>>(Ws1,  p_s1, DDIM, DDIM);
    conv_rows_kernel<half><<<DDIM, 128>>>(Ws2,  p_s2, CDIM, DDIM);

    // --- 1) approx tau (bf16 out) = c16 @ mc16^T ---
    wgemm<bf16, 0, true><<<dim3((NMEM + 127) / 128, 2), blk, SM_WG>>>(
        p_c16, p_mc16, nullptr, nullptr, p_tau16,
        NB, NMEM, DDIM, DDIM, DDIM, NMEM);

    // --- 2) radix candidate select + exact fp32 rescore ---
    topk16_kernel<<<NB, blk>>>();
    rescore_kernel<<<NB, blk>>>(c, mem_c);

    // --- 3) mems + fp16 emit ---
    build_mems_kernel<<<ROWS, 128>>>(mem_c);

    // --- 4) qkv = mems @ Wqkv + bqkv  (LN fused into attention) ---
    wgemm<half, 1, false><<<dim3(5, 128), blk, SM_WG>>>(
        p_ah, p_wq, bqkv, p_qkv, (half*)nullptr,
        ROWS, TOTW, DDIM, DDIM, TOTW, TOTW);

    // --- 5) fused LN + attention ---
    attn_ln_kernel<<<NB, blk, SM_ATTN>>>(gq, bq);

    // --- 6) mem = LN(mems + attended)  (+ fp16 emit) ---
    ln_kernel<<<ROWS, 128>>>(p_mems, p_att, gm, bm, p_mem, p_ah, DDIM);

    // --- 7) two residual MLP blocks ---
    for (int rep = 0; rep < 2; rep++) {
        wgemm<half, 2, false><<<dim3(4, 128), blk, SM_WG>>>(
            p_ah, p_w1, b1, nullptr, p_hh,
            ROWS, DDIM, DDIM, DDIM, DDIM, DDIM);
        wgemm<half, 1, false><<<dim3(4, 128), blk, SM_WG>>>(
            p_hh, p_w2, b2, p_t2, (half*)nullptr,
            ROWS, DDIM, DDIM, DDIM, DDIM, DDIM);
        ln_kernel<<<ROWS, 128>>>(p_t2, p_mem, gm, bm, p_mem, p_ah, DDIM);
    }

    // --- 8) c_prime = relu(mem @ Ws1 + bs1) @ Ws2 + bs2 ---
    wgemm<half, 2, false><<<dim3(4, 128), blk, SM_WG>>>(
        p_ah, p_s1, bs1, nullptr, p_hh,
        ROWS, DDIM, DDIM, DDIM, DDIM, DDIM);
    wgemm<half, 1, false><<<dim3(4, 128), blk, SM_WG>>>(
        p_hh, p_s2, bs2, out, (half*)nullptr,
        ROWS, CDIM, DDIM, DDIM, DDIM, CDIM);
}

// round 15
// speedup vs baseline: 2.3090x; 1.0396x over previous
#include <cuda_runtime.h>
#include <cuda_bf16.h>
#include <cuda_fp16.h>
#include <mma.h>
#include <math.h>

using namespace nvcuda;
typedef __nv_bfloat16 bf16;

#define NB    256
#define NMEM  100000
#define CDIM  511
#define DDIM  512
#define KEYS  64
#define TOTW  640
#define KTOP  64
#define ROWS  (NB*KTOP)   // 16384
#define CAP   1024        // candidate cap per row

// ---------------- scratch (device globals; no allocations allowed) ----------
__device__ bf16  g_tau16[(size_t)NB*NMEM];     // approx tau in bf16, 51.2 MB
__device__ float g_deltas[NB*KTOP];
__device__ int   g_topidx[NB*KTOP];
__device__ int   g_candidx[(size_t)NB*CAP];
__device__ int   g_candcnt[NB];
__device__ float g_mems[(size_t)ROWS*DDIM];
__device__ float g_qkvbuf[(size_t)ROWS*TOTW];
__device__ float g_att[(size_t)ROWS*DDIM];
__device__ float g_mem[(size_t)ROWS*DDIM];
__device__ float g_t2[(size_t)ROWS*DDIM];

// tau path stays bf16 (selection invariance)
__device__ bf16 g_c16[(size_t)NB*DDIM];
__device__ bf16 g_mc16[(size_t)NMEM*DDIM];
// downstream path: fp16 single-term
__device__ half g_ah[(size_t)ROWS*DDIM];
__device__ half g_hh[(size_t)ROWS*DDIM];
__device__ half g_wqkv[(size_t)DDIM*TOTW];
__device__ half g_w1[(size_t)DDIM*DDIM];
__device__ half g_w2[(size_t)DDIM*DDIM];
__device__ half g_ws1[(size_t)DDIM*DDIM];
__device__ half g_ws2[(size_t)DDIM*DDIM];     // 511->512 pad

// ---------------- cp.async helpers ------------------------------------------
__device__ __forceinline__ void cp16(void* dst_smem, const void* src, bool pred) {
    unsigned d = (unsigned)__cvta_generic_to_shared(dst_smem);
    int sz = pred ? 16 : 0;
    asm volatile("cp.async.cg.shared.global [%0], [%1], 16, %2;\n"
                 :: "r"(d), "l"(src), "r"(sz));
}
__device__ __forceinline__ void cp_commit() {
    asm volatile("cp.async.commit_group;\n");
}
template<int NN>
__device__ __forceinline__ void cp_wait() {
    asm volatile("cp.async.wait_group %0;\n" :: "n"(NN));
}

__device__ __forceinline__ unsigned short f2key16(unsigned short b) {
    return (b & 0x8000u) ? (unsigned short)(~b) : (unsigned short)(b | 0x8000u);
}
__device__ __forceinline__ float key16_to_f(unsigned short k) {
    unsigned short raw = (k & 0x8000u) ? (unsigned short)(k & 0x7FFFu)
                                       : (unsigned short)(~k);
    __nv_bfloat16_raw br; br.x = raw;
    return __bfloat162float((bf16)br);
}

template<typename T> __device__ __forceinline__ T f2t(float v);
template<> __device__ __forceinline__ half f2t<half>(float v) { return __float2half_rn(v); }
template<> __device__ __forceinline__ bf16 f2t<bf16>(float v) { return __float2bfloat16_rn(v); }

// ---------------- fp32 -> T convert, one row per block ----------------------
template<typename T>
__global__ void conv_rows_kernel(const float* __restrict__ src,
                                 T* __restrict__ dst, int scols, int dcols)
{
    const int r = blockIdx.x;
    const float* s = src + (size_t)r * scols;
    T* d = dst + (size_t)r * dcols;
    for (int c = threadIdx.x; c < dcols; c += blockDim.x)
        d[c] = f2t<T>(c < scols ? s[c] : 0.f);
}

// ---------------- fused small conversions: c + 5 weights in ONE launch ------
// blockIdx.x ranges: [0,256) c->bf16 pad512 | [256,768) Wqkv | [768,1280) W1 |
// [1280,1792) W2 | [1792,2304) Ws1 | [2304,2816) Ws2 (511->512 pad)
__global__ void conv_small_kernel(
    const float* __restrict__ c,   bf16* __restrict__ c16,
    const float* __restrict__ wq,  half* __restrict__ wq16,
    const float* __restrict__ w1,  half* __restrict__ w116,
    const float* __restrict__ w2,  half* __restrict__ w216,
    const float* __restrict__ s1,  half* __restrict__ s116,
    const float* __restrict__ s2,  half* __restrict__ s216)
{
    const int b = blockIdx.x;
    if (b < 256) {
        const float* s = c + (size_t)b * CDIM;
        bf16* d = c16 + (size_t)b * DDIM;
        for (int cc = threadIdx.x; cc < DDIM; cc += blockDim.x)
            d[cc] = __float2bfloat16_rn(cc < CDIM ? s[cc] : 0.f);
    } else if (b < 768) {
        int r = b - 256;
        const float* s = wq + (size_t)r * TOTW;
        half* d = wq16 + (size_t)r * TOTW;
        for (int cc = threadIdx.x; cc < TOTW; cc += blockDim.x)
            d[cc] = __float2half_rn(s[cc]);
    } else if (b < 1280) {
        int r = b - 768;
        const float* s = w1 + (size_t)r * DDIM;
        half* d = w116 + (size_t)r * DDIM;
        for (int cc = threadIdx.x; cc < DDIM; cc += blockDim.x)
            d[cc] = __float2half_rn(s[cc]);
    } else if (b < 1792) {
        int r = b - 1280;
        const float* s = w2 + (size_t)r * DDIM;
        half* d = w216 + (size_t)r * DDIM;
        for (int cc = threadIdx.x; cc < DDIM; cc += blockDim.x)
            d[cc] = __float2half_rn(s[cc]);
    } else if (b < 2304) {
        int r = b - 1792;
        const float* s = s1 + (size_t)r * DDIM;
        half* d = s116 + (size_t)r * DDIM;
        for (int cc = threadIdx.x; cc < DDIM; cc += blockDim.x)
            d[cc] = __float2half_rn(s[cc]);
    } else {
        int r = b - 2304;
        const float* s = s2 + (size_t)r * CDIM;
        half* d = s216 + (size_t)r * DDIM;
        for (int cc = threadIdx.x; cc < DDIM; cc += blockDim.x)
            d[cc] = __float2half_rn(cc < CDIM ? s[cc] : 0.f);
    }
}

// ---------------- WMMA GEMM: 128x128 tile, K-chunk 64, 2-stage, 2 CTA/SM ----
// (EXACT R11 configuration — the 809us passing version)
template<typename TT, int EPI, bool BCOL>
__global__ void __launch_bounds__(256, 2) wgemm(
    const TT* __restrict__ A, const TT* __restrict__ B,
    const float* __restrict__ bias, float* __restrict__ C,
    TT* __restrict__ OH,
    int M, int N, int K, int lda, int ldb, int ldc)
{
    extern __shared__ __align__(16) char smem[];
    constexpr int AP  = 72;
    constexpr int BPR = 136;
    constexpr int STAGE = 36864;

    const int tid = threadIdx.x;
    const int w = tid >> 5, lane = tid & 31;
    const int wm = w >> 1, wn = w & 1;
    const int m0 = blockIdx.y * 128, n0 = blockIdx.x * 128;

    wmma::fragment<wmma::accumulator, 16, 16, 16, float> acc[2][4];
#pragma unroll
    for (int i = 0; i < 2; i++)
#pragma unroll
        for (int j = 0; j < 4; j++) wmma::fill_fragment(acc[i][j], 0.f);

    auto issue = [&](int k0, int s) {
        char* base = smem + s * STAGE;
        TT* sA = (TT*)base;
        TT* sB = (TT*)(base + 18432);
#pragma unroll
        for (int e = 0; e < 4; e++) {
            int idx = tid + e * 256;
            {
                int row = idx >> 3, c4 = idx & 7;
                size_t off = (size_t)(m0 + row) * lda + k0 + c4 * 8;
                cp16(sA + row * AP + c4 * 8, A + off, true);
            }
            if (BCOL) {
                int n = idx >> 3, c4 = idx & 7;
                bool v = (n0 + n) < N;
                size_t off = v ? ((size_t)(n0 + n) * ldb + k0 + c4 * 8) : 0;
                cp16(sB + n * AP + c4 * 8, B + off, v);
            } else {
                int row = idx >> 4, c4 = idx & 15;
                size_t off = (size_t)(k0 + row) * ldb + n0 + c4 * 8;
                cp16(sB + row * BPR + c4 * 8, B + off, true);
            }
        }
        cp_commit();
    };

    auto compute = [&](int s) {
        char* base = smem + s * STAGE;
        TT* sA = (TT*)base;
        TT* sB = (TT*)(base + 18432);
#pragma unroll
        for (int kf = 0; kf < 64; kf += 16) {
            wmma::fragment<wmma::matrix_a, 16, 16, 16, TT, wmma::row_major> af[2];
#pragma unroll
            for (int i = 0; i < 2; i++)
                wmma::load_matrix_sync(af[i], sA + (wm * 32 + i * 16) * AP + kf, AP);
            if constexpr (BCOL) {
                wmma::fragment<wmma::matrix_b, 16, 16, 16, TT, wmma::col_major> bf;
#pragma unroll
                for (int j = 0; j < 4; j++) {
                    wmma::load_matrix_sync(bf, sB + (wn * 64 + j * 16) * AP + kf, AP);
#pragma unroll
                    for (int i = 0; i < 2; i++)
                        wmma::mma_sync(acc[i][j], af[i], bf, acc[i][j]);
                }
            } else {
                wmma::fragment<wmma::matrix_b, 16, 16, 16, TT, wmma::row_major> bf;
#pragma unroll
                for (int j = 0; j < 4; j++) {
                    wmma::load_matrix_sync(bf, sB + kf * BPR + wn * 64 + j * 16, BPR);
#pragma unroll
                    for (int i = 0; i < 2; i++)
                        wmma::mma_sync(acc[i][j], af[i], bf, acc[i][j]);
                }
            }
        }
    };

    issue(0, 0);
    int cur = 0;
    for (int k0 = 0; k0 < K; k0 += 64) {
        cp_wait<0>();
        __syncthreads();
        if (k0 + 64 < K) issue(k0 + 64, cur ^ 1);
        compute(cur);
        cur ^= 1;
    }
    __syncthreads();

    float* ep = (float*)smem + w * 2176;
#pragma unroll
    for (int i = 0; i < 2; i++)
#pragma unroll
        for (int j = 0; j < 4; j++)
            wmma::store_matrix_sync(ep + i * 16 * 68 + j * 16, acc[i][j], 68,
                                    wmma::mem_row_major);
    __syncwarp();
#pragma unroll 4
    for (int r = 0; r < 32; r++) {
        int gm = m0 + wm * 32 + r;
#pragma unroll
        for (int it = 0; it < 2; it++) {
            int gn = n0 + wn * 64 + it * 32 + lane;
            if (gn < N) {
                float v = ep[r * 68 + it * 32 + lane];
                if (EPI >= 1) v += bias[gn];
                if (EPI == 2) v = fmaxf(v, 0.f);
                size_t off = (size_t)gm * ldc + gn;
                if (C) C[off] = v;
                if (OH) OH[off] = f2t<TT>(v);
            }
        }
    }
}

// ---------------- approx top-64: 2-pass uint16 radix, per-warp hists --------
__global__ void __launch_bounds__(256) topk16_kernel()
{
    const int r = blockIdx.x, tid = threadIdx.x;
    const int wid = tid >> 5;
    const bf16* row = g_tau16 + (size_t)r * NMEM;
    const uint4* row4 = (const uint4*)row;
    __shared__ unsigned hist[8 * 256];
    __shared__ int sh_d, sh_need, cnt;
    unsigned* myh = hist + wid * 256;

    for (int i = tid; i < 8 * 256; i += 256) hist[i] = 0;
    __syncthreads();
    for (int i = tid; i < NMEM / 8; i += 256) {
        uint4 q = row4[i];
        unsigned short hb[8] = {
            (unsigned short)(q.x & 0xFFFFu), (unsigned short)(q.x >> 16),
            (unsigned short)(q.y & 0xFFFFu), (unsigned short)(q.y >> 16),
            (unsigned short)(q.z & 0xFFFFu), (unsigned short)(q.z >> 16),
            (unsigned short)(q.w & 0xFFFFu), (unsigned short)(q.w >> 16)};
#pragma unroll
        for (int t = 0; t < 8; t++)
            atomicAdd(&myh[f2key16(hb[t]) >> 8], 1u);
    }
    __syncthreads();
    {
        unsigned tot = 0;
#pragma unroll
        for (int wdx = 0; wdx < 8; wdx++) tot += hist[wdx * 256 + tid];
        __syncthreads();
        hist[tid] = tot;
    }
    __syncthreads();
    if (tid == 0) {
        int cum = 0, d = 255;
        for (; d >= 0; --d) {
            if (cum + (int)hist[d] >= KTOP) break;
            cum += (int)hist[d];
        }
        if (d < 0) d = 0;
        sh_d = d; sh_need = KTOP - cum;
    }
    __syncthreads();
    const unsigned hi8 = (unsigned)sh_d;
    const int need = sh_need;
    __syncthreads();

    for (int i = tid; i < 8 * 256; i += 256) hist[i] = 0;
    __syncthreads();
    for (int i = tid; i < NMEM / 8; i += 256) {
        uint4 q = row4[i];
        unsigned short hb[8] = {
            (unsigned short)(q.x & 0xFFFFu), (unsigned short)(q.x >> 16),
            (unsigned short)(q.y & 0xFFFFu), (unsigned short)(q.y >> 16),
            (unsigned short)(q.z & 0xFFFFu), (unsigned short)(q.z >> 16),
            (unsigned short)(q.w & 0xFFFFu), (unsigned short)(q.w >> 16)};
#pragma unroll
        for (int t = 0; t < 8; t++) {
            unsigned short k = f2key16(hb[t]);
            if ((k >> 8) == hi8) atomicAdd(&myh[k & 0xFFu], 1u);
        }
    }
    __syncthreads();
    {
        unsigned tot = 0;
#pragma unroll
        for (int wdx = 0; wdx < 8; wdx++) tot += hist[wdx * 256 + tid];
        __syncthreads();
        hist[tid] = tot;
    }
    __syncthreads();
    if (tid == 0) {
        int cum = 0, d = 255;
        for (; d >= 0; --d) {
            if (cum + (int)hist[d] >= need) break;
            cum += (int)hist[d];
        }
        if (d < 0) d = 0;
        sh_d = d;
        cnt = 0;
    }
    __syncthreads();
    const unsigned short k64 = (unsigned short)((hi8 << 8) | (unsigned)sh_d);
    const float thr = key16_to_f(k64) - 2.0f;
    __syncthreads();

    for (int i = tid; i < NMEM / 8; i += 256) {
        uint4 q = row4[i];
        unsigned short hb[8] = {
            (unsigned short)(q.x & 0xFFFFu), (unsigned short)(q.x >> 16),
            (unsigned short)(q.y & 0xFFFFu), (unsigned short)(q.y >> 16),
            (unsigned short)(q.z & 0xFFFFu), (unsigned short)(q.z >> 16),
            (unsigned short)(q.w & 0xFFFFu), (unsigned short)(q.w >> 16)};
#pragma unroll
        for (int t = 0; t < 8; t++) {
            __nv_bfloat16_raw br; br.x = hb[t];
            if (__bfloat162float((bf16)br) >= thr) {
                int p = atomicAdd(&cnt, 1);
                if (p < CAP) g_candidx[(size_t)r * CAP + p] = i * 8 + t;
            }
        }
    }
    __syncthreads();
    if (tid == 0) g_candcnt[r] = (cnt < CAP) ? cnt : CAP;
}

// ---------------- fp32 rescore (sequential-k fma, UNCHANGED) ----------------
__global__ void __launch_bounds__(256) rescore_kernel(
    const float* __restrict__ c, const float* __restrict__ mem_c)
{
    const int r = blockIdx.x, tid = threadIdx.x;
    __shared__ float sc[512];
    __shared__ float scores[CAP];
    __shared__ int   cidx[CAP];
    const int nc = g_candcnt[r];

    for (int k = tid; k < CDIM; k += 256) sc[k] = c[(size_t)r * CDIM + k];
    for (int i = tid; i < nc; i += 256) cidx[i] = g_candidx[(size_t)r * CAP + i];
    __syncthreads();

    for (int ci = tid; ci < nc; ci += 256) {
        const float* mr = mem_c + (size_t)cidx[ci] * CDIM;
        float s = 0.f;
#pragma unroll 8
        for (int k = 0; k < CDIM; k++) s = fmaf(sc[k], mr[k], s);
        scores[ci] = s;
    }
    __syncthreads();

    for (int ci = tid; ci < nc; ci += 256) {
        float v = scores[ci]; int id = cidx[ci];
        int rank = 0;
        for (int j = 0; j < nc; j++) {
            float vj = scores[j];
            rank += (vj > v) || (vj == v && cidx[j] < id);
        }
        if (rank < KTOP) {
            g_deltas[r * KTOP + rank] = v;
            g_topidx[r * KTOP + rank] = id;
        }
    }
}

// ---------------- mems = concat(delta, mem_c[idx]) + fp16 emit --------------
__global__ void build_mems_kernel(const float* __restrict__ mem_c)
{
    const int row = blockIdx.x, tid = threadIdx.x;
    const int idx = g_topidx[row];
    const float d0 = g_deltas[row];
    float* out = g_mems + (size_t)row * DDIM;
    half*  oh  = g_ah  + (size_t)row * DDIM;
    const float* src = mem_c + (size_t)idx * CDIM;
    for (int cpos = tid; cpos < DDIM; cpos += blockDim.x) {
        float v = (cpos == 0) ? d0 : src[cpos - 1];
        out[cpos] = v;
        oh[cpos] = __float2half_rn(v);
    }
}

// ---------------- single-pass vectorized LayerNorm (fp16 emit) --------------
__global__ void ln_kernel(
    const float* __restrict__ x, const float* __restrict__ res,
    const float* __restrict__ g, const float* __restrict__ bb,
    float* __restrict__ out, half* __restrict__ oh, int W)
{
    const int row = blockIdx.x, tid = threadIdx.x;
    float4 v = ((const float4*)(x + (size_t)row * W))[tid];
    if (res) {
        float4 r = ((const float4*)(res + (size_t)row * W))[tid];
        v.x += r.x; v.y += r.y; v.z += r.z; v.w += r.w;
    }
    float s  = v.x + v.y + v.z + v.w;
    float s2 = v.x * v.x + v.y * v.y + v.z * v.z + v.w * v.w;
    __shared__ float red1[8], red2[8];
#pragma unroll
    for (int o = 16; o > 0; o >>= 1) {
        s  += __shfl_xor_sync(0xFFFFFFFFu, s, o);
        s2 += __shfl_xor_sync(0xFFFFFFFFu, s2, o);
    }
    const int wid = tid >> 5, nw = blockDim.x >> 5;
    if ((tid & 31) == 0) { red1[wid] = s; red2[wid] = s2; }
    __syncthreads();
    if (tid < 32) {
        s  = (tid < nw) ? red1[tid] : 0.f;
        s2 = (tid < nw) ? red2[tid] : 0.f;
#pragma unroll
        for (int o = 4; o > 0; o >>= 1) {
            s  += __shfl_xor_sync(0xFFFFFFFFu, s, o);
            s2 += __shfl_xor_sync(0xFFFFFFFFu, s2, o);
        }
        if (tid == 0) { red1[0] = s; red2[0] = s2; }
    }
    __syncthreads();
    const float mu = red1[0] / W;
    const float var = red2[0] / W - mu * mu;
    const float rs = rsqrtf(var + 1e-5f);

    float4 gg = ((const float4*)g)[tid];
    float4 b4 = ((const float4*)bb)[tid];
    float4 y;
    y.x = (v.x - mu) * rs * gg.x + b4.x;
    y.y = (v.y - mu) * rs * gg.y + b4.y;
    y.z = (v.z - mu) * rs * gg.z + b4.z;
    y.w = (v.w - mu) * rs * gg.w + b4.w;
    ((float4*)(out + (size_t)row * W))[tid] = y;
    if (oh) {
        union { half h[4]; uint2 u; } H;
        H.h[0] = __float2half_rn(y.x);
        H.h[1] = __float2half_rn(y.y);
        H.h[2] = __float2half_rn(y.z);
        H.h[3] = __float2half_rn(y.w);
        ((uint2*)(oh + (size_t)row * W))[tid] = H.u;
    }
}

// ---------------- fused LN(qkv) + attention per batch ------------------------
#define QP 645
#define SP 68
__global__ void __launch_bounds__(256) attn_ln_kernel(
    const float* __restrict__ gq, const float* __restrict__ gb)
{
    extern __shared__ float smf[];
    float* sqkv = smf;                    // 64*645
    float* ss   = smf + 64 * QP;          // 64*68
    float* smu  = ss + 64 * SP;           // 64
    float* srs  = smu + 64;               // 64
    const int b = blockIdx.x, tid = threadIdx.x;
    const int wid = tid >> 5, lane = tid & 31;
    const float* qkv = g_qkvbuf + (size_t)b * 64 * TOTW;

    // vectorized tile load: contiguous 64*640 floats, float4 never crosses rows
    const float4* qkv4 = (const float4*)qkv;
    for (int e4 = tid; e4 < 64 * TOTW / 4; e4 += 256) {
        float4 f = qkv4[e4];
        int flat = e4 * 4;
        int i = flat / TOTW, col = flat % TOTW;
        float* dst = sqkv + i * QP + col;
        dst[0] = f.x; dst[1] = f.y; dst[2] = f.z; dst[3] = f.w;
    }
    __syncthreads();

    for (int rr = 0; rr < 8; rr++) {
        int rowi = wid * 8 + rr;
        float s = 0.f, s2 = 0.f;
        for (int col = lane; col < TOTW; col += 32) {
            float v = sqkv[rowi * QP + col];
            s += v; s2 += v * v;
        }
#pragma unroll
        for (int o = 16; o > 0; o >>= 1) {
            s  += __shfl_xor_sync(0xFFFFFFFFu, s, o);
            s2 += __shfl_xor_sync(0xFFFFFFFFu, s2, o);
        }
        if (lane == 0) {
            float mu = s / TOTW;
            float var = s2 / TOTW - mu * mu;
            smu[rowi] = mu;
            srs[rowi] = rsqrtf(var + 1e-5f);
        }
    }
    __syncthreads();

    for (int e = tid; e < 64 * TOTW; e += 256) {
        int i = e / TOTW, col = e % TOTW;
        float v = (sqkv[i * QP + col] - smu[i]) * srs[i] * gq[col] + gb[col];
        if (col < KEYS) v *= 0.125f;
        sqkv[i * QP + col] = v;
    }
    __syncthreads();

    for (int e = tid; e < 4096; e += 256) {
        int i = e >> 6, j = e & 63;
        float acc = 0.f;
#pragma unroll 16
        for (int d = 0; d < 64; d++)
            acc += sqkv[i * QP + d] * sqkv[j * QP + KEYS + d];
        ss[i * SP + j] = acc;
    }
    __syncthreads();

    for (int rowi = wid; rowi < 64; rowi += 8) {
        float m = -1e30f;
        for (int j = lane; j < 64; j += 32) m = fmaxf(m, ss[rowi * SP + j]);
#pragma unroll
        for (int o = 16; o > 0; o >>= 1)
            m = fmaxf(m, __shfl_xor_sync(0xFFFFFFFFu, m, o));
        float s = 0.f;
        for (int j = lane; j < 64; j += 32) {
            float e = expf(ss[rowi * SP + j] - m);
            ss[rowi * SP + j] = e; s += e;
        }
#pragma unroll
        for (int o = 16; o > 0; o >>= 1)
            s += __shfl_xor_sync(0xFFFFFFFFu, s, o);
        float inv = 1.f / s;
        for (int j = lane; j < 64; j += 32) ss[rowi * SP + j] *= inv;
    }
    __syncthreads();

    for (int dpass = 0; dpass < 2; dpass++) {
        const int d = dpass * 256 + tid;
        float acc[64];
#pragma unroll
        for (int i = 0; i < 64; i++) acc[i] = 0.f;
        for (int jb = 0; jb < 64; jb += 8) {
            float vv[8];
#pragma unroll
            for (int t = 0; t < 8; t++)
                vv[t] = sqkv[(jb + t) * QP + 2 * KEYS + d];
#pragma unroll
            for (int i = 0; i < 64; i++) {
                float4 w0 = *(const float4*)&ss[i * SP + jb];
                float4 w1 = *(const float4*)&ss[i * SP + jb + 4];
                acc[i] += w0.x * vv[0] + w0.y * vv[1] + w0.z * vv[2] + w0.w * vv[3]
                        + w1.x * vv[4] + w1.y * vv[5] + w1.z * vv[6] + w1.w * vv[7];
            }
        }
#pragma unroll
        for (int i = 0; i < 64; i++)
            g_att[(size_t)(b * 64 + i) * DDIM + d] = acc[i];
    }
}

// ---------------- host orchestration -----------------------------------------
extern "C" void kernel_launch(void* const* d_in, const int* in_sizes, int n_in,
                              void* d_out, int out_size)
{
    const float* c     = (const float*)d_in[0];
    const float* mem_c = (const float*)d_in[1];
    const float* Wqkv  = (const float*)d_in[2];
    const float* bqkv  = (const float*)d_in[3];
    const float* gq    = (const float*)d_in[4];
    const float* bq    = (const float*)d_in[5];
    const float* gm    = (const float*)d_in[6];
    const float* bm    = (const float*)d_in[7];
    const float* W1    = (const float*)d_in[8];
    const float* b1    = (const float*)d_in[9];
    const float* W2    = (const float*)d_in[10];
    const float* b2    = (const float*)d_in[11];
    const float* Ws1   = (const float*)d_in[12];
    const float* bs1   = (const float*)d_in[13];
    const float* Ws2   = (const float*)d_in[14];
    const float* bs2   = (const float*)d_in[15];
    float* out = (float*)d_out;

    float *p_mems, *p_qkv, *p_att, *p_mem, *p_t2;
    bf16 *p_tau16, *p_c16, *p_mc16;
    half *p_ah, *p_hh, *p_wq, *p_w1, *p_w2, *p_s1, *p_s2;
    cudaGetSymbolAddress((void**)&p_tau16, g_tau16);
    cudaGetSymbolAddress((void**)&p_mems, g_mems);
    cudaGetSymbolAddress((void**)&p_qkv,  g_qkvbuf);
    cudaGetSymbolAddress((void**)&p_att,  g_att);
    cudaGetSymbolAddress((void**)&p_mem,  g_mem);
    cudaGetSymbolAddress((void**)&p_t2,   g_t2);
    cudaGetSymbolAddress((void**)&p_c16,  g_c16);
    cudaGetSymbolAddress((void**)&p_mc16, g_mc16);
    cudaGetSymbolAddress((void**)&p_ah,   g_ah);
    cudaGetSymbolAddress((void**)&p_hh,   g_hh);
    cudaGetSymbolAddress((void**)&p_wq,   g_wqkv);
    cudaGetSymbolAddress((void**)&p_w1,   g_w1);
    cudaGetSymbolAddress((void**)&p_w2,   g_w2);
    cudaGetSymbolAddress((void**)&p_s1,   g_ws1);
    cudaGetSymbolAddress((void**)&p_s2,   g_ws2);

    const int SM_WG = 73728;                              // 2 stages x 36864
    const int SM_ATTN = (64 * QP + 64 * SP + 128) * 4;    // 183040
    cudaFuncSetAttribute(wgemm<bf16, 0, true>,  cudaFuncAttributeMaxDynamicSharedMemorySize, SM_WG);
    cudaFuncSetAttribute(wgemm<half, 1, false>, cudaFuncAttributeMaxDynamicSharedMemorySize, SM_WG);
    cudaFuncSetAttribute(wgemm<half, 2, false>, cudaFuncAttributeMaxDynamicSharedMemorySize, SM_WG);
    cudaFuncSetAttribute(attn_ln_kernel, cudaFuncAttributeMaxDynamicSharedMemorySize, SM_ATTN);
    const dim3 blk(256);

    // --- conversions: 1 fused launch (small tensors) + mem_c ---
    conv_small_kernel<<<2816, 128>>>(c, p_c16, Wqkv, p_wq, W1, p_w1,
                                     W2, p_w2, Ws1, p_s1, Ws2, p_s2);
    conv_rows_kernel<bf16><<<NMEM, 128>>>(mem_c, p_mc16, CDIM, DDIM);

    // --- 1) approx tau (bf16 out) = c16 @ mc16^T ---
    wgemm<bf16, 0, true><<<dim3((NMEM + 127) / 128, 2), blk, SM_WG>>>(
        p_c16, p_mc16, nullptr, nullptr, p_tau16,
        NB, NMEM, DDIM, DDIM, DDIM, NMEM);

    // --- 2) radix candidate select + exact fp32 rescore ---
    topk16_kernel<<<NB, blk>>>();
    rescore_kernel<<<NB, blk>>>(c, mem_c);

    // --- 3) mems + fp16 emit ---
    build_mems_kernel<<<ROWS, 128>>>(mem_c);

    // --- 4) qkv = mems @ Wqkv + bqkv  (LN fused into attention) ---
    wgemm<half, 1, false><<<dim3(5, 128), blk, SM_WG>>>(
        p_ah, p_wq, bqkv, p_qkv, (half*)nullptr,
        ROWS, TOTW, DDIM, DDIM, TOTW, TOTW);

    // --- 5) fused LN + attention ---
    attn_ln_kernel<<<NB, blk, SM_ATTN>>>(gq, bq);

    // --- 6) mem = LN(mems + attended)  (+ fp16 emit) ---
    ln_kernel<<<ROWS, 128>>>(p_mems, p_att, gm, bm, p_mem, p_ah, DDIM);

    // --- 7) two residual MLP blocks ---
    for (int rep = 0; rep < 2; rep++) {
        wgemm<half, 2, false><<<dim3(4, 128), blk, SM_WG>>>(
            p_ah, p_w1, b1, nullptr, p_hh,
            ROWS, DDIM, DDIM, DDIM, DDIM, DDIM);
        wgemm<half, 1, false><<<dim3(4, 128), blk, SM_WG>>>(
            p_hh, p_w2, b2, p_t2, (half*)nullptr,
            ROWS, DDIM, DDIM, DDIM, DDIM, DDIM);
        ln_kernel<<<ROWS, 128>>>(p_t2, p_mem, gm, bm, p_mem, p_ah, DDIM);
    }

    // --- 8) c_prime = relu(mem @ Ws1 + bs1) @ Ws2 + bs2 ---
    wgemm<half, 2, false><<<dim3(4, 128), blk, SM_WG>>>(
        p_ah, p_s1, bs1, nullptr, p_hh,
        ROWS, DDIM, DDIM, DDIM, DDIM, DDIM);
    wgemm<half, 1, false><<<dim3(4, 128), blk, SM_WG>>>(
        p_hh, p_s2, bs2, out, (half*)nullptr,
        ROWS, CDIM, DDIM, DDIM, DDIM, CDIM);
}

// round 16
// speedup vs baseline: 2.4974x; 1.0816x over previous
#include <cuda_runtime.h>
#include <cuda_bf16.h>
#include <cuda_fp16.h>
#include <mma.h>
#include <math.h>

using namespace nvcuda;
typedef __nv_bfloat16 bf16;

#define NB    256
#define NMEM  100000
#define CDIM  511
#define DDIM  512
#define KEYS  64
#define TOTW  640
#define KTOP  64
#define ROWS  (NB*KTOP)   // 16384
#define CAP   1024        // candidate cap per row

// ---------------- scratch (device globals; no allocations allowed) ----------
__device__ bf16  g_tau16[(size_t)NB*NMEM];     // approx tau in bf16, 51.2 MB
__device__ float g_deltas[NB*KTOP];
__device__ int   g_topidx[NB*KTOP];
__device__ int   g_candidx[(size_t)NB*CAP];
__device__ int   g_candcnt[NB];
__device__ float g_mems[(size_t)ROWS*DDIM];
__device__ float g_qkvbuf[(size_t)ROWS*TOTW];
__device__ float g_att[(size_t)ROWS*DDIM];
__device__ float g_mem[(size_t)ROWS*DDIM];
__device__ float g_t2[(size_t)ROWS*DDIM];

// tau path stays bf16 (selection invariance)
__device__ bf16 g_c16[(size_t)NB*DDIM];
__device__ bf16 g_mc16[(size_t)NMEM*DDIM];
// downstream path: fp16 single-term
__device__ half g_ah[(size_t)ROWS*DDIM];
__device__ half g_hh[(size_t)ROWS*DDIM];
__device__ half g_wqkv[(size_t)DDIM*TOTW];
__device__ half g_w1[(size_t)DDIM*DDIM];
__device__ half g_w2[(size_t)DDIM*DDIM];
__device__ half g_ws1[(size_t)DDIM*DDIM];
__device__ half g_ws2[(size_t)DDIM*DDIM];     // 511->512 pad

// ---------------- cp.async helpers ------------------------------------------
__device__ __forceinline__ void cp16(void* dst_smem, const void* src, bool pred) {
    unsigned d = (unsigned)__cvta_generic_to_shared(dst_smem);
    int sz = pred ? 16 : 0;
    asm volatile("cp.async.cg.shared.global [%0], [%1], 16, %2;\n"
                 :: "r"(d), "l"(src), "r"(sz));
}
__device__ __forceinline__ void cp_commit() {
    asm volatile("cp.async.commit_group;\n");
}
template<int NN>
__device__ __forceinline__ void cp_wait() {
    asm volatile("cp.async.wait_group %0;\n" :: "n"(NN));
}

__device__ __forceinline__ unsigned short f2key16(unsigned short b) {
    return (b & 0x8000u) ? (unsigned short)(~b) : (unsigned short)(b | 0x8000u);
}
__device__ __forceinline__ float key16_to_f(unsigned short k) {
    unsigned short raw = (k & 0x8000u) ? (unsigned short)(k & 0x7FFFu)
                                       : (unsigned short)(~k);
    __nv_bfloat16_raw br; br.x = raw;
    return __bfloat162float((bf16)br);
}

template<typename T> __device__ __forceinline__ T f2t(float v);
template<> __device__ __forceinline__ half f2t<half>(float v) { return __float2half_rn(v); }
template<> __device__ __forceinline__ bf16 f2t<bf16>(float v) { return __float2bfloat16_rn(v); }

// ---------------- mem_c conversion: flat float4, constant divisor -----------
__global__ void conv_memc_kernel(const float* __restrict__ src, bf16* __restrict__ dst)
{
    const size_t total4 = (size_t)NMEM * CDIM / 4;   // 12,775,000 exactly
    const size_t stride = (size_t)gridDim.x * blockDim.x;
    for (size_t i4 = (size_t)blockIdx.x * blockDim.x + threadIdx.x;
         i4 < total4; i4 += stride) {
        float4 f = ((const float4*)src)[i4];
        size_t flat = i4 * 4;
        float vv[4] = {f.x, f.y, f.z, f.w};
#pragma unroll
        for (int t = 0; t < 4; t++) {
            size_t e = flat + t;
            size_t r = e / CDIM;          // constant divisor -> mulhi+shift
            size_t c = e - r * CDIM;
            dst[r * DDIM + c] = __float2bfloat16_rn(vv[t]);
        }
    }
    // zero pad column 511
    for (size_t r = (size_t)blockIdx.x * blockDim.x + threadIdx.x;
         r < NMEM; r += stride)
        dst[r * DDIM + CDIM] = __float2bfloat16_rn(0.f);
}

// ---------------- fused small conversions: c + 5 weights in ONE launch ------
__global__ void conv_small_kernel(
    const float* __restrict__ c,   bf16* __restrict__ c16,
    const float* __restrict__ wq,  half* __restrict__ wq16,
    const float* __restrict__ w1,  half* __restrict__ w116,
    const float* __restrict__ w2,  half* __restrict__ w216,
    const float* __restrict__ s1,  half* __restrict__ s116,
    const float* __restrict__ s2,  half* __restrict__ s216)
{
    const int b = blockIdx.x;
    if (b < 256) {
        const float* s = c + (size_t)b * CDIM;
        bf16* d = c16 + (size_t)b * DDIM;
        for (int cc = threadIdx.x; cc < DDIM; cc += blockDim.x)
            d[cc] = __float2bfloat16_rn(cc < CDIM ? s[cc] : 0.f);
    } else if (b < 768) {
        int r = b - 256;
        const float* s = wq + (size_t)r * TOTW;
        half* d = wq16 + (size_t)r * TOTW;
        for (int cc = threadIdx.x; cc < TOTW; cc += blockDim.x)
            d[cc] = __float2half_rn(s[cc]);
    } else if (b < 1280) {
        int r = b - 768;
        const float* s = w1 + (size_t)r * DDIM;
        half* d = w116 + (size_t)r * DDIM;
        for (int cc = threadIdx.x; cc < DDIM; cc += blockDim.x)
            d[cc] = __float2half_rn(s[cc]);
    } else if (b < 1792) {
        int r = b - 1280;
        const float* s = w2 + (size_t)r * DDIM;
        half* d = w216 + (size_t)r * DDIM;
        for (int cc = threadIdx.x; cc < DDIM; cc += blockDim.x)
            d[cc] = __float2half_rn(s[cc]);
    } else if (b < 2304) {
        int r = b - 1792;
        const float* s = s1 + (size_t)r * DDIM;
        half* d = s116 + (size_t)r * DDIM;
        for (int cc = threadIdx.x; cc < DDIM; cc += blockDim.x)
            d[cc] = __float2half_rn(s[cc]);
    } else {
        int r = b - 2304;
        const float* s = s2 + (size_t)r * CDIM;
        half* d = s216 + (size_t)r * DDIM;
        for (int cc = threadIdx.x; cc < DDIM; cc += blockDim.x)
            d[cc] = __float2half_rn(cc < CDIM ? s[cc] : 0.f);
    }
}

// ---------------- WMMA GEMM: 128x128 tile, K-chunk 64, 2-stage, 2 CTA/SM ----
template<typename TT, int EPI, bool BCOL>
__global__ void __launch_bounds__(256, 2) wgemm(
    const TT* __restrict__ A, const TT* __restrict__ B,
    const float* __restrict__ bias, float* __restrict__ C,
    TT* __restrict__ OH,
    int M, int N, int K, int lda, int ldb, int ldc)
{
    extern __shared__ __align__(16) char smem[];
    constexpr int AP  = 72;
    constexpr int BPR = 136;
    constexpr int STAGE = 36864;

    const int tid = threadIdx.x;
    const int w = tid >> 5, lane = tid & 31;
    const int wm = w >> 1, wn = w & 1;
    const int m0 = blockIdx.y * 128, n0 = blockIdx.x * 128;

    wmma::fragment<wmma::accumulator, 16, 16, 16, float> acc[2][4];
#pragma unroll
    for (int i = 0; i < 2; i++)
#pragma unroll
        for (int j = 0; j < 4; j++) wmma::fill_fragment(acc[i][j], 0.f);

    auto issue = [&](int k0, int s) {
        char* base = smem + s * STAGE;
        TT* sA = (TT*)base;
        TT* sB = (TT*)(base + 18432);
#pragma unroll
        for (int e = 0; e < 4; e++) {
            int idx = tid + e * 256;
            {
                int row = idx >> 3, c4 = idx & 7;
                size_t off = (size_t)(m0 + row) * lda + k0 + c4 * 8;
                cp16(sA + row * AP + c4 * 8, A + off, true);
            }
            if (BCOL) {
                int n = idx >> 3, c4 = idx & 7;
                bool v = (n0 + n) < N;
                size_t off = v ? ((size_t)(n0 + n) * ldb + k0 + c4 * 8) : 0;
                cp16(sB + n * AP + c4 * 8, B + off, v);
            } else {
                int row = idx >> 4, c4 = idx & 15;
                size_t off = (size_t)(k0 + row) * ldb + n0 + c4 * 8;
                cp16(sB + row * BPR + c4 * 8, B + off, true);
            }
        }
        cp_commit();
    };

    auto compute = [&](int s) {
        char* base = smem + s * STAGE;
        TT* sA = (TT*)base;
        TT* sB = (TT*)(base + 18432);
#pragma unroll
        for (int kf = 0; kf < 64; kf += 16) {
            wmma::fragment<wmma::matrix_a, 16, 16, 16, TT, wmma::row_major> af[2];
#pragma unroll
            for (int i = 0; i < 2; i++)
                wmma::load_matrix_sync(af[i], sA + (wm * 32 + i * 16) * AP + kf, AP);
            if constexpr (BCOL) {
                wmma::fragment<wmma::matrix_b, 16, 16, 16, TT, wmma::col_major> bf;
#pragma unroll
                for (int j = 0; j < 4; j++) {
                    wmma::load_matrix_sync(bf, sB + (wn * 64 + j * 16) * AP + kf, AP);
#pragma unroll
                    for (int i = 0; i < 2; i++)
                        wmma::mma_sync(acc[i][j], af[i], bf, acc[i][j]);
                }
            } else {
                wmma::fragment<wmma::matrix_b, 16, 16, 16, TT, wmma::row_major> bf;
#pragma unroll
                for (int j = 0; j < 4; j++) {
                    wmma::load_matrix_sync(bf, sB + kf * BPR + wn * 64 + j * 16, BPR);
#pragma unroll
                    for (int i = 0; i < 2; i++)
                        wmma::mma_sync(acc[i][j], af[i], bf, acc[i][j]);
                }
            }
        }
    };

    issue(0, 0);
    int cur = 0;
    for (int k0 = 0; k0 < K; k0 += 64) {
        cp_wait<0>();
        __syncthreads();
        if (k0 + 64 < K) issue(k0 + 64, cur ^ 1);
        compute(cur);
        cur ^= 1;
    }
    __syncthreads();

    float* ep = (float*)smem + w * 2176;
#pragma unroll
    for (int i = 0; i < 2; i++)
#pragma unroll
        for (int j = 0; j < 4; j++)
            wmma::store_matrix_sync(ep + i * 16 * 68 + j * 16, acc[i][j], 68,
                                    wmma::mem_row_major);
    __syncwarp();
#pragma unroll 4
    for (int r = 0; r < 32; r++) {
        int gm = m0 + wm * 32 + r;
#pragma unroll
        for (int it = 0; it < 2; it++) {
            int gn = n0 + wn * 64 + it * 32 + lane;
            if (gn < N) {
                float v = ep[r * 68 + it * 32 + lane];
                if (EPI >= 1) v += bias[gn];
                if (EPI == 2) v = fmaxf(v, 0.f);
                size_t off = (size_t)gm * ldc + gn;
                if (C) C[off] = v;
                if (OH) OH[off] = f2t<TT>(v);
            }
        }
    }
}

// ---------------- approx top-64: 2-pass uint16 radix, 1024 threads ----------
__global__ void __launch_bounds__(1024) topk16_kernel()
{
    const int r = blockIdx.x, tid = threadIdx.x;
    const int wid = tid >> 5;
    const bf16* row = g_tau16 + (size_t)r * NMEM;
    const uint4* row4 = (const uint4*)row;
    __shared__ unsigned hist[32 * 256];
    __shared__ int sh_d, sh_need, cnt;
    unsigned* myh = hist + wid * 256;

    // pass 1: per-warp histogram of key high byte
    for (int i = tid; i < 32 * 256; i += 1024) hist[i] = 0;
    __syncthreads();
    for (int i = tid; i < NMEM / 8; i += 1024) {
        uint4 q = row4[i];
        unsigned short hb[8] = {
            (unsigned short)(q.x & 0xFFFFu), (unsigned short)(q.x >> 16),
            (unsigned short)(q.y & 0xFFFFu), (unsigned short)(q.y >> 16),
            (unsigned short)(q.z & 0xFFFFu), (unsigned short)(q.z >> 16),
            (unsigned short)(q.w & 0xFFFFu), (unsigned short)(q.w >> 16)};
#pragma unroll
        for (int t = 0; t < 8; t++)
            atomicAdd(&myh[f2key16(hb[t]) >> 8], 1u);
    }
    __syncthreads();
    {
        unsigned tot = 0;
        if (tid < 256) {
#pragma unroll
            for (int wdx = 0; wdx < 32; wdx++) tot += hist[wdx * 256 + tid];
        }
        __syncthreads();
        if (tid < 256) hist[tid] = tot;
    }
    __syncthreads();
    if (tid == 0) {
        int cum = 0, d = 255;
        for (; d >= 0; --d) {
            if (cum + (int)hist[d] >= KTOP) break;
            cum += (int)hist[d];
        }
        if (d < 0) d = 0;
        sh_d = d; sh_need = KTOP - cum;
    }
    __syncthreads();
    const unsigned hi8 = (unsigned)sh_d;
    const int need = sh_need;
    __syncthreads();

    // pass 2: per-warp histogram of low byte among matching high byte
    for (int i = tid; i < 32 * 256; i += 1024) hist[i] = 0;
    __syncthreads();
    for (int i = tid; i < NMEM / 8; i += 1024) {
        uint4 q = row4[i];
        unsigned short hb[8] = {
            (unsigned short)(q.x & 0xFFFFu), (unsigned short)(q.x >> 16),
            (unsigned short)(q.y & 0xFFFFu), (unsigned short)(q.y >> 16),
            (unsigned short)(q.z & 0xFFFFu), (unsigned short)(q.z >> 16),
            (unsigned short)(q.w & 0xFFFFu), (unsigned short)(q.w >> 16)};
#pragma unroll
        for (int t = 0; t < 8; t++) {
            unsigned short k = f2key16(hb[t]);
            if ((k >> 8) == hi8) atomicAdd(&myh[k & 0xFFu], 1u);
        }
    }
    __syncthreads();
    {
        unsigned tot = 0;
        if (tid < 256) {
#pragma unroll
            for (int wdx = 0; wdx < 32; wdx++) tot += hist[wdx * 256 + tid];
        }
        __syncthreads();
        if (tid < 256) hist[tid] = tot;
    }
    __syncthreads();
    if (tid == 0) {
        int cum = 0, d = 255;
        for (; d >= 0; --d) {
            if (cum + (int)hist[d] >= need) break;
            cum += (int)hist[d];
        }
        if (d < 0) d = 0;
        sh_d = d;
        cnt = 0;
    }
    __syncthreads();
    const unsigned short k64 = (unsigned short)((hi8 << 8) | (unsigned)sh_d);
    const float thr = key16_to_f(k64) - 2.0f;   // margin covers bf16+accum error
    __syncthreads();

    // gather candidates
    for (int i = tid; i < NMEM / 8; i += 1024) {
        uint4 q = row4[i];
        unsigned short hb[8] = {
            (unsigned short)(q.x & 0xFFFFu), (unsigned short)(q.x >> 16),
            (unsigned short)(q.y & 0xFFFFu), (unsigned short)(q.y >> 16),
            (unsigned short)(q.z & 0xFFFFu), (unsigned short)(q.z >> 16),
            (unsigned short)(q.w & 0xFFFFu), (unsigned short)(q.w >> 16)};
#pragma unroll
        for (int t = 0; t < 8; t++) {
            __nv_bfloat16_raw br; br.x = hb[t];
            if (__bfloat162float((bf16)br) >= thr) {
                int p = atomicAdd(&cnt, 1);
                if (p < CAP) g_candidx[(size_t)r * CAP + p] = i * 8 + t;
            }
        }
    }
    __syncthreads();
    if (tid == 0) g_candcnt[r] = (cnt < CAP) ? cnt : CAP;
}

// ---------------- fp32 rescore (sequential-k fma, UNCHANGED) ----------------
__global__ void __launch_bounds__(256) rescore_kernel(
    const float* __restrict__ c, const float* __restrict__ mem_c)
{
    const int r = blockIdx.x, tid = threadIdx.x;
    __shared__ float sc[512];
    __shared__ float scores[CAP];
    __shared__ int   cidx[CAP];
    const int nc = g_candcnt[r];

    for (int k = tid; k < CDIM; k += 256) sc[k] = c[(size_t)r * CDIM + k];
    for (int i = tid; i < nc; i += 256) cidx[i] = g_candidx[(size_t)r * CAP + i];
    __syncthreads();

    for (int ci = tid; ci < nc; ci += 256) {
        const float* mr = mem_c + (size_t)cidx[ci] * CDIM;
        float s = 0.f;
#pragma unroll 8
        for (int k = 0; k < CDIM; k++) s = fmaf(sc[k], mr[k], s);
        scores[ci] = s;
    }
    __syncthreads();

    for (int ci = tid; ci < nc; ci += 256) {
        float v = scores[ci]; int id = cidx[ci];
        int rank = 0;
        for (int j = 0; j < nc; j++) {
            float vj = scores[j];
            rank += (vj > v) || (vj == v && cidx[j] < id);
        }
        if (rank < KTOP) {
            g_deltas[r * KTOP + rank] = v;
            g_topidx[r * KTOP + rank] = id;
        }
    }
}

// ---------------- mems = concat(delta, mem_c[idx]) + fp16 emit --------------
__global__ void build_mems_kernel(const float* __restrict__ mem_c)
{
    const int row = blockIdx.x, tid = threadIdx.x;
    const int idx = g_topidx[row];
    const float d0 = g_deltas[row];
    float* out = g_mems + (size_t)row * DDIM;
    half*  oh  = g_ah  + (size_t)row * DDIM;
    const float* src = mem_c + (size_t)idx * CDIM;
    for (int cpos = tid; cpos < DDIM; cpos += blockDim.x) {
        float v = (cpos == 0) ? d0 : src[cpos - 1];
        out[cpos] = v;
        oh[cpos] = __float2half_rn(v);
    }
}

// ---------------- single-pass vectorized LayerNorm (fp16 emit) --------------
__global__ void ln_kernel(
    const float* __restrict__ x, const float* __restrict__ res,
    const float* __restrict__ g, const float* __restrict__ bb,
    float* __restrict__ out, half* __restrict__ oh, int W)
{
    const int row = blockIdx.x, tid = threadIdx.x;
    float4 v = ((const float4*)(x + (size_t)row * W))[tid];
    if (res) {
        float4 r = ((const float4*)(res + (size_t)row * W))[tid];
        v.x += r.x; v.y += r.y; v.z += r.z; v.w += r.w;
    }
    float s  = v.x + v.y + v.z + v.w;
    float s2 = v.x * v.x + v.y * v.y + v.z * v.z + v.w * v.w;
    __shared__ float red1[8], red2[8];
#pragma unroll
    for (int o = 16; o > 0; o >>= 1) {
        s  += __shfl_xor_sync(0xFFFFFFFFu, s, o);
        s2 += __shfl_xor_sync(0xFFFFFFFFu, s2, o);
    }
    const int wid = tid >> 5, nw = blockDim.x >> 5;
    if ((tid & 31) == 0) { red1[wid] = s; red2[wid] = s2; }
    __syncthreads();
    if (tid < 32) {
        s  = (tid < nw) ? red1[tid] : 0.f;
        s2 = (tid < nw) ? red2[tid] : 0.f;
#pragma unroll
        for (int o = 4; o > 0; o >>= 1) {
            s  += __shfl_xor_sync(0xFFFFFFFFu, s, o);
            s2 += __shfl_xor_sync(0xFFFFFFFFu, s2, o);
        }
        if (tid == 0) { red1[0] = s; red2[0] = s2; }
    }
    __syncthreads();
    const float mu = red1[0] / W;
    const float var = red2[0] / W - mu * mu;
    const float rs = rsqrtf(var + 1e-5f);

    float4 gg = ((const float4*)g)[tid];
    float4 b4 = ((const float4*)bb)[tid];
    float4 y;
    y.x = (v.x - mu) * rs * gg.x + b4.x;
    y.y = (v.y - mu) * rs * gg.y + b4.y;
    y.z = (v.z - mu) * rs * gg.z + b4.z;
    y.w = (v.w - mu) * rs * gg.w + b4.w;
    ((float4*)(out + (size_t)row * W))[tid] = y;
    if (oh) {
        union { half h[4]; uint2 u; } H;
        H.h[0] = __float2half_rn(y.x);
        H.h[1] = __float2half_rn(y.y);
        H.h[2] = __float2half_rn(y.z);
        H.h[3] = __float2half_rn(y.w);
        ((uint2*)(oh + (size_t)row * W))[tid] = H.u;
    }
}

// ---------------- fused LN(qkv) + attention per batch ------------------------
#define QP 645
#define SP 68
__global__ void __launch_bounds__(256) attn_ln_kernel(
    const float* __restrict__ gq, const float* __restrict__ gb)
{
    extern __shared__ float smf[];
    float* sqkv = smf;                    // 64*645
    float* ss   = smf + 64 * QP;          // 64*68
    float* smu  = ss + 64 * SP;           // 64
    float* srs  = smu + 64;               // 64
    const int b = blockIdx.x, tid = threadIdx.x;
    const int wid = tid >> 5, lane = tid & 31;
    const float* qkv = g_qkvbuf + (size_t)b * 64 * TOTW;

    const float4* qkv4 = (const float4*)qkv;
    for (int e4 = tid; e4 < 64 * TOTW / 4; e4 += 256) {
        float4 f = qkv4[e4];
        int flat = e4 * 4;
        int i = flat / TOTW, col = flat % TOTW;
        float* dst = sqkv + i * QP + col;
        dst[0] = f.x; dst[1] = f.y; dst[2] = f.z; dst[3] = f.w;
    }
    __syncthreads();

    for (int rr = 0; rr < 8; rr++) {
        int rowi = wid * 8 + rr;
        float s = 0.f, s2 = 0.f;
        for (int col = lane; col < TOTW; col += 32) {
            float v = sqkv[rowi * QP + col];
            s += v; s2 += v * v;
        }
#pragma unroll
        for (int o = 16; o > 0; o >>= 1) {
            s  += __shfl_xor_sync(0xFFFFFFFFu, s, o);
            s2 += __shfl_xor_sync(0xFFFFFFFFu, s2, o);
        }
        if (lane == 0) {
            float mu = s / TOTW;
            float var = s2 / TOTW - mu * mu;
            smu[rowi] = mu;
            srs[rowi] = rsqrtf(var + 1e-5f);
        }
    }
    __syncthreads();

    for (int e = tid; e < 64 * TOTW; e += 256) {
        int i = e / TOTW, col = e % TOTW;
        float v = (sqkv[i * QP + col] - smu[i]) * srs[i] * gq[col] + gb[col];
        if (col < KEYS) v *= 0.125f;
        sqkv[i * QP + col] = v;
    }
    __syncthreads();

    for (int e = tid; e < 4096; e += 256) {
        int i = e >> 6, j = e & 63;
        float acc = 0.f;
#pragma unroll 16
        for (int d = 0; d < 64; d++)
            acc += sqkv[i * QP + d] * sqkv[j * QP + KEYS + d];
        ss[i * SP + j] = acc;
    }
    __syncthreads();

    for (int rowi = wid; rowi < 64; rowi += 8) {
        float m = -1e30f;
        for (int j = lane; j < 64; j += 32) m = fmaxf(m, ss[rowi * SP + j]);
#pragma unroll
        for (int o = 16; o > 0; o >>= 1)
            m = fmaxf(m, __shfl_xor_sync(0xFFFFFFFFu, m, o));
        float s = 0.f;
        for (int j = lane; j < 64; j += 32) {
            float e = expf(ss[rowi * SP + j] - m);
            ss[rowi * SP + j] = e; s += e;
        }
#pragma unroll
        for (int o = 16; o > 0; o >>= 1)
            s += __shfl_xor_sync(0xFFFFFFFFu, s, o);
        float inv = 1.f / s;
        for (int j = lane; j < 64; j += 32) ss[rowi * SP + j] *= inv;
    }
    __syncthreads();

    for (int dpass = 0; dpass < 2; dpass++) {
        const int d = dpass * 256 + tid;
        float acc[64];
#pragma unroll
        for (int i = 0; i < 64; i++) acc[i] = 0.f;
        for (int jb = 0; jb < 64; jb += 8) {
            float vv[8];
#pragma unroll
            for (int t = 0; t < 8; t++)
                vv[t] = sqkv[(jb + t) * QP + 2 * KEYS + d];
#pragma unroll
            for (int i = 0; i < 64; i++) {
                float4 w0 = *(const float4*)&ss[i * SP + jb];
                float4 w1 = *(const float4*)&ss[i * SP + jb + 4];
                acc[i] += w0.x * vv[0] + w0.y * vv[1] + w0.z * vv[2] + w0.w * vv[3]
                        + w1.x * vv[4] + w1.y * vv[5] + w1.z * vv[6] + w1.w * vv[7];
            }
        }
#pragma unroll
        for (int i = 0; i < 64; i++)
            g_att[(size_t)(b * 64 + i) * DDIM + d] = acc[i];
    }
}

// ---------------- host orchestration -----------------------------------------
extern "C" void kernel_launch(void* const* d_in, const int* in_sizes, int n_in,
                              void* d_out, int out_size)
{
    const float* c     = (const float*)d_in[0];
    const float* mem_c = (const float*)d_in[1];
    const float* Wqkv  = (const float*)d_in[2];
    const float* bqkv  = (const float*)d_in[3];
    const float* gq    = (const float*)d_in[4];
    const float* bq    = (const float*)d_in[5];
    const float* gm    = (const float*)d_in[6];
    const float* bm    = (const float*)d_in[7];
    const float* W1    = (const float*)d_in[8];
    const float* b1    = (const float*)d_in[9];
    const float* W2    = (const float*)d_in[10];
    const float* b2    = (const float*)d_in[11];
    const float* Ws1   = (const float*)d_in[12];
    const float* bs1   = (const float*)d_in[13];
    const float* Ws2   = (const float*)d_in[14];
    const float* bs2   = (const float*)d_in[15];
    float* out = (float*)d_out;

    float *p_mems, *p_qkv, *p_att, *p_mem, *p_t2;
    bf16 *p_tau16, *p_c16, *p_mc16;
    half *p_ah, *p_hh, *p_wq, *p_w1, *p_w2, *p_s1, *p_s2;
    cudaGetSymbolAddress((void**)&p_tau16, g_tau16);
    cudaGetSymbolAddress((void**)&p_mems, g_mems);
    cudaGetSymbolAddress((void**)&p_qkv,  g_qkvbuf);
    cudaGetSymbolAddress((void**)&p_att,  g_att);
    cudaGetSymbolAddress((void**)&p_mem,  g_mem);
    cudaGetSymbolAddress((void**)&p_t2,   g_t2);
    cudaGetSymbolAddress((void**)&p_c16,  g_c16);
    cudaGetSymbolAddress((void**)&p_mc16, g_mc16);
    cudaGetSymbolAddress((void**)&p_ah,   g_ah);
    cudaGetSymbolAddress((void**)&p_hh,   g_hh);
    cudaGetSymbolAddress((void**)&p_wq,   g_wqkv);
    cudaGetSymbolAddress((void**)&p_w1,   g_w1);
    cudaGetSymbolAddress((void**)&p_w2,   g_w2);
    cudaGetSymbolAddress((void**)&p_s1,   g_ws1);
    cudaGetSymbolAddress((void**)&p_s2,   g_ws2);

    const int SM_WG = 73728;                              // 2 stages x 36864
    const int SM_ATTN = (64 * QP + 64 * SP + 128) * 4;    // 183040
    cudaFuncSetAttribute(wgemm<bf16, 0, true>,  cudaFuncAttributeMaxDynamicSharedMemorySize, SM_WG);
    cudaFuncSetAttribute(wgemm<half, 1, false>, cudaFuncAttributeMaxDynamicSharedMemorySize, SM_WG);
    cudaFuncSetAttribute(wgemm<half, 2, false>, cudaFuncAttributeMaxDynamicSharedMemorySize, SM_WG);
    cudaFuncSetAttribute(attn_ln_kernel, cudaFuncAttributeMaxDynamicSharedMemorySize, SM_ATTN);
    const dim3 blk(256);

    // --- conversions ---
    conv_small_kernel<<<2816, 128>>>(c, p_c16, Wqkv, p_wq, W1, p_w1,
                                     W2, p_w2, Ws1, p_s1, Ws2, p_s2);
    conv_memc_kernel<<<2048, 256>>>(mem_c, p_mc16);

    // --- 1) approx tau (bf16 out) = c16 @ mc16^T ---
    wgemm<bf16, 0, true><<<dim3((NMEM + 127) / 128, 2), blk, SM_WG>>>(
        p_c16, p_mc16, nullptr, nullptr, p_tau16,
        NB, NMEM, DDIM, DDIM, DDIM, NMEM);

    // --- 2) radix candidate select (1024 thr) + exact fp32 rescore ---
    topk16_kernel<<<NB, 1024>>>();
    rescore_kernel<<<NB, blk>>>(c, mem_c);

    // --- 3) mems + fp16 emit ---
    build_mems_kernel<<<ROWS, 128>>>(mem_c);

    // --- 4) qkv = mems @ Wqkv + bqkv  (LN fused into attention) ---
    wgemm<half, 1, false><<<dim3(5, 128), blk, SM_WG>>>(
        p_ah, p_wq, bqkv, p_qkv, (half*)nullptr,
        ROWS, TOTW, DDIM, DDIM, TOTW, TOTW);

    // --- 5) fused LN + attention ---
    attn_ln_kernel<<<NB, blk, SM_ATTN>>>(gq, bq);

    // --- 6) mem = LN(mems + attended)  (+ fp16 emit) ---
    ln_kernel<<<ROWS, 128>>>(p_mems, p_att, gm, bm, p_mem, p_ah, DDIM);

    // --- 7) two residual MLP blocks ---
    for (int rep = 0; rep < 2; rep++) {
        wgemm<half, 2, false><<<dim3(4, 128), blk, SM_WG>>>(
            p_ah, p_w1, b1, nullptr, p_hh,
            ROWS, DDIM, DDIM, DDIM, DDIM, DDIM);
        wgemm<half, 1, false><<<dim3(4, 128), blk, SM_WG>>>(
            p_hh, p_w2, b2, p_t2, (half*)nullptr,
            ROWS, DDIM, DDIM, DDIM, DDIM, DDIM);
        ln_kernel<<<ROWS, 128>>>(p_t2, p_mem, gm, bm, p_mem, p_ah, DDIM);
    }

    // --- 8) c_prime = relu(mem @ Ws1 + bs1) @ Ws2 + bs2 ---
    wgemm<half, 2, false><<<dim3(4, 128), blk, SM_WG>>>(
        p_ah, p_s1, bs1, nullptr, p_hh,
        ROWS, DDIM, DDIM, DDIM, DDIM, DDIM);
    wgemm<half, 1, false><<<dim3(4, 128), blk, SM_WG>>>(
        p_hh, p_s2, bs2, out, (half*)nullptr,
        ROWS, CDIM, DDIM, DDIM, DDIM, CDIM);
}

// round 17
// speedup vs baseline: 2.5335x; 1.0144x over previous
#include <cuda_runtime.h>
#include <cuda_bf16.h>
#include <cuda_fp16.h>
#include <mma.h>
#include <math.h>

using namespace nvcuda;
typedef __nv_bfloat16 bf16;

#define NB    256
#define NMEM  100000
#define CDIM  511
#define DDIM  512
#define KEYS  64
#define TOTW  640
#define KTOP  64
#define ROWS  (NB*KTOP)   // 16384
#define CAP   1024        // candidate cap per row

// ---------------- scratch (device globals; no allocations allowed) ----------
__device__ bf16  g_tau16[(size_t)NB*NMEM];     // approx tau in bf16, 51.2 MB
__device__ float g_deltas[NB*KTOP];
__device__ int   g_topidx[NB*KTOP];
__device__ int   g_candidx[(size_t)NB*CAP];
__device__ int   g_candcnt[NB];
__device__ float g_mems[(size_t)ROWS*DDIM];
__device__ float g_qkvbuf[(size_t)ROWS*TOTW];
__device__ float g_mem[(size_t)ROWS*DDIM];
__device__ float g_t2[(size_t)ROWS*DDIM];

// tau path stays bf16 (selection invariance)
__device__ bf16 g_c16[(size_t)NB*DDIM];
__device__ bf16 g_mc16[(size_t)NMEM*DDIM];
// downstream path: fp16 single-term
__device__ half g_ah[(size_t)ROWS*DDIM];
__device__ half g_hh[(size_t)ROWS*DDIM];
__device__ half g_wqkv[(size_t)DDIM*TOTW];
__device__ half g_w1[(size_t)DDIM*DDIM];
__device__ half g_w2[(size_t)DDIM*DDIM];
__device__ half g_ws1[(size_t)DDIM*DDIM];
__device__ half g_ws2[(size_t)DDIM*DDIM];     // 511->512 pad

// ---------------- cp.async helpers ------------------------------------------
__device__ __forceinline__ void cp16(void* dst_smem, const void* src, bool pred) {
    unsigned d = (unsigned)__cvta_generic_to_shared(dst_smem);
    int sz = pred ? 16 : 0;
    asm volatile("cp.async.cg.shared.global [%0], [%1], 16, %2;\n"
                 :: "r"(d), "l"(src), "r"(sz));
}
__device__ __forceinline__ void cp_commit() {
    asm volatile("cp.async.commit_group;\n");
}
template<int NN>
__device__ __forceinline__ void cp_wait() {
    asm volatile("cp.async.wait_group %0;\n" :: "n"(NN));
}

__device__ __forceinline__ unsigned short f2key16(unsigned short b) {
    return (b & 0x8000u) ? (unsigned short)(~b) : (unsigned short)(b | 0x8000u);
}
__device__ __forceinline__ float key16_to_f(unsigned short k) {
    unsigned short raw = (k & 0x8000u) ? (unsigned short)(k & 0x7FFFu)
                                       : (unsigned short)(~k);
    __nv_bfloat16_raw br; br.x = raw;
    return __bfloat162float((bf16)br);
}

template<typename T> __device__ __forceinline__ T f2t(float v);
template<> __device__ __forceinline__ half f2t<half>(float v) { return __float2half_rn(v); }
template<> __device__ __forceinline__ bf16 f2t<bf16>(float v) { return __float2bfloat16_rn(v); }

// ---------------- mem_c conversion: flat float4, constant divisor -----------
__global__ void conv_memc_kernel(const float* __restrict__ src, bf16* __restrict__ dst)
{
    const size_t total4 = (size_t)NMEM * CDIM / 4;
    const size_t stride = (size_t)gridDim.x * blockDim.x;
    for (size_t i4 = (size_t)blockIdx.x * blockDim.x + threadIdx.x;
         i4 < total4; i4 += stride) {
        float4 f = ((const float4*)src)[i4];
        size_t flat = i4 * 4;
        float vv[4] = {f.x, f.y, f.z, f.w};
#pragma unroll
        for (int t = 0; t < 4; t++) {
            size_t e = flat + t;
            size_t r = e / CDIM;
            size_t c = e - r * CDIM;
            dst[r * DDIM + c] = __float2bfloat16_rn(vv[t]);
        }
    }
    for (size_t r = (size_t)blockIdx.x * blockDim.x + threadIdx.x;
         r < NMEM; r += stride)
        dst[r * DDIM + CDIM] = __float2bfloat16_rn(0.f);
}

// ---------------- fused small conversions: c + 5 weights in ONE launch ------
__global__ void conv_small_kernel(
    const float* __restrict__ c,   bf16* __restrict__ c16,
    const float* __restrict__ wq,  half* __restrict__ wq16,
    const float* __restrict__ w1,  half* __restrict__ w116,
    const float* __restrict__ w2,  half* __restrict__ w216,
    const float* __restrict__ s1,  half* __restrict__ s116,
    const float* __restrict__ s2,  half* __restrict__ s216)
{
    const int b = blockIdx.x;
    if (b < 256) {
        const float* s = c + (size_t)b * CDIM;
        bf16* d = c16 + (size_t)b * DDIM;
        for (int cc = threadIdx.x; cc < DDIM; cc += blockDim.x)
            d[cc] = __float2bfloat16_rn(cc < CDIM ? s[cc] : 0.f);
    } else if (b < 768) {
        int r = b - 256;
        const float* s = wq + (size_t)r * TOTW;
        half* d = wq16 + (size_t)r * TOTW;
        for (int cc = threadIdx.x; cc < TOTW; cc += blockDim.x)
            d[cc] = __float2half_rn(s[cc]);
    } else if (b < 1280) {
        int r = b - 768;
        const float* s = w1 + (size_t)r * DDIM;
        half* d = w116 + (size_t)r * DDIM;
        for (int cc = threadIdx.x; cc < DDIM; cc += blockDim.x)
            d[cc] = __float2half_rn(s[cc]);
    } else if (b < 1792) {
        int r = b - 1280;
        const float* s = w2 + (size_t)r * DDIM;
        half* d = w216 + (size_t)r * DDIM;
        for (int cc = threadIdx.x; cc < DDIM; cc += blockDim.x)
            d[cc] = __float2half_rn(s[cc]);
    } else if (b < 2304) {
        int r = b - 1792;
        const float* s = s1 + (size_t)r * DDIM;
        half* d = s116 + (size_t)r * DDIM;
        for (int cc = threadIdx.x; cc < DDIM; cc += blockDim.x)
            d[cc] = __float2half_rn(s[cc]);
    } else {
        int r = b - 2304;
        const float* s = s2 + (size_t)r * CDIM;
        half* d = s216 + (size_t)r * DDIM;
        for (int cc = threadIdx.x; cc < DDIM; cc += blockDim.x)
            d[cc] = __float2half_rn(cc < CDIM ? s[cc] : 0.f);
    }
}

// ---------------- WMMA GEMM: 128x128 tile, K-chunk 64, 2-stage, 2 CTA/SM ----
template<typename TT, int EPI, bool BCOL>
__global__ void __launch_bounds__(256, 2) wgemm(
    const TT* __restrict__ A, const TT* __restrict__ B,
    const float* __restrict__ bias, float* __restrict__ C,
    TT* __restrict__ OH,
    int M, int N, int K, int lda, int ldb, int ldc)
{
    extern __shared__ __align__(16) char smem[];
    constexpr int AP  = 72;
    constexpr int BPR = 136;
    constexpr int STAGE = 36864;

    const int tid = threadIdx.x;
    const int w = tid >> 5, lane = tid & 31;
    const int wm = w >> 1, wn = w & 1;
    const int m0 = blockIdx.y * 128, n0 = blockIdx.x * 128;

    wmma::fragment<wmma::accumulator, 16, 16, 16, float> acc[2][4];
#pragma unroll
    for (int i = 0; i < 2; i++)
#pragma unroll
        for (int j = 0; j < 4; j++) wmma::fill_fragment(acc[i][j], 0.f);

    auto issue = [&](int k0, int s) {
        char* base = smem + s * STAGE;
        TT* sA = (TT*)base;
        TT* sB = (TT*)(base + 18432);
#pragma unroll
        for (int e = 0; e < 4; e++) {
            int idx = tid + e * 256;
            {
                int row = idx >> 3, c4 = idx & 7;
                size_t off = (size_t)(m0 + row) * lda + k0 + c4 * 8;
                cp16(sA + row * AP + c4 * 8, A + off, true);
            }
            if (BCOL) {
                int n = idx >> 3, c4 = idx & 7;
                bool v = (n0 + n) < N;
                size_t off = v ? ((size_t)(n0 + n) * ldb + k0 + c4 * 8) : 0;
                cp16(sB + n * AP + c4 * 8, B + off, v);
            } else {
                int row = idx >> 4, c4 = idx & 15;
                size_t off = (size_t)(k0 + row) * ldb + n0 + c4 * 8;
                cp16(sB + row * BPR + c4 * 8, B + off, true);
            }
        }
        cp_commit();
    };

    auto compute = [&](int s) {
        char* base = smem + s * STAGE;
        TT* sA = (TT*)base;
        TT* sB = (TT*)(base + 18432);
#pragma unroll
        for (int kf = 0; kf < 64; kf += 16) {
            wmma::fragment<wmma::matrix_a, 16, 16, 16, TT, wmma::row_major> af[2];
#pragma unroll
            for (int i = 0; i < 2; i++)
                wmma::load_matrix_sync(af[i], sA + (wm * 32 + i * 16) * AP + kf, AP);
            if constexpr (BCOL) {
                wmma::fragment<wmma::matrix_b, 16, 16, 16, TT, wmma::col_major> bf;
#pragma unroll
                for (int j = 0; j < 4; j++) {
                    wmma::load_matrix_sync(bf, sB + (wn * 64 + j * 16) * AP + kf, AP);
#pragma unroll
                    for (int i = 0; i < 2; i++)
                        wmma::mma_sync(acc[i][j], af[i], bf, acc[i][j]);
                }
            } else {
                wmma::fragment<wmma::matrix_b, 16, 16, 16, TT, wmma::row_major> bf;
#pragma unroll
                for (int j = 0; j < 4; j++) {
                    wmma::load_matrix_sync(bf, sB + kf * BPR + wn * 64 + j * 16, BPR);
#pragma unroll
                    for (int i = 0; i < 2; i++)
                        wmma::mma_sync(acc[i][j], af[i], bf, acc[i][j]);
                }
            }
        }
    };

    issue(0, 0);
    int cur = 0;
    for (int k0 = 0; k0 < K; k0 += 64) {
        cp_wait<0>();
        __syncthreads();
        if (k0 + 64 < K) issue(k0 + 64, cur ^ 1);
        compute(cur);
        cur ^= 1;
    }
    __syncthreads();

    float* ep = (float*)smem + w * 2176;
#pragma unroll
    for (int i = 0; i < 2; i++)
#pragma unroll
        for (int j = 0; j < 4; j++)
            wmma::store_matrix_sync(ep + i * 16 * 68 + j * 16, acc[i][j], 68,
                                    wmma::mem_row_major);
    __syncwarp();
#pragma unroll 4
    for (int r = 0; r < 32; r++) {
        int gm = m0 + wm * 32 + r;
#pragma unroll
        for (int it = 0; it < 2; it++) {
            int gn = n0 + wn * 64 + it * 32 + lane;
            if (gn < N) {
                float v = ep[r * 68 + it * 32 + lane];
                if (EPI >= 1) v += bias[gn];
                if (EPI == 2) v = fmaxf(v, 0.f);
                size_t off = (size_t)gm * ldc + gn;
                if (C) C[off] = v;
                if (OH) OH[off] = f2t<TT>(v);
            }
        }
    }
}

// ---------------- approx top-64: SINGLE-pass 13-bit histogram + gather ------
// Threshold = bottom of the 13-bit bucket containing the 64th value, -2.0
// margin. Candidate set is a SUPERSET of the 2-pass version's; rescore is
// exact, so the selected top-64 is identical. Expected ~120-170 cands << CAP.
__global__ void __launch_bounds__(1024) topk16_kernel()
{
    const int r = blockIdx.x, tid = threadIdx.x;
    const bf16* row = g_tau16 + (size_t)r * NMEM;
    const uint4* row4 = (const uint4*)row;
    __shared__ unsigned hist[8192];
    __shared__ unsigned gsum[256];
    __shared__ int sh_bin, cnt;

    for (int i = tid; i < 8192; i += 1024) hist[i] = 0;
    __syncthreads();
    for (int i = tid; i < NMEM / 8; i += 1024) {
        uint4 q = row4[i];
        unsigned short hb[8] = {
            (unsigned short)(q.x & 0xFFFFu), (unsigned short)(q.x >> 16),
            (unsigned short)(q.y & 0xFFFFu), (unsigned short)(q.y >> 16),
            (unsigned short)(q.z & 0xFFFFu), (unsigned short)(q.z >> 16),
            (unsigned short)(q.w & 0xFFFFu), (unsigned short)(q.w >> 16)};
#pragma unroll
        for (int t = 0; t < 8; t++)
            atomicAdd(&hist[f2key16(hb[t]) >> 3], 1u);
    }
    __syncthreads();
    if (tid < 256) {
        unsigned s = 0;
#pragma unroll
        for (int k = 0; k < 32; k++) s += hist[tid * 32 + k];
        gsum[tid] = s;
    }
    __syncthreads();
    if (tid == 0) {
        int cum = 0, g = 255;
        for (; g >= 0; --g) {
            if (cum + (int)gsum[g] >= KTOP) break;
            cum += (int)gsum[g];
        }
        if (g < 0) { g = 0; }
        int b = g * 32 + 31;
        for (; b > g * 32; --b) {
            if (cum + (int)hist[b] >= KTOP) break;
            cum += (int)hist[b];
        }
        sh_bin = b;
        cnt = 0;
    }
    __syncthreads();
    const float thr = key16_to_f((unsigned short)(sh_bin << 3)) - 2.0f;
    __syncthreads();

    for (int i = tid; i < NMEM / 8; i += 1024) {
        uint4 q = row4[i];
        unsigned short hb[8] = {
            (unsigned short)(q.x & 0xFFFFu), (unsigned short)(q.x >> 16),
            (unsigned short)(q.y & 0xFFFFu), (unsigned short)(q.y >> 16),
            (unsigned short)(q.z & 0xFFFFu), (unsigned short)(q.z >> 16),
            (unsigned short)(q.w & 0xFFFFu), (unsigned short)(q.w >> 16)};
#pragma unroll
        for (int t = 0; t < 8; t++) {
            __nv_bfloat16_raw br; br.x = hb[t];
            if (__bfloat162float((bf16)br) >= thr) {
                int p = atomicAdd(&cnt, 1);
                if (p < CAP) g_candidx[(size_t)r * CAP + p] = i * 8 + t;
            }
        }
    }
    __syncthreads();
    if (tid == 0) g_candcnt[r] = (cnt < CAP) ? cnt : CAP;
}

// ---------------- fp32 rescore (sequential-k fma, UNCHANGED) ----------------
__global__ void __launch_bounds__(256) rescore_kernel(
    const float* __restrict__ c, const float* __restrict__ mem_c)
{
    const int r = blockIdx.x, tid = threadIdx.x;
    __shared__ float sc[512];
    __shared__ float scores[CAP];
    __shared__ int   cidx[CAP];
    const int nc = g_candcnt[r];

    for (int k = tid; k < CDIM; k += 256) sc[k] = c[(size_t)r * CDIM + k];
    for (int i = tid; i < nc; i += 256) cidx[i] = g_candidx[(size_t)r * CAP + i];
    __syncthreads();

    for (int ci = tid; ci < nc; ci += 256) {
        const float* mr = mem_c + (size_t)cidx[ci] * CDIM;
        float s = 0.f;
#pragma unroll 8
        for (int k = 0; k < CDIM; k++) s = fmaf(sc[k], mr[k], s);
        scores[ci] = s;
    }
    __syncthreads();

    for (int ci = tid; ci < nc; ci += 256) {
        float v = scores[ci]; int id = cidx[ci];
        int rank = 0;
        for (int j = 0; j < nc; j++) {
            float vj = scores[j];
            rank += (vj > v) || (vj == v && cidx[j] < id);
        }
        if (rank < KTOP) {
            g_deltas[r * KTOP + rank] = v;
            g_topidx[r * KTOP + rank] = id;
        }
    }
}

// ---------------- mems = concat(delta, mem_c[idx]) + fp16 emit --------------
__global__ void build_mems_kernel(const float* __restrict__ mem_c)
{
    const int row = blockIdx.x, tid = threadIdx.x;
    const int idx = g_topidx[row];
    const float d0 = g_deltas[row];
    float* out = g_mems + (size_t)row * DDIM;
    half*  oh  = g_ah  + (size_t)row * DDIM;
    const float* src = mem_c + (size_t)idx * CDIM;
    for (int cpos = tid; cpos < DDIM; cpos += blockDim.x) {
        float v = (cpos == 0) ? d0 : src[cpos - 1];
        out[cpos] = v;
        oh[cpos] = __float2half_rn(v);
    }
}

// ---------------- single-pass vectorized LayerNorm (fp16 emit) --------------
__global__ void ln_kernel(
    const float* __restrict__ x, const float* __restrict__ res,
    const float* __restrict__ g, const float* __restrict__ bb,
    float* __restrict__ out, half* __restrict__ oh, int W)
{
    const int row = blockIdx.x, tid = threadIdx.x;
    float4 v = ((const float4*)(x + (size_t)row * W))[tid];
    if (res) {
        float4 r = ((const float4*)(res + (size_t)row * W))[tid];
        v.x += r.x; v.y += r.y; v.z += r.z; v.w += r.w;
    }
    float s  = v.x + v.y + v.z + v.w;
    float s2 = v.x * v.x + v.y * v.y + v.z * v.z + v.w * v.w;
    __shared__ float red1[8], red2[8];
#pragma unroll
    for (int o = 16; o > 0; o >>= 1) {
        s  += __shfl_xor_sync(0xFFFFFFFFu, s, o);
        s2 += __shfl_xor_sync(0xFFFFFFFFu, s2, o);
    }
    const int wid = tid >> 5, nw = blockDim.x >> 5;
    if ((tid & 31) == 0) { red1[wid] = s; red2[wid] = s2; }
    __syncthreads();
    if (tid < 32) {
        s  = (tid < nw) ? red1[tid] : 0.f;
        s2 = (tid < nw) ? red2[tid] : 0.f;
#pragma unroll
        for (int o = 4; o > 0; o >>= 1) {
            s  += __shfl_xor_sync(0xFFFFFFFFu, s, o);
            s2 += __shfl_xor_sync(0xFFFFFFFFu, s2, o);
        }
        if (tid == 0) { red1[0] = s; red2[0] = s2; }
    }
    __syncthreads();
    const float mu = red1[0] / W;
    const float var = red2[0] / W - mu * mu;
    const float rs = rsqrtf(var + 1e-5f);

    float4 gg = ((const float4*)g)[tid];
    float4 b4 = ((const float4*)bb)[tid];
    float4 y;
    y.x = (v.x - mu) * rs * gg.x + b4.x;
    y.y = (v.y - mu) * rs * gg.y + b4.y;
    y.z = (v.z - mu) * rs * gg.z + b4.z;
    y.w = (v.w - mu) * rs * gg.w + b4.w;
    ((float4*)(out + (size_t)row * W))[tid] = y;
    if (oh) {
        union { half h[4]; uint2 u; } H;
        H.h[0] = __float2half_rn(y.x);
        H.h[1] = __float2half_rn(y.y);
        H.h[2] = __float2half_rn(y.z);
        H.h[3] = __float2half_rn(y.w);
        ((uint2*)(oh + (size_t)row * W))[tid] = H.u;
    }
}

// ---------------- fused LN(qkv) + attention + residual-LN per batch ----------
// Computes qkv-LN, attention, attended (in-place over v region), then
// mem = LN(mems + attended) directly into g_mem (fp32) and g_ah (fp16).
#define QP 645
#define SP 68
__global__ void __launch_bounds__(256) attn_ln_kernel(
    const float* __restrict__ gq, const float* __restrict__ gb,
    const float* __restrict__ gm, const float* __restrict__ bm)
{
    extern __shared__ float smf[];
    float* sqkv = smf;                    // 64*645
    float* ss   = smf + 64 * QP;          // 64*68
    float* smu  = ss + 64 * SP;           // 64
    float* srs  = smu + 64;               // 64
    const int b = blockIdx.x, tid = threadIdx.x;
    const int wid = tid >> 5, lane = tid & 31;
    const float* qkv = g_qkvbuf + (size_t)b * 64 * TOTW;

    const float4* qkv4 = (const float4*)qkv;
    for (int e4 = tid; e4 < 64 * TOTW / 4; e4 += 256) {
        float4 f = qkv4[e4];
        int flat = e4 * 4;
        int i = flat / TOTW, col = flat % TOTW;
        float* dst = sqkv + i * QP + col;
        dst[0] = f.x; dst[1] = f.y; dst[2] = f.z; dst[3] = f.w;
    }
    __syncthreads();

    for (int rr = 0; rr < 8; rr++) {
        int rowi = wid * 8 + rr;
        float s = 0.f, s2 = 0.f;
        for (int col = lane; col < TOTW; col += 32) {
            float v = sqkv[rowi * QP + col];
            s += v; s2 += v * v;
        }
#pragma unroll
        for (int o = 16; o > 0; o >>= 1) {
            s  += __shfl_xor_sync(0xFFFFFFFFu, s, o);
            s2 += __shfl_xor_sync(0xFFFFFFFFu, s2, o);
        }
        if (lane == 0) {
            float mu = s / TOTW;
            float var = s2 / TOTW - mu * mu;
            smu[rowi] = mu;
            srs[rowi] = rsqrtf(var + 1e-5f);
        }
    }
    __syncthreads();

    for (int e = tid; e < 64 * TOTW; e += 256) {
        int i = e / TOTW, col = e % TOTW;
        float v = (sqkv[i * QP + col] - smu[i]) * srs[i] * gq[col] + gb[col];
        if (col < KEYS) v *= 0.125f;
        sqkv[i * QP + col] = v;
    }
    __syncthreads();

    for (int e = tid; e < 4096; e += 256) {
        int i = e >> 6, j = e & 63;
        float acc = 0.f;
#pragma unroll 16
        for (int d = 0; d < 64; d++)
            acc += sqkv[i * QP + d] * sqkv[j * QP + KEYS + d];
        ss[i * SP + j] = acc;
    }
    __syncthreads();

    for (int rowi = wid; rowi < 64; rowi += 8) {
        float m = -1e30f;
        for (int j = lane; j < 64; j += 32) m = fmaxf(m, ss[rowi * SP + j]);
#pragma unroll
        for (int o = 16; o > 0; o >>= 1)
            m = fmaxf(m, __shfl_xor_sync(0xFFFFFFFFu, m, o));
        float s = 0.f;
        for (int j = lane; j < 64; j += 32) {
            float e = expf(ss[rowi * SP + j] - m);
            ss[rowi * SP + j] = e; s += e;
        }
#pragma unroll
        for (int o = 16; o > 0; o >>= 1)
            s += __shfl_xor_sync(0xFFFFFFFFu, s, o);
        float inv = 1.f / s;
        for (int j = lane; j < 64; j += 32) ss[rowi * SP + j] *= inv;
    }
    __syncthreads();

    // attended overwrites the v region IN PLACE (column-private per thread:
    // all reads of column d complete before its writes; dpasses touch
    // disjoint column sets, so no sync needed inside the loop)
    for (int dpass = 0; dpass < 2; dpass++) {
        const int d = dpass * 256 + tid;
        float acc[64];
#pragma unroll
        for (int i = 0; i < 64; i++) acc[i] = 0.f;
        for (int jb = 0; jb < 64; jb += 8) {
            float vv[8];
#pragma unroll
            for (int t = 0; t < 8; t++)
                vv[t] = sqkv[(jb + t) * QP + 2 * KEYS + d];
#pragma unroll
            for (int i = 0; i < 64; i++) {
                float4 w0 = *(const float4*)&ss[i * SP + jb];
                float4 w1 = *(const float4*)&ss[i * SP + jb + 4];
                acc[i] += w0.x * vv[0] + w0.y * vv[1] + w0.z * vv[2] + w0.w * vv[3]
                        + w1.x * vv[4] + w1.y * vv[5] + w1.z * vv[6] + w1.w * vv[7];
            }
        }
#pragma unroll
        for (int i = 0; i < 64; i++)
            sqkv[i * QP + 2 * KEYS + d] = acc[i];
    }
    __syncthreads();

    // residual + LN: mem = LN(mems + attended), emit fp32 + fp16
    for (int rr = 0; rr < 8; rr++) {
        const int i = wid * 8 + rr;
        const size_t row = (size_t)(b * 64 + i);
        float s = 0.f, s2 = 0.f;
        for (int col = lane; col < DDIM; col += 32) {
            float a = sqkv[i * QP + 2 * KEYS + col] + g_mems[row * DDIM + col];
            sqkv[i * QP + 2 * KEYS + col] = a;
            s += a; s2 += a * a;
        }
#pragma unroll
        for (int o = 16; o > 0; o >>= 1) {
            s  += __shfl_xor_sync(0xFFFFFFFFu, s, o);
            s2 += __shfl_xor_sync(0xFFFFFFFFu, s2, o);
        }
        const float mu = s / DDIM;
        const float var = s2 / DDIM - mu * mu;
        const float rs = rsqrtf(var + 1e-5f);
        for (int col = lane; col < DDIM; col += 32) {
            float a = sqkv[i * QP + 2 * KEYS + col];
            float y = (a - mu) * rs * gm[col] + bm[col];
            g_mem[row * DDIM + col] = y;
            g_ah[row * DDIM + col] = __float2half_rn(y);
        }
    }
}

// ---------------- host orchestration -----------------------------------------
extern "C" void kernel_launch(void* const* d_in, const int* in_sizes, int n_in,
                              void* d_out, int out_size)
{
    const float* c     = (const float*)d_in[0];
    const float* mem_c = (const float*)d_in[1];
    const float* Wqkv  = (const float*)d_in[2];
    const float* bqkv  = (const float*)d_in[3];
    const float* gq    = (const float*)d_in[4];
    const float* bq    = (const float*)d_in[5];
    const float* gm    = (const float*)d_in[6];
    const float* bm    = (const float*)d_in[7];
    const float* W1    = (const float*)d_in[8];
    const float* b1    = (const float*)d_in[9];
    const float* W2    = (const float*)d_in[10];
    const float* b2    = (const float*)d_in[11];
    const float* Ws1   = (const float*)d_in[12];
    const float* bs1   = (const float*)d_in[13];
    const float* Ws2   = (const float*)d_in[14];
    const float* bs2   = (const float*)d_in[15];
    float* out = (float*)d_out;

    float *p_mems, *p_qkv, *p_mem, *p_t2;
    bf16 *p_tau16, *p_c16, *p_mc16;
    half *p_ah, *p_hh, *p_wq, *p_w1, *p_w2, *p_s1, *p_s2;
    cudaGetSymbolAddress((void**)&p_tau16, g_tau16);
    cudaGetSymbolAddress((void**)&p_mems, g_mems);
    cudaGetSymbolAddress((void**)&p_qkv,  g_qkvbuf);
    cudaGetSymbolAddress((void**)&p_mem,  g_mem);
    cudaGetSymbolAddress((void**)&p_t2,   g_t2);
    cudaGetSymbolAddress((void**)&p_c16,  g_c16);
    cudaGetSymbolAddress((void**)&p_mc16, g_mc16);
    cudaGetSymbolAddress((void**)&p_ah,   g_ah);
    cudaGetSymbolAddress((void**)&p_hh,   g_hh);
    cudaGetSymbolAddress((void**)&p_wq,   g_wqkv);
    cudaGetSymbolAddress((void**)&p_w1,   g_w1);
    cudaGetSymbolAddress((void**)&p_w2,   g_w2);
    cudaGetSymbolAddress((void**)&p_s1,   g_ws1);
    cudaGetSymbolAddress((void**)&p_s2,   g_ws2);

    const int SM_WG = 73728;                              // 2 stages x 36864
    const int SM_ATTN = (64 * QP + 64 * SP + 128) * 4;    // 183040
    cudaFuncSetAttribute(wgemm<bf16, 0, true>,  cudaFuncAttributeMaxDynamicSharedMemorySize, SM_WG);
    cudaFuncSetAttribute(wgemm<half, 1, false>, cudaFuncAttributeMaxDynamicSharedMemorySize, SM_WG);
    cudaFuncSetAttribute(wgemm<half, 2, false>, cudaFuncAttributeMaxDynamicSharedMemorySize, SM_WG);
    cudaFuncSetAttribute(attn_ln_kernel, cudaFuncAttributeMaxDynamicSharedMemorySize, SM_ATTN);
    const dim3 blk(256);

    // --- conversions ---
    conv_small_kernel<<<2816, 128>>>(c, p_c16, Wqkv, p_wq, W1, p_w1,
                                     W2, p_w2, Ws1, p_s1, Ws2, p_s2);
    conv_memc_kernel<<<2048, 256>>>(mem_c, p_mc16);

    // --- 1) approx tau (bf16 out) = c16 @ mc16^T ---
    wgemm<bf16, 0, true><<<dim3((NMEM + 127) / 128, 2), blk, SM_WG>>>(
        p_c16, p_mc16, nullptr, nullptr, p_tau16,
        NB, NMEM, DDIM, DDIM, DDIM, NMEM);

    // --- 2) single-pass histogram candidate select + exact fp32 rescore ---
    topk16_kernel<<<NB, 1024>>>();
    rescore_kernel<<<NB, blk>>>(c, mem_c);

    // --- 3) mems + fp16 emit ---
    build_mems_kernel<<<ROWS, 128>>>(mem_c);

    // --- 4) qkv = mems @ Wqkv + bqkv ---
    wgemm<half, 1, false><<<dim3(5, 128), blk, SM_WG>>>(
        p_ah, p_wq, bqkv, p_qkv, (half*)nullptr,
        ROWS, TOTW, DDIM, DDIM, TOTW, TOTW);

    // --- 5+6) fused LN + attention + residual-LN -> p_mem, p_ah ---
    attn_ln_kernel<<<NB, blk, SM_ATTN>>>(gq, bq, gm, bm);

    // --- 7) two residual MLP blocks ---
    for (int rep = 0; rep < 2; rep++) {
        wgemm<half, 2, false><<<dim3(4, 128), blk, SM_WG>>>(
            p_ah, p_w1, b1, nullptr, p_hh,
            ROWS, DDIM, DDIM, DDIM, DDIM, DDIM);
        wgemm<half, 1, false><<<dim3(4, 128), blk, SM_WG>>>(
            p_hh, p_w2, b2, p_t2, (half*)nullptr,
            ROWS, DDIM, DDIM, DDIM, DDIM, DDIM);
        ln_kernel<<<ROWS, 128>>>(p_t2, p_mem, gm, bm, p_mem, p_ah, DDIM);
    }

    // --- 8) c_prime = relu(mem @ Ws1 + bs1) @ Ws2 + bs2 ---
    wgemm<half, 2, false><<<dim3(4, 128), blk, SM_WG>>>(
        p_ah, p_s1, bs1, nullptr, p_hh,
        ROWS, DDIM, DDIM, DDIM, DDIM, DDIM);
    wgemm<half, 1, false><<<dim3(4, 128), blk, SM_WG>>>(
        p_hh, p_s2, bs2, out, (half*)nullptr,
        ROWS, CDIM, DDIM, DDIM, DDIM, CDIM);
}